// round 1
// baseline (speedup 1.0000x reference)
#include <cuda_runtime.h>
#include <math.h>

// ---------------- problem constants ----------------
#define NB    2
#define DD    256
#define LQT   12240
#define NHH   8
#define NLAY  6
#define DFF_  1024
#define MTOT  (NB*LQT)   // 24480

__constant__ int c_H[4]     = {96,48,24,12};
__constant__ int c_W[4]     = {96,48,24,12};
__constant__ int c_start[4] = {0,9216,11520,12096};
__constant__ int c_len[4]   = {9216,2304,576,144};

// ---------------- scratch (device globals; no allocation) ----------------
__device__ float g_src[NB*LQT*DD];
__device__ float g_pos[NB*LQT*DD];
__device__ float g_q  [NB*LQT*DD];
__device__ float g_off[NB*LQT*DD];
__device__ float g_aw [NB*LQT*128];
__device__ float g_val[NB*LQT*DD];
__device__ float g_msd[NB*LQT*DD];
__device__ float g_att[NB*LQT*DD];
__device__ float g_h  [NB*LQT*DFF_];
__device__ float g_ref[LQT*2];

__device__ __forceinline__ int lvl_of(int q) {
    return (q < 9216) ? 0 : (q < 11520) ? 1 : (q < 12096) ? 2 : 3;
}

// block-wide sum for blockDim.x == 256
__device__ __forceinline__ float blockSum(float v) {
    __shared__ float sh[8];
    int lane = threadIdx.x & 31, w = threadIdx.x >> 5;
    #pragma unroll
    for (int o = 16; o > 0; o >>= 1) v += __shfl_xor_sync(0xffffffffu, v, o);
    if (lane == 0) sh[w] = v;
    __syncthreads();
    if (w == 0) {
        float r = (lane < 8) ? sh[lane] : 0.f;
        #pragma unroll
        for (int o = 4; o > 0; o >>= 1) r += __shfl_xor_sync(0xffffffffu, r, o);
        if (lane == 0) sh[0] = r;
    }
    __syncthreads();
    float res = sh[0];
    __syncthreads();
    return res;
}

// ---------------- GEMM: C[m,n] = sum_k A[m,k]*W[n,k] + bias[n]  (A row-major MxK, W row-major NxK)
__global__ void __launch_bounds__(256)
gemm_nt_kernel(const float* __restrict__ A, const float* __restrict__ W,
               const float* __restrict__ bias, float* __restrict__ C,
               int M, int N, int K, int relu)
{
    __shared__ __align__(16) float As[16][68];
    __shared__ __align__(16) float Ws[16][68];
    int tid = threadIdx.x;
    int tx = tid & 15, ty = tid >> 4;
    int m0 = blockIdx.y * 64, n0 = blockIdx.x * 64;
    int lm = tid >> 2;
    int lk = (tid & 3) * 4;
    const float* Aptr = A + (size_t)(m0 + lm) * K + lk;
    const float* Wptr = W + (size_t)(n0 + lm) * K + lk;
    bool aok = (m0 + lm) < M;
    float acc[4][4] = {};
    for (int k0 = 0; k0 < K; k0 += 16) {
        float4 a4 = aok ? *(const float4*)(Aptr + k0) : make_float4(0.f,0.f,0.f,0.f);
        float4 w4 = *(const float4*)(Wptr + k0);
        As[lk+0][lm]=a4.x; As[lk+1][lm]=a4.y; As[lk+2][lm]=a4.z; As[lk+3][lm]=a4.w;
        Ws[lk+0][lm]=w4.x; Ws[lk+1][lm]=w4.y; Ws[lk+2][lm]=w4.z; Ws[lk+3][lm]=w4.w;
        __syncthreads();
        #pragma unroll
        for (int k = 0; k < 16; k++) {
            float4 a = *(const float4*)&As[k][ty*4];
            float4 w = *(const float4*)&Ws[k][tx*4];
            float ar[4] = {a.x,a.y,a.z,a.w}, wr[4] = {w.x,w.y,w.z,w.w};
            #pragma unroll
            for (int i = 0; i < 4; i++)
                #pragma unroll
                for (int j = 0; j < 4; j++)
                    acc[i][j] = fmaf(ar[i], wr[j], acc[i][j]);
        }
        __syncthreads();
    }
    #pragma unroll
    for (int i = 0; i < 4; i++) {
        int m = m0 + ty*4 + i;
        if (m >= M) break;
        #pragma unroll
        for (int j = 0; j < 4; j++) {
            int n = n0 + tx*4 + j;
            float v = acc[i][j] + bias[n];
            if (relu) v = fmaxf(v, 0.f);
            C[(size_t)m*N + n] = v;
        }
    }
}

// ---------------- GEMM (tokenizer): C[m,n] = sum_k A[k,m]*W[n,k] + bias[n]
// A: KxM with m contiguous (ld == M); W: NxK row-major.
__global__ void __launch_bounds__(256)
gemm_tn_kernel(const float* __restrict__ A, const float* __restrict__ W,
               const float* __restrict__ bias, float* __restrict__ C,
               int M, int N, int K)
{
    __shared__ __align__(16) float As[16][68];
    __shared__ __align__(16) float Ws[16][68];
    int tid = threadIdx.x;
    int tx = tid & 15, ty = tid >> 4;
    int m0 = blockIdx.y * 64, n0 = blockIdx.x * 64;
    int ak = tid >> 4, amq = (tid & 15) * 4;   // A tile: 16(k) x 64(m)
    int wn = tid >> 2, wk  = (tid & 3) * 4;    // W tile: 64(n) x 16(k)
    bool aok = (m0 + amq) < M;                 // M % 4 == 0 in all uses
    float acc[4][4] = {};
    for (int k0 = 0; k0 < K; k0 += 16) {
        float4 a4 = aok ? *(const float4*)(A + (size_t)(k0+ak)*M + m0 + amq)
                        : make_float4(0.f,0.f,0.f,0.f);
        *(float4*)&As[ak][amq] = a4;
        float4 w4 = *(const float4*)(W + (size_t)(n0+wn)*K + k0 + wk);
        Ws[wk+0][wn]=w4.x; Ws[wk+1][wn]=w4.y; Ws[wk+2][wn]=w4.z; Ws[wk+3][wn]=w4.w;
        __syncthreads();
        #pragma unroll
        for (int k = 0; k < 16; k++) {
            float4 a = *(const float4*)&As[k][ty*4];
            float4 w = *(const float4*)&Ws[k][tx*4];
            float ar[4] = {a.x,a.y,a.z,a.w}, wr[4] = {w.x,w.y,w.z,w.w};
            #pragma unroll
            for (int i = 0; i < 4; i++)
                #pragma unroll
                for (int j = 0; j < 4; j++)
                    acc[i][j] = fmaf(ar[i], wr[j], acc[i][j]);
        }
        __syncthreads();
    }
    #pragma unroll
    for (int i = 0; i < 4; i++) {
        int m = m0 + ty*4 + i;
        if (m >= M) break;
        #pragma unroll
        for (int j = 0; j < 4; j++) {
            int n = n0 + tx*4 + j;
            C[(size_t)m*N + n] = acc[i][j] + bias[n];
        }
    }
}

// ---------------- GroupNorm (stats over (level positions, 8 channels) per (b, group))
__global__ void __launch_bounds__(256)
gn_kernel(float* __restrict__ src, const float* __restrict__ g, const float* __restrict__ b)
{
    int grp = blockIdx.x & 31;
    int bb  = (blockIdx.x >> 5) & 1;
    int lvl = blockIdx.x >> 6;
    int L = c_len[lvl], st = c_start[lvl];
    float* base = src + ((size_t)bb*LQT + st) * DD;
    int n = L * 8;
    float s = 0.f;
    for (int i = threadIdx.x; i < n; i += 256)
        s += base[(size_t)(i>>3)*DD + grp*8 + (i&7)];
    float mean = blockSum(s) / (float)n;
    float s2 = 0.f;
    for (int i = threadIdx.x; i < n; i += 256) {
        float d = base[(size_t)(i>>3)*DD + grp*8 + (i&7)] - mean;
        s2 += d*d;
    }
    float rstd = rsqrtf(blockSum(s2) / (float)n + 1e-5f);
    for (int i = threadIdx.x; i < n; i += 256) {
        int c = grp*8 + (i&7);
        size_t id = (size_t)(i>>3)*DD + c;
        base[id] = (base[id] - mean) * rstd * g[lvl*DD + c] + b[lvl*DD + c];
    }
}

// ---------------- sine positional embedding + level embed (same for both batches)
__global__ void pos_kernel(const float* __restrict__ lemb, float* __restrict__ pos)
{
    int idx = blockIdx.x*blockDim.x + threadIdx.x;
    if (idx >= LQT*DD) return;
    int qq = idx >> 8, d = idx & 255;
    int lvl = lvl_of(qq);
    int st = c_start[lvl], H = c_H[lvl], W = c_W[lvl];
    int p = qq - st; int y = p / W, x = p % W;
    const float TWO_PI = 6.28318530717958647692f;
    const float LN1E4_64 = 0.14391156831212787f;  // ln(10000)/64
    float v;
    if (d < 128) {
        float e = (float)(y+1) / ((float)H + 1e-6f) * TWO_PI;
        int i = d >> 1;
        float u = e * expf(-LN1E4_64 * (float)i);
        v = (d & 1) ? cosf(u) : sinf(u);
    } else {
        int dd = d - 128;
        float e = (float)(x+1) / ((float)W + 1e-6f) * TWO_PI;
        int i = dd >> 1;
        float u = e * expf(-LN1E4_64 * (float)i);
        v = (dd & 1) ? cosf(u) : sinf(u);
    }
    v += lemb[lvl*DD + d];
    pos[(size_t)qq*DD + d] = v;
    pos[(size_t)(LQT + qq)*DD + d] = v;
}

__global__ void ref_kernel(float* __restrict__ ref)
{
    int qq = blockIdx.x*blockDim.x + threadIdx.x;
    if (qq >= LQT) return;
    int lvl = lvl_of(qq);
    int st = c_start[lvl], H = c_H[lvl], W = c_W[lvl];
    int p = qq - st; int y = p / W, x = p % W;
    ref[qq*2+0] = ((float)x + 0.5f) / (float)W;
    ref[qq*2+1] = ((float)y + 0.5f) / (float)H;
}

__global__ void add4_kernel(const float4* __restrict__ a, const float4* __restrict__ b,
                            float4* __restrict__ c, int n4)
{
    int i = blockIdx.x*blockDim.x + threadIdx.x;
    if (i < n4) {
        float4 x = a[i], y = b[i];
        c[i] = make_float4(x.x+y.x, x.y+y.y, x.z+y.z, x.w+y.w);
    }
}

// ---------------- softmax over last 16 (NL*NP) for each (b,q,head)
__global__ void softmax16_kernel(float* __restrict__ aw, int n)
{
    int t = blockIdx.x*blockDim.x + threadIdx.x;
    if (t >= n) return;
    float* p = aw + (size_t)t*16;
    float buf[16];
    float m = -1e30f;
    #pragma unroll
    for (int i = 0; i < 16; i++) { buf[i] = p[i]; m = fmaxf(m, buf[i]); }
    float s = 0.f;
    #pragma unroll
    for (int i = 0; i < 16; i++) { buf[i] = expf(buf[i] - m); s += buf[i]; }
    float inv = 1.f / s;
    #pragma unroll
    for (int i = 0; i < 16; i++) p[i] = buf[i] * inv;
}

// ---------------- multi-scale deformable attention core: one warp per (b,q,head)
__global__ void __launch_bounds__(256)
msdeform_kernel(const float* __restrict__ val, const float* __restrict__ off,
                const float* __restrict__ aw, const float* __restrict__ ref,
                float* __restrict__ out)
{
    int warp = blockIdx.x * (blockDim.x >> 5) + (threadIdx.x >> 5);
    int lane = threadIdx.x & 31;
    if (warp >= NB*LQT*NHH) return;
    int h  = warp & 7;
    int bq = warp >> 3;
    int q  = bq % LQT;
    int b  = bq / LQT;
    float gx = ref[q*2], gy = ref[q*2+1];
    const float* offp = off + (size_t)bq*DD  + h*32;
    const float* awp  = aw  + (size_t)bq*128 + h*16;
    float acc = 0.f;
    #pragma unroll
    for (int l = 0; l < 4; l++) {
        int Wl = c_W[l], Hl = c_H[l], st = c_start[l];
        float fW = (float)Wl, fH = (float)Hl;
        const float* vb = val + ((size_t)b*LQT + st)*DD + h*32 + lane;
        #pragma unroll
        for (int p = 0; p < 4; p++) {
            float ox = offp[(l*4+p)*2+0], oy = offp[(l*4+p)*2+1];
            float a  = awp[l*4+p];
            float x = (gx + ox / fW) * fW - 0.5f;
            float y = (gy + oy / fH) * fH - 0.5f;
            float x0f = floorf(x), y0f = floorf(y);
            float tx = x - x0f, ty = y - y0f;
            int x0 = (int)x0f, y0 = (int)y0f;
            float w00 = (1.f-tx)*(1.f-ty)*a;
            float w10 = tx*(1.f-ty)*a;
            float w01 = (1.f-tx)*ty*a;
            float w11 = tx*ty*a;
            bool xv0 = (x0   >= 0) && (x0   < Wl);
            bool xv1 = (x0+1 >= 0) && (x0+1 < Wl);
            bool yv0 = (y0   >= 0) && (y0   < Hl);
            bool yv1 = (y0+1 >= 0) && (y0+1 < Hl);
            if (xv0 && yv0) acc += w00 * vb[(size_t)(y0*Wl + x0)     * DD];
            if (xv1 && yv0) acc += w10 * vb[(size_t)(y0*Wl + x0 + 1) * DD];
            if (xv0 && yv1) acc += w01 * vb[(size_t)((y0+1)*Wl + x0)     * DD];
            if (xv1 && yv1) acc += w11 * vb[(size_t)((y0+1)*Wl + x0 + 1) * DD];
        }
    }
    out[(size_t)bq*DD + h*32 + lane] = acc;
}

// ---------------- residual + LayerNorm over D=256 (one block per row)
__global__ void __launch_bounds__(256)
addln_kernel(float* __restrict__ src, const float* __restrict__ res,
             const float* __restrict__ g, const float* __restrict__ b)
{
    int row = blockIdx.x, t = threadIdx.x;
    size_t idx = (size_t)row*DD + t;
    float x = src[idx] + res[idx];
    float mean = blockSum(x) * (1.f/DD);
    float d = x - mean;
    float var = blockSum(d*d) * (1.f/DD);
    src[idx] = d * rsqrtf(var + 1e-5f) * g[t] + b[t];
}

// ---------------- finalize: copy src + metadata tail to d_out
__global__ void finalize_kernel(const float* __restrict__ src, float* __restrict__ out, int out_size)
{
    int i = blockIdx.x*blockDim.x + threadIdx.x;
    if (i >= out_size) return;
    const int n = NB*LQT*DD;
    if (i < n) { out[i] = src[i]; return; }
    int j = i - n;
    float v;
    if (j < 4)       v = (float)c_start[j];
    else if (j < 12) v = (float)c_H[(j-4) >> 1];   // shapes are square (h==w)
    else             v = 1.0f;                     // valid_ratios
    out[i] = v;
}

// ---------------- host orchestration ----------------
extern "C" void kernel_launch(void* const* d_in, const int* in_sizes, int n_in,
                              void* d_out, int out_size)
{
    (void)n_in;
    const float *X[4], *FW[4], *FB[4];
    if (in_sizes[1] == 65536) {
        // setup_inputs dict order: x1,fc1_w,fc1_b,x2,fc2_w,fc2_b,...
        for (int i = 0; i < 4; i++) {
            X[i]  = (const float*)d_in[3*i+0];
            FW[i] = (const float*)d_in[3*i+1];
            FB[i] = (const float*)d_in[3*i+2];
        }
    } else {
        // reference signature order: x1..x4, fc1_w,fc1_b,...,fc4_w,fc4_b
        for (int i = 0; i < 4; i++) {
            X[i]  = (const float*)d_in[i];
            FW[i] = (const float*)d_in[4+2*i];
            FB[i] = (const float*)d_in[5+2*i];
        }
    }
    const float* gn_g  = (const float*)d_in[12];
    const float* gn_b  = (const float*)d_in[13];
    const float* lemb  = (const float*)d_in[14];
    const float* off_w = (const float*)d_in[15];
    const float* off_b = (const float*)d_in[16];
    const float* aw_w  = (const float*)d_in[17];
    const float* aw_b  = (const float*)d_in[18];
    const float* val_w = (const float*)d_in[19];
    const float* val_b = (const float*)d_in[20];
    const float* out_w = (const float*)d_in[21];
    const float* out_b = (const float*)d_in[22];
    const float* ln1_g = (const float*)d_in[23];
    const float* ln1_b = (const float*)d_in[24];
    const float* l1_w  = (const float*)d_in[25];
    const float* l1_b  = (const float*)d_in[26];
    const float* l2_w  = (const float*)d_in[27];
    const float* l2_b  = (const float*)d_in[28];
    const float* ln2_g = (const float*)d_in[29];
    const float* ln2_b = (const float*)d_in[30];

    float *src, *pos, *q, *off, *aw, *val, *msd, *att, *hbuf, *ref;
    cudaGetSymbolAddress((void**)&src,  g_src);
    cudaGetSymbolAddress((void**)&pos,  g_pos);
    cudaGetSymbolAddress((void**)&q,    g_q);
    cudaGetSymbolAddress((void**)&off,  g_off);
    cudaGetSymbolAddress((void**)&aw,   g_aw);
    cudaGetSymbolAddress((void**)&val,  g_val);
    cudaGetSymbolAddress((void**)&msd,  g_msd);
    cudaGetSymbolAddress((void**)&att,  g_att);
    cudaGetSymbolAddress((void**)&hbuf, g_h);
    cudaGetSymbolAddress((void**)&ref,  g_ref);

    const int HS[4] = {96,48,24,12};
    const int CIN[4] = {256,512,768,1024};
    const int START[4] = {0,9216,11520,12096};

    // Tokenizers: per level, per batch
    for (int l = 0; l < 4; l++) {
        int HW = HS[l]*HS[l];
        dim3 grid(DD/64, (HW + 63)/64);
        for (int b = 0; b < 2; b++) {
            gemm_tn_kernel<<<grid, 256>>>(
                X[l] + (size_t)b*CIN[l]*HW, FW[l], FB[l],
                src + ((size_t)b*LQT + START[l])*DD, HW, DD, CIN[l]);
        }
    }
    gn_kernel<<<4*2*32, 256>>>(src, gn_g, gn_b);
    pos_kernel<<<(LQT*DD + 255)/256, 256>>>(lemb, pos);
    ref_kernel<<<(LQT + 255)/256, 256>>>(ref);

    dim3 g256(DD/64,   (MTOT + 63)/64);
    dim3 g128(128/64,  (MTOT + 63)/64);
    dim3 g1024(DFF_/64,(MTOT + 63)/64);
    int n4 = MTOT*DD/4;

    for (int l = 0; l < NLAY; l++) {
        add4_kernel<<<(n4 + 255)/256, 256>>>((const float4*)src, (const float4*)pos, (float4*)q, n4);
        gemm_nt_kernel<<<g256, 256>>>(q, off_w + (size_t)l*DD*DD, off_b + l*DD, off, MTOT, DD, DD, 0);
        gemm_nt_kernel<<<g128, 256>>>(q, aw_w + (size_t)l*128*DD, aw_b + l*128, aw, MTOT, 128, DD, 0);
        softmax16_kernel<<<(MTOT*NHH + 255)/256, 256>>>(aw, MTOT*NHH);
        gemm_nt_kernel<<<g256, 256>>>(src, val_w + (size_t)l*DD*DD, val_b + l*DD, val, MTOT, DD, DD, 0);
        msdeform_kernel<<<MTOT, 256>>>(val, off, aw, ref, msd);
        gemm_nt_kernel<<<g256, 256>>>(msd, out_w + (size_t)l*DD*DD, out_b + l*DD, att, MTOT, DD, DD, 0);
        addln_kernel<<<MTOT, 256>>>(src, att, ln1_g + l*DD, ln1_b + l*DD);
        gemm_nt_kernel<<<g1024, 256>>>(src, l1_w + (size_t)l*DFF_*DD, l1_b + l*DFF_, hbuf, MTOT, DFF_, DD, 1);
        gemm_nt_kernel<<<g256, 256>>>(hbuf, l2_w + (size_t)l*DD*DFF_, l2_b + l*DD, att, MTOT, DD, DFF_, 0);
        addln_kernel<<<MTOT, 256>>>(src, att, ln2_g + l*DD, ln2_b + l*DD);
    }

    finalize_kernel<<<(out_size + 255)/256, 256>>>(src, (float*)d_out, out_size);
}

// round 3
// speedup vs baseline: 1.2517x; 1.2517x over previous
#include <cuda_runtime.h>
#include <math.h>

// ---------------- problem constants ----------------
#define NB    2
#define DD    256
#define LQT   12240
#define NHH   8
#define NLAY  6
#define DFF_  1024
#define MTOT  (NB*LQT)   // 24480

__constant__ int c_H[4]     = {96,48,24,12};
__constant__ int c_W[4]     = {96,48,24,12};
__constant__ int c_start[4] = {0,9216,11520,12096};
__constant__ int c_len[4]   = {9216,2304,576,144};

// ---------------- scratch (device globals; no allocation) ----------------
__device__ float g_src[NB*LQT*DD];
__device__ float g_pos[NB*LQT*DD];
__device__ float g_off[NB*LQT*DD];
__device__ float g_aw [NB*LQT*128];
__device__ float g_val[NB*LQT*DD];
__device__ float g_msd[NB*LQT*DD];
__device__ float g_att[NB*LQT*DD];
__device__ float g_h  [NB*LQT*DFF_];
__device__ float g_ref[LQT*2];

__device__ __forceinline__ int lvl_of(int q) {
    return (q < 9216) ? 0 : (q < 11520) ? 1 : (q < 12096) ? 2 : 3;
}

// block-wide sum for blockDim.x == 256
__device__ __forceinline__ float blockSum(float v) {
    __shared__ float sh[8];
    int lane = threadIdx.x & 31, w = threadIdx.x >> 5;
    #pragma unroll
    for (int o = 16; o > 0; o >>= 1) v += __shfl_xor_sync(0xffffffffu, v, o);
    if (lane == 0) sh[w] = v;
    __syncthreads();
    if (w == 0) {
        float r = (lane < 8) ? sh[lane] : 0.f;
        #pragma unroll
        for (int o = 4; o > 0; o >>= 1) r += __shfl_xor_sync(0xffffffffu, r, o);
        if (lane == 0) sh[0] = r;
    }
    __syncthreads();
    float res = sh[0];
    __syncthreads();
    return res;
}

// ---------------- 3xTF32 tensor-core GEMM ----------------
// C[m,n] = sum_k (A[m,k] (+A2[m,k])) * W[n,k] + bias[n], optional relu.
// BM=128, BN=128, BK=16, 256 threads (8 warps, 4x2), warp tile 32x64.
__device__ __forceinline__ void split_tf32(float x, unsigned& hi, unsigned& lo) {
    asm("cvt.rna.tf32.f32 %0, %1;" : "=r"(hi) : "f"(x));
    float r = x - __uint_as_float(hi);
    asm("cvt.rna.tf32.f32 %0, %1;" : "=r"(lo) : "f"(r));
}

__device__ __forceinline__ void mma_tf32(float c[4],
    unsigned a0, unsigned a1, unsigned a2, unsigned a3,
    unsigned b0, unsigned b1)
{
    asm volatile("mma.sync.aligned.m16n8k8.row.col.f32.tf32.tf32.f32 "
        "{%0,%1,%2,%3}, {%4,%5,%6,%7}, {%8,%9}, {%0,%1,%2,%3};"
        : "+f"(c[0]), "+f"(c[1]), "+f"(c[2]), "+f"(c[3])
        : "r"(a0), "r"(a1), "r"(a2), "r"(a3), "r"(b0), "r"(b1));
}

__global__ void __launch_bounds__(256, 2)
gemm_mma_kernel(const float* __restrict__ A, const float* __restrict__ A2,
                const float* __restrict__ W, const float* __restrict__ bias,
                float* __restrict__ C, int M, int N, int K, int relu)
{
    __shared__ __align__(16) float As[128*20];
    __shared__ __align__(16) float Bs[128*20];
    int tid  = threadIdx.x;
    int lane = tid & 31, warp = tid >> 5;
    int wm = warp & 3, wn = warp >> 2;           // 4 (m) x 2 (n)
    int m0 = blockIdx.y * 128, n0 = blockIdx.x * 128;
    int g = lane >> 2, qd = lane & 3;
    float acc[2][8][4] = {};

    for (int k0 = 0; k0 < K; k0 += 16) {
        #pragma unroll
        for (int i = 0; i < 2; i++) {
            int f = tid + 256*i;
            int row = f >> 2, kq = (f & 3) * 4;
            int m = m0 + row;
            float4 a = make_float4(0.f,0.f,0.f,0.f);
            if (m < M) {
                a = *(const float4*)(A + (size_t)m*K + k0 + kq);
                if (A2) {
                    float4 a2 = *(const float4*)(A2 + (size_t)m*K + k0 + kq);
                    a.x += a2.x; a.y += a2.y; a.z += a2.z; a.w += a2.w;
                }
            }
            *(float4*)&As[row*20 + kq] = a;
            float4 b = *(const float4*)(W + (size_t)(n0 + row)*K + k0 + kq);
            *(float4*)&Bs[row*20 + kq] = b;
        }
        __syncthreads();
        #pragma unroll
        for (int kk = 0; kk < 16; kk += 8) {
            unsigned ah[2][4], al[2][4];
            #pragma unroll
            for (int im = 0; im < 2; im++) {
                int rb = wm*32 + im*16;
                float x0 = As[(rb + g     )*20 + kk + qd];
                float x1 = As[(rb + 8 + g )*20 + kk + qd];
                float x2 = As[(rb + g     )*20 + kk + 4 + qd];
                float x3 = As[(rb + 8 + g )*20 + kk + 4 + qd];
                split_tf32(x0, ah[im][0], al[im][0]);
                split_tf32(x1, ah[im][1], al[im][1]);
                split_tf32(x2, ah[im][2], al[im][2]);
                split_tf32(x3, ah[im][3], al[im][3]);
            }
            #pragma unroll
            for (int in_ = 0; in_ < 8; in_++) {
                int cb = wn*64 + in_*8 + g;
                float y0 = Bs[cb*20 + kk + qd];
                float y1 = Bs[cb*20 + kk + 4 + qd];
                unsigned bh0, bl0, bh1, bl1;
                split_tf32(y0, bh0, bl0);
                split_tf32(y1, bh1, bl1);
                #pragma unroll
                for (int im = 0; im < 2; im++) {
                    mma_tf32(acc[im][in_], al[im][0], al[im][1], al[im][2], al[im][3], bh0, bh1);
                    mma_tf32(acc[im][in_], ah[im][0], ah[im][1], ah[im][2], ah[im][3], bl0, bl1);
                    mma_tf32(acc[im][in_], ah[im][0], ah[im][1], ah[im][2], ah[im][3], bh0, bh1);
                }
            }
        }
        __syncthreads();
    }
    // epilogue
    #pragma unroll
    for (int im = 0; im < 2; im++) {
        int r0 = m0 + wm*32 + im*16 + g;
        #pragma unroll
        for (int in_ = 0; in_ < 8; in_++) {
            int cn = n0 + wn*64 + in_*8 + qd*2;
            float bv0 = bias[cn], bv1 = bias[cn+1];
            float v0 = acc[im][in_][0] + bv0;
            float v1 = acc[im][in_][1] + bv1;
            float v2 = acc[im][in_][2] + bv0;
            float v3 = acc[im][in_][3] + bv1;
            if (relu) {
                v0 = fmaxf(v0, 0.f); v1 = fmaxf(v1, 0.f);
                v2 = fmaxf(v2, 0.f); v3 = fmaxf(v3, 0.f);
            }
            if (r0 < M)     *(float2*)(C + (size_t)r0*N + cn)     = make_float2(v0, v1);
            if (r0 + 8 < M) *(float2*)(C + (size_t)(r0+8)*N + cn) = make_float2(v2, v3);
        }
    }
}

// ---------------- GEMM (tokenizer): C[m,n] = sum_k A[k,m]*W[n,k] + bias[n]
__global__ void __launch_bounds__(256)
gemm_tn_kernel(const float* __restrict__ A, const float* __restrict__ W,
               const float* __restrict__ bias, float* __restrict__ C,
               int M, int N, int K)
{
    __shared__ __align__(16) float As[16][68];
    __shared__ __align__(16) float Ws[16][68];
    int tid = threadIdx.x;
    int tx = tid & 15, ty = tid >> 4;
    int m0 = blockIdx.y * 64, n0 = blockIdx.x * 64;
    int ak = tid >> 4, amq = (tid & 15) * 4;
    int wn = tid >> 2, wk  = (tid & 3) * 4;
    bool aok = (m0 + amq) < M;
    float acc[4][4] = {};
    for (int k0 = 0; k0 < K; k0 += 16) {
        float4 a4 = aok ? *(const float4*)(A + (size_t)(k0+ak)*M + m0 + amq)
                        : make_float4(0.f,0.f,0.f,0.f);
        *(float4*)&As[ak][amq] = a4;
        float4 w4 = *(const float4*)(W + (size_t)(n0+wn)*K + k0 + wk);
        Ws[wk+0][wn]=w4.x; Ws[wk+1][wn]=w4.y; Ws[wk+2][wn]=w4.z; Ws[wk+3][wn]=w4.w;
        __syncthreads();
        #pragma unroll
        for (int k = 0; k < 16; k++) {
            float4 a = *(const float4*)&As[k][ty*4];
            float4 w = *(const float4*)&Ws[k][tx*4];
            float ar[4] = {a.x,a.y,a.z,a.w}, wr[4] = {w.x,w.y,w.z,w.w};
            #pragma unroll
            for (int i = 0; i < 4; i++)
                #pragma unroll
                for (int j = 0; j < 4; j++)
                    acc[i][j] = fmaf(ar[i], wr[j], acc[i][j]);
        }
        __syncthreads();
    }
    #pragma unroll
    for (int i = 0; i < 4; i++) {
        int m = m0 + ty*4 + i;
        if (m >= M) break;
        #pragma unroll
        for (int j = 0; j < 4; j++) {
            int n = n0 + tx*4 + j;
            C[(size_t)m*N + n] = acc[i][j] + bias[n];
        }
    }
}

// ---------------- GroupNorm ----------------
__global__ void __launch_bounds__(256)
gn_kernel(float* __restrict__ src, const float* __restrict__ g, const float* __restrict__ b)
{
    int grp = blockIdx.x & 31;
    int bb  = (blockIdx.x >> 5) & 1;
    int lvl = blockIdx.x >> 6;
    int L = c_len[lvl], st = c_start[lvl];
    float* base = src + ((size_t)bb*LQT + st) * DD;
    int n = L * 8;
    float s = 0.f;
    for (int i = threadIdx.x; i < n; i += 256)
        s += base[(size_t)(i>>3)*DD + grp*8 + (i&7)];
    float mean = blockSum(s) / (float)n;
    float s2 = 0.f;
    for (int i = threadIdx.x; i < n; i += 256) {
        float d = base[(size_t)(i>>3)*DD + grp*8 + (i&7)] - mean;
        s2 += d*d;
    }
    float rstd = rsqrtf(blockSum(s2) / (float)n + 1e-5f);
    for (int i = threadIdx.x; i < n; i += 256) {
        int c = grp*8 + (i&7);
        size_t id = (size_t)(i>>3)*DD + c;
        base[id] = (base[id] - mean) * rstd * g[lvl*DD + c] + b[lvl*DD + c];
    }
}

// ---------------- sine positional embedding + level embed ----------------
__global__ void pos_kernel(const float* __restrict__ lemb, float* __restrict__ pos)
{
    int idx = blockIdx.x*blockDim.x + threadIdx.x;
    if (idx >= LQT*DD) return;
    int qq = idx >> 8, d = idx & 255;
    int lvl = lvl_of(qq);
    int st = c_start[lvl], H = c_H[lvl], W = c_W[lvl];
    int p = qq - st; int y = p / W, x = p % W;
    const float TWO_PI = 6.28318530717958647692f;
    const float LN1E4_64 = 0.14391156831212787f;
    float v;
    if (d < 128) {
        float e = (float)(y+1) / ((float)H + 1e-6f) * TWO_PI;
        int i = d >> 1;
        float u = e * expf(-LN1E4_64 * (float)i);
        v = (d & 1) ? cosf(u) : sinf(u);
    } else {
        int dd = d - 128;
        float e = (float)(x+1) / ((float)W + 1e-6f) * TWO_PI;
        int i = dd >> 1;
        float u = e * expf(-LN1E4_64 * (float)i);
        v = (dd & 1) ? cosf(u) : sinf(u);
    }
    v += lemb[lvl*DD + d];
    pos[(size_t)qq*DD + d] = v;
    pos[(size_t)(LQT + qq)*DD + d] = v;
}

__global__ void ref_kernel(float* __restrict__ ref)
{
    int qq = blockIdx.x*blockDim.x + threadIdx.x;
    if (qq >= LQT) return;
    int lvl = lvl_of(qq);
    int st = c_start[lvl], H = c_H[lvl], W = c_W[lvl];
    int p = qq - st; int y = p / W, x = p % W;
    ref[qq*2+0] = ((float)x + 0.5f) / (float)W;
    ref[qq*2+1] = ((float)y + 0.5f) / (float)H;
}

// ---------------- softmax over 16 ----------------
__global__ void softmax16_kernel(float* __restrict__ aw, int n)
{
    int t = blockIdx.x*blockDim.x + threadIdx.x;
    if (t >= n) return;
    float* p = aw + (size_t)t*16;
    float buf[16];
    float m = -1e30f;
    #pragma unroll
    for (int i = 0; i < 16; i++) { buf[i] = p[i]; m = fmaxf(m, buf[i]); }
    float s = 0.f;
    #pragma unroll
    for (int i = 0; i < 16; i++) { buf[i] = expf(buf[i] - m); s += buf[i]; }
    float inv = 1.f / s;
    #pragma unroll
    for (int i = 0; i < 16; i++) p[i] = buf[i] * inv;
}

// ---------------- ms-deform attention core ----------------
__global__ void __launch_bounds__(256)
msdeform_kernel(const float* __restrict__ val, const float* __restrict__ off,
                const float* __restrict__ aw, const float* __restrict__ ref,
                float* __restrict__ out)
{
    int warp = blockIdx.x * (blockDim.x >> 5) + (threadIdx.x >> 5);
    int lane = threadIdx.x & 31;
    if (warp >= NB*LQT*NHH) return;
    int h  = warp & 7;
    int bq = warp >> 3;
    int q  = bq % LQT;
    int b  = bq / LQT;
    float gx = ref[q*2], gy = ref[q*2+1];
    const float* offp = off + (size_t)bq*DD  + h*32;
    const float* awp  = aw  + (size_t)bq*128 + h*16;
    float acc = 0.f;
    #pragma unroll
    for (int l = 0; l < 4; l++) {
        int Wl = c_W[l], Hl = c_H[l], st = c_start[l];
        float fW = (float)Wl, fH = (float)Hl;
        const float* vb = val + ((size_t)b*LQT + st)*DD + h*32 + lane;
        #pragma unroll
        for (int p = 0; p < 4; p++) {
            float ox = offp[(l*4+p)*2+0], oy = offp[(l*4+p)*2+1];
            float a  = awp[l*4+p];
            float x = (gx + ox / fW) * fW - 0.5f;
            float y = (gy + oy / fH) * fH - 0.5f;
            float x0f = floorf(x), y0f = floorf(y);
            float tx = x - x0f, ty = y - y0f;
            int x0 = (int)x0f, y0 = (int)y0f;
            float w00 = (1.f-tx)*(1.f-ty)*a;
            float w10 = tx*(1.f-ty)*a;
            float w01 = (1.f-tx)*ty*a;
            float w11 = tx*ty*a;
            bool xv0 = (x0   >= 0) && (x0   < Wl);
            bool xv1 = (x0+1 >= 0) && (x0+1 < Wl);
            bool yv0 = (y0   >= 0) && (y0   < Hl);
            bool yv1 = (y0+1 >= 0) && (y0+1 < Hl);
            if (xv0 && yv0) acc += w00 * vb[(size_t)(y0*Wl + x0)     * DD];
            if (xv1 && yv0) acc += w10 * vb[(size_t)(y0*Wl + x0 + 1) * DD];
            if (xv0 && yv1) acc += w01 * vb[(size_t)((y0+1)*Wl + x0)     * DD];
            if (xv1 && yv1) acc += w11 * vb[(size_t)((y0+1)*Wl + x0 + 1) * DD];
        }
    }
    out[(size_t)bq*DD + h*32 + lane] = acc;
}

// ---------------- residual + LayerNorm ----------------
__global__ void __launch_bounds__(256)
addln_kernel(float* __restrict__ src, const float* __restrict__ res,
             const float* __restrict__ g, const float* __restrict__ b)
{
    int row = blockIdx.x, t = threadIdx.x;
    size_t idx = (size_t)row*DD + t;
    float x = src[idx] + res[idx];
    float mean = blockSum(x) * (1.f/DD);
    float d = x - mean;
    float var = blockSum(d*d) * (1.f/DD);
    src[idx] = d * rsqrtf(var + 1e-5f) * g[t] + b[t];
}

// ---------------- finalize ----------------
__global__ void finalize_kernel(const float* __restrict__ src, float* __restrict__ out, int out_size)
{
    int i = blockIdx.x*blockDim.x + threadIdx.x;
    if (i >= out_size) return;
    const int n = NB*LQT*DD;
    if (i < n) { out[i] = src[i]; return; }
    int j = i - n;
    float v;
    if (j < 4)       v = (float)c_start[j];
    else if (j < 12) v = (float)c_H[(j-4) >> 1];
    else             v = 1.0f;
    out[i] = v;
}

// ---------------- host orchestration ----------------
extern "C" void kernel_launch(void* const* d_in, const int* in_sizes, int n_in,
                              void* d_out, int out_size)
{
    (void)n_in;
    const float *X[4], *FW[4], *FB[4];
    if (in_sizes[1] == 65536) {
        for (int i = 0; i < 4; i++) {
            X[i]  = (const float*)d_in[3*i+0];
            FW[i] = (const float*)d_in[3*i+1];
            FB[i] = (const float*)d_in[3*i+2];
        }
    } else {
        for (int i = 0; i < 4; i++) {
            X[i]  = (const float*)d_in[i];
            FW[i] = (const float*)d_in[4+2*i];
            FB[i] = (const float*)d_in[5+2*i];
        }
    }
    const float* gn_g  = (const float*)d_in[12];
    const float* gn_b  = (const float*)d_in[13];
    const float* lemb  = (const float*)d_in[14];
    const float* off_w = (const float*)d_in[15];
    const float* off_b = (const float*)d_in[16];
    const float* aw_w  = (const float*)d_in[17];
    const float* aw_b  = (const float*)d_in[18];
    const float* val_w = (const float*)d_in[19];
    const float* val_b = (const float*)d_in[20];
    const float* out_w = (const float*)d_in[21];
    const float* out_b = (const float*)d_in[22];
    const float* ln1_g = (const float*)d_in[23];
    const float* ln1_b = (const float*)d_in[24];
    const float* l1_w  = (const float*)d_in[25];
    const float* l1_b  = (const float*)d_in[26];
    const float* l2_w  = (const float*)d_in[27];
    const float* l2_b  = (const float*)d_in[28];
    const float* ln2_g = (const float*)d_in[29];
    const float* ln2_b = (const float*)d_in[30];

    float *src, *pos, *off, *aw, *val, *msd, *att, *hbuf, *ref;
    cudaGetSymbolAddress((void**)&src,  g_src);
    cudaGetSymbolAddress((void**)&pos,  g_pos);
    cudaGetSymbolAddress((void**)&off,  g_off);
    cudaGetSymbolAddress((void**)&aw,   g_aw);
    cudaGetSymbolAddress((void**)&val,  g_val);
    cudaGetSymbolAddress((void**)&msd,  g_msd);
    cudaGetSymbolAddress((void**)&att,  g_att);
    cudaGetSymbolAddress((void**)&hbuf, g_h);
    cudaGetSymbolAddress((void**)&ref,  g_ref);

    const int HS[4] = {96,48,24,12};
    const int CIN[4] = {256,512,768,1024};
    const int START[4] = {0,9216,11520,12096};

    for (int l = 0; l < 4; l++) {
        int HW = HS[l]*HS[l];
        dim3 grid(DD/64, (HW + 63)/64);
        for (int b = 0; b < 2; b++) {
            gemm_tn_kernel<<<grid, 256>>>(
                X[l] + (size_t)b*CIN[l]*HW, FW[l], FB[l],
                src + ((size_t)b*LQT + START[l])*DD, HW, DD, CIN[l]);
        }
    }
    gn_kernel<<<4*2*32, 256>>>(src, gn_g, gn_b);
    pos_kernel<<<(LQT*DD + 255)/256, 256>>>(lemb, pos);
    ref_kernel<<<(LQT + 255)/256, 256>>>(ref);

    int gy = (MTOT + 127)/128;
    dim3 g256(DD/128,   gy);
    dim3 g128(1,        gy);
    dim3 g1024(DFF_/128, gy);

    for (int l = 0; l < NLAY; l++) {
        gemm_mma_kernel<<<g256, 256>>>(src, pos, off_w + (size_t)l*DD*DD, off_b + l*DD, off, MTOT, DD, DD, 0);
        gemm_mma_kernel<<<g128, 256>>>(src, pos, aw_w + (size_t)l*128*DD, aw_b + l*128, aw, MTOT, 128, DD, 0);
        softmax16_kernel<<<(MTOT*NHH + 255)/256, 256>>>(aw, MTOT*NHH);
        gemm_mma_kernel<<<g256, 256>>>(src, (const float*)0, val_w + (size_t)l*DD*DD, val_b + l*DD, val, MTOT, DD, DD, 0);
        msdeform_kernel<<<MTOT, 256>>>(val, off, aw, ref, msd);
        gemm_mma_kernel<<<g256, 256>>>(msd, (const float*)0, out_w + (size_t)l*DD*DD, out_b + l*DD, att, MTOT, DD, DD, 0);
        addln_kernel<<<MTOT, 256>>>(src, att, ln1_g + l*DD, ln1_b + l*DD);
        gemm_mma_kernel<<<g1024, 256>>>(src, (const float*)0, l1_w + (size_t)l*DFF_*DD, l1_b + l*DFF_, hbuf, MTOT, DFF_, DD, 1);
        gemm_mma_kernel<<<g256, 256>>>(hbuf, (const float*)0, l2_w + (size_t)l*DD*DFF_, l2_b + l*DD, att, MTOT, DD, DFF_, 0);
        addln_kernel<<<MTOT, 256>>>(src, att, ln2_g + l*DD, ln2_b + l*DD);
    }

    finalize_kernel<<<(out_size + 255)/256, 256>>>(src, (float*)d_out, out_size);
}

// round 4
// speedup vs baseline: 1.5926x; 1.2723x over previous
#include <cuda_runtime.h>
#include <cuda_bf16.h>
#include <math.h>

// ---------------- problem constants ----------------
#define NB    2
#define DD    256
#define LQT   12240
#define NHH   8
#define NLAY  6
#define DFF_  1024
#define MTOT  (NB*LQT)   // 24480

__constant__ int c_H[4]     = {96,48,24,12};
__constant__ int c_W[4]     = {96,48,24,12};
__constant__ int c_start[4] = {0,9216,11520,12096};
__constant__ int c_len[4]   = {9216,2304,576,144};

// ---------------- scratch (device globals; no allocation) ----------------
__device__ float g_src[NB*LQT*DD];
__device__ float g_pos[NB*LQT*DD];
__device__ float g_off[NB*LQT*DD];
__device__ float g_aw [NB*LQT*128];
__device__ float g_val[NB*LQT*DD];
__device__ float g_msd[NB*LQT*DD];
__device__ float g_att[NB*LQT*DD];
__device__ float g_h  [NB*LQT*DFF_];
__device__ float g_ref[LQT*2];

// pre-split layer weights (bf16 hi/lo), layout: [off|aw|val|out|l1|l2] each stacked over 6 layers
#define OFF_OFF 0
#define OFF_AW  393216
#define OFF_VAL 589824
#define OFF_OUT 983040
#define OFF_L1  1376256
#define OFF_L2  2949120
#define W_TOTAL 4521984
__device__ __nv_bfloat16 g_wh[W_TOTAL];
__device__ __nv_bfloat16 g_wl[W_TOTAL];

__device__ __forceinline__ int lvl_of(int q) {
    return (q < 9216) ? 0 : (q < 11520) ? 1 : (q < 12096) ? 2 : 3;
}

// block-wide sum for blockDim.x == 256
__device__ __forceinline__ float blockSum(float v) {
    __shared__ float sh[8];
    int lane = threadIdx.x & 31, w = threadIdx.x >> 5;
    #pragma unroll
    for (int o = 16; o > 0; o >>= 1) v += __shfl_xor_sync(0xffffffffu, v, o);
    if (lane == 0) sh[w] = v;
    __syncthreads();
    if (w == 0) {
        float r = (lane < 8) ? sh[lane] : 0.f;
        #pragma unroll
        for (int o = 4; o > 0; o >>= 1) r += __shfl_xor_sync(0xffffffffu, r, o);
        if (lane == 0) sh[0] = r;
    }
    __syncthreads();
    float res = sh[0];
    __syncthreads();
    return res;
}

// ---------------- weight split: fp32 -> bf16 hi + bf16 lo ----------------
__global__ void split_kernel(const float* __restrict__ in,
                             __nv_bfloat16* __restrict__ hi,
                             __nv_bfloat16* __restrict__ lo, int n)
{
    int i = blockIdx.x*blockDim.x + threadIdx.x;
    if (i >= n) return;
    float x = in[i];
    __nv_bfloat16 h = __float2bfloat16(x);
    float r = x - __bfloat162float(h);
    hi[i] = h;
    lo[i] = __float2bfloat16(r);
}

// ---------------- bf16x3 tensor-core GEMM ----------------
// C[m,n] = sum_k (A[m,k] (+A2[m,k])) * W[n,k] + bias[n], optional relu.
// W pre-split into Wh/Wl (bf16). BM=BN=128, BK=32, 256 thr (8 warps 4x2), warp tile 32x64.
#define SST 40   // smem stride in bf16 units (conflict-free)

__device__ __forceinline__ void mma_bf16(float c[4], const unsigned a[4],
                                         unsigned b0, unsigned b1)
{
    asm volatile("mma.sync.aligned.m16n8k16.row.col.f32.bf16.bf16.f32 "
        "{%0,%1,%2,%3}, {%4,%5,%6,%7}, {%8,%9}, {%0,%1,%2,%3};"
        : "+f"(c[0]), "+f"(c[1]), "+f"(c[2]), "+f"(c[3])
        : "r"(a[0]), "r"(a[1]), "r"(a[2]), "r"(a[3]), "r"(b0), "r"(b1));
}

__global__ void __launch_bounds__(256, 2)
gemm_bf3_kernel(const float* __restrict__ A, const float* __restrict__ A2,
                const __nv_bfloat16* __restrict__ Wh, const __nv_bfloat16* __restrict__ Wl,
                const float* __restrict__ bias, float* __restrict__ C,
                int M, int N, int K, int relu)
{
    __shared__ __align__(16) __nv_bfloat16 sAh[128*SST];
    __shared__ __align__(16) __nv_bfloat16 sAl[128*SST];
    __shared__ __align__(16) __nv_bfloat16 sBh[128*SST];
    __shared__ __align__(16) __nv_bfloat16 sBl[128*SST];
    int tid  = threadIdx.x;
    int lane = tid & 31, warp = tid >> 5;
    int wm = warp & 3, wn = warp >> 2;
    int m0 = blockIdx.y * 128, n0 = blockIdx.x * 128;
    int g = lane >> 2, qd = lane & 3;
    int lrow = tid >> 1, lcol = (tid & 1) * 16;   // 2 threads/row, 16 cols each
    float acc[2][8][4] = {};

    for (int k0 = 0; k0 < K; k0 += 32) {
        // ---- load + split A tile (128x32 fp32 -> bf16 hi/lo) ----
        {
            int m = m0 + lrow;
            float v[16];
            if (m < M) {
                const float4* ap = (const float4*)(A + (size_t)m*K + k0 + lcol);
                #pragma unroll
                for (int j = 0; j < 4; j++) {
                    float4 f = ap[j];
                    v[4*j+0]=f.x; v[4*j+1]=f.y; v[4*j+2]=f.z; v[4*j+3]=f.w;
                }
                if (A2) {
                    const float4* a2p = (const float4*)(A2 + (size_t)m*K + k0 + lcol);
                    #pragma unroll
                    for (int j = 0; j < 4; j++) {
                        float4 f = a2p[j];
                        v[4*j+0]+=f.x; v[4*j+1]+=f.y; v[4*j+2]+=f.z; v[4*j+3]+=f.w;
                    }
                }
            } else {
                #pragma unroll
                for (int j = 0; j < 16; j++) v[j] = 0.f;
            }
            unsigned hw[8], lw[8];
            #pragma unroll
            for (int i = 0; i < 8; i++) {
                float x0 = v[2*i], x1 = v[2*i+1];
                __nv_bfloat162 h = __floats2bfloat162_rn(x0, x1);
                float r0 = x0 - __bfloat162float(h.x);
                float r1 = x1 - __bfloat162float(h.y);
                __nv_bfloat162 l = __floats2bfloat162_rn(r0, r1);
                hw[i] = *(unsigned*)&h;
                lw[i] = *(unsigned*)&l;
            }
            int sb = lrow*SST + lcol;
            #pragma unroll
            for (int j = 0; j < 4; j++) {
                *(uint2*)&sAh[sb + 4*j] = make_uint2(hw[2*j], hw[2*j+1]);
                *(uint2*)&sAl[sb + 4*j] = make_uint2(lw[2*j], lw[2*j+1]);
            }
            // ---- load B tile (pre-split bf16) ----
            const uint4* bph = (const uint4*)(Wh + (size_t)(n0+lrow)*K + k0 + lcol);
            const uint4* bpl = (const uint4*)(Wl + (size_t)(n0+lrow)*K + k0 + lcol);
            uint4 bh0 = bph[0], bh1 = bph[1];
            uint4 bl0 = bpl[0], bl1 = bpl[1];
            *(uint2*)&sBh[sb +  0] = make_uint2(bh0.x, bh0.y);
            *(uint2*)&sBh[sb +  4] = make_uint2(bh0.z, bh0.w);
            *(uint2*)&sBh[sb +  8] = make_uint2(bh1.x, bh1.y);
            *(uint2*)&sBh[sb + 12] = make_uint2(bh1.z, bh1.w);
            *(uint2*)&sBl[sb +  0] = make_uint2(bl0.x, bl0.y);
            *(uint2*)&sBl[sb +  4] = make_uint2(bl0.z, bl0.w);
            *(uint2*)&sBl[sb +  8] = make_uint2(bl1.x, bl1.y);
            *(uint2*)&sBl[sb + 12] = make_uint2(bl1.z, bl1.w);
        }
        __syncthreads();
        // ---- compute: 2 x (k16) steps, pure LDS + MMA ----
        #pragma unroll
        for (int kk = 0; kk < 32; kk += 16) {
            unsigned ah[2][4], al[2][4];
            #pragma unroll
            for (int im = 0; im < 2; im++) {
                int base = (wm*32 + im*16 + g)*SST + kk + 2*qd;
                ah[im][0] = *(const unsigned*)&sAh[base];
                ah[im][1] = *(const unsigned*)&sAh[base + 8*SST];
                ah[im][2] = *(const unsigned*)&sAh[base + 8];
                ah[im][3] = *(const unsigned*)&sAh[base + 8*SST + 8];
                al[im][0] = *(const unsigned*)&sAl[base];
                al[im][1] = *(const unsigned*)&sAl[base + 8*SST];
                al[im][2] = *(const unsigned*)&sAl[base + 8];
                al[im][3] = *(const unsigned*)&sAl[base + 8*SST + 8];
            }
            #pragma unroll
            for (int in_ = 0; in_ < 8; in_++) {
                int bb = (wn*64 + in_*8 + g)*SST + kk + 2*qd;
                unsigned bh0 = *(const unsigned*)&sBh[bb];
                unsigned bh1 = *(const unsigned*)&sBh[bb + 8];
                unsigned bl0 = *(const unsigned*)&sBl[bb];
                unsigned bl1 = *(const unsigned*)&sBl[bb + 8];
                #pragma unroll
                for (int im = 0; im < 2; im++) {
                    mma_bf16(acc[im][in_], ah[im], bh0, bh1);
                    mma_bf16(acc[im][in_], ah[im], bl0, bl1);
                    mma_bf16(acc[im][in_], al[im], bh0, bh1);
                }
            }
        }
        __syncthreads();
    }
    // ---- epilogue ----
    #pragma unroll
    for (int im = 0; im < 2; im++) {
        int r0 = m0 + wm*32 + im*16 + g;
        #pragma unroll
        for (int in_ = 0; in_ < 8; in_++) {
            int cn = n0 + wn*64 + in_*8 + qd*2;
            float bv0 = bias[cn], bv1 = bias[cn+1];
            float v0 = acc[im][in_][0] + bv0;
            float v1 = acc[im][in_][1] + bv1;
            float v2 = acc[im][in_][2] + bv0;
            float v3 = acc[im][in_][3] + bv1;
            if (relu) {
                v0 = fmaxf(v0, 0.f); v1 = fmaxf(v1, 0.f);
                v2 = fmaxf(v2, 0.f); v3 = fmaxf(v3, 0.f);
            }
            if (r0 < M)     *(float2*)(C + (size_t)r0*N + cn)     = make_float2(v0, v1);
            if (r0 + 8 < M) *(float2*)(C + (size_t)(r0+8)*N + cn) = make_float2(v2, v3);
        }
    }
}

// ---------------- GEMM (tokenizer): C[m,n] = sum_k A[k,m]*W[n,k] + bias[n]
__global__ void __launch_bounds__(256)
gemm_tn_kernel(const float* __restrict__ A, const float* __restrict__ W,
               const float* __restrict__ bias, float* __restrict__ C,
               int M, int N, int K)
{
    __shared__ __align__(16) float As[16][68];
    __shared__ __align__(16) float Ws[16][68];
    int tid = threadIdx.x;
    int tx = tid & 15, ty = tid >> 4;
    int m0 = blockIdx.y * 64, n0 = blockIdx.x * 64;
    int ak = tid >> 4, amq = (tid & 15) * 4;
    int wn = tid >> 2, wk  = (tid & 3) * 4;
    bool aok = (m0 + amq) < M;
    float acc[4][4] = {};
    for (int k0 = 0; k0 < K; k0 += 16) {
        float4 a4 = aok ? *(const float4*)(A + (size_t)(k0+ak)*M + m0 + amq)
                        : make_float4(0.f,0.f,0.f,0.f);
        *(float4*)&As[ak][amq] = a4;
        float4 w4 = *(const float4*)(W + (size_t)(n0+wn)*K + k0 + wk);
        Ws[wk+0][wn]=w4.x; Ws[wk+1][wn]=w4.y; Ws[wk+2][wn]=w4.z; Ws[wk+3][wn]=w4.w;
        __syncthreads();
        #pragma unroll
        for (int k = 0; k < 16; k++) {
            float4 a = *(const float4*)&As[k][ty*4];
            float4 w = *(const float4*)&Ws[k][tx*4];
            float ar[4] = {a.x,a.y,a.z,a.w}, wr[4] = {w.x,w.y,w.z,w.w};
            #pragma unroll
            for (int i = 0; i < 4; i++)
                #pragma unroll
                for (int j = 0; j < 4; j++)
                    acc[i][j] = fmaf(ar[i], wr[j], acc[i][j]);
        }
        __syncthreads();
    }
    #pragma unroll
    for (int i = 0; i < 4; i++) {
        int m = m0 + ty*4 + i;
        if (m >= M) break;
        #pragma unroll
        for (int j = 0; j < 4; j++) {
            int n = n0 + tx*4 + j;
            C[(size_t)m*N + n] = acc[i][j] + bias[n];
        }
    }
}

// ---------------- GroupNorm ----------------
__global__ void __launch_bounds__(256)
gn_kernel(float* __restrict__ src, const float* __restrict__ g, const float* __restrict__ b)
{
    int grp = blockIdx.x & 31;
    int bb  = (blockIdx.x >> 5) & 1;
    int lvl = blockIdx.x >> 6;
    int L = c_len[lvl], st = c_start[lvl];
    float* base = src + ((size_t)bb*LQT + st) * DD;
    int n = L * 8;
    float s = 0.f;
    for (int i = threadIdx.x; i < n; i += 256)
        s += base[(size_t)(i>>3)*DD + grp*8 + (i&7)];
    float mean = blockSum(s) / (float)n;
    float s2 = 0.f;
    for (int i = threadIdx.x; i < n; i += 256) {
        float d = base[(size_t)(i>>3)*DD + grp*8 + (i&7)] - mean;
        s2 += d*d;
    }
    float rstd = rsqrtf(blockSum(s2) / (float)n + 1e-5f);
    for (int i = threadIdx.x; i < n; i += 256) {
        int c = grp*8 + (i&7);
        size_t id = (size_t)(i>>3)*DD + c;
        base[id] = (base[id] - mean) * rstd * g[lvl*DD + c] + b[lvl*DD + c];
    }
}

// ---------------- sine positional embedding + level embed ----------------
__global__ void pos_kernel(const float* __restrict__ lemb, float* __restrict__ pos)
{
    int idx = blockIdx.x*blockDim.x + threadIdx.x;
    if (idx >= LQT*DD) return;
    int qq = idx >> 8, d = idx & 255;
    int lvl = lvl_of(qq);
    int st = c_start[lvl], H = c_H[lvl], W = c_W[lvl];
    int p = qq - st; int y = p / W, x = p % W;
    const float TWO_PI = 6.28318530717958647692f;
    const float LN1E4_64 = 0.14391156831212787f;
    float v;
    if (d < 128) {
        float e = (float)(y+1) / ((float)H + 1e-6f) * TWO_PI;
        int i = d >> 1;
        float u = e * expf(-LN1E4_64 * (float)i);
        v = (d & 1) ? cosf(u) : sinf(u);
    } else {
        int dd = d - 128;
        float e = (float)(x+1) / ((float)W + 1e-6f) * TWO_PI;
        int i = dd >> 1;
        float u = e * expf(-LN1E4_64 * (float)i);
        v = (dd & 1) ? cosf(u) : sinf(u);
    }
    v += lemb[lvl*DD + d];
    pos[(size_t)qq*DD + d] = v;
    pos[(size_t)(LQT + qq)*DD + d] = v;
}

__global__ void ref_kernel(float* __restrict__ ref)
{
    int qq = blockIdx.x*blockDim.x + threadIdx.x;
    if (qq >= LQT) return;
    int lvl = lvl_of(qq);
    int st = c_start[lvl], H = c_H[lvl], W = c_W[lvl];
    int p = qq - st; int y = p / W, x = p % W;
    ref[qq*2+0] = ((float)x + 0.5f) / (float)W;
    ref[qq*2+1] = ((float)y + 0.5f) / (float)H;
}

// ---------------- softmax over 16 ----------------
__global__ void softmax16_kernel(float* __restrict__ aw, int n)
{
    int t = blockIdx.x*blockDim.x + threadIdx.x;
    if (t >= n) return;
    float* p = aw + (size_t)t*16;
    float buf[16];
    float m = -1e30f;
    #pragma unroll
    for (int i = 0; i < 16; i++) { buf[i] = p[i]; m = fmaxf(m, buf[i]); }
    float s = 0.f;
    #pragma unroll
    for (int i = 0; i < 16; i++) { buf[i] = expf(buf[i] - m); s += buf[i]; }
    float inv = 1.f / s;
    #pragma unroll
    for (int i = 0; i < 16; i++) p[i] = buf[i] * inv;
}

// ---------------- ms-deform attention core ----------------
__global__ void __launch_bounds__(256)
msdeform_kernel(const float* __restrict__ val, const float* __restrict__ off,
                const float* __restrict__ aw, const float* __restrict__ ref,
                float* __restrict__ out)
{
    int warp = blockIdx.x * (blockDim.x >> 5) + (threadIdx.x >> 5);
    int lane = threadIdx.x & 31;
    if (warp >= NB*LQT*NHH) return;
    int h  = warp & 7;
    int bq = warp >> 3;
    int q  = bq % LQT;
    int b  = bq / LQT;
    float gx = ref[q*2], gy = ref[q*2+1];
    const float* offp = off + (size_t)bq*DD  + h*32;
    const float* awp  = aw  + (size_t)bq*128 + h*16;
    float acc = 0.f;
    #pragma unroll
    for (int l = 0; l < 4; l++) {
        int Wl = c_W[l], Hl = c_H[l], st = c_start[l];
        float fW = (float)Wl, fH = (float)Hl;
        const float* vb = val + ((size_t)b*LQT + st)*DD + h*32 + lane;
        #pragma unroll
        for (int p = 0; p < 4; p++) {
            float ox = offp[(l*4+p)*2+0], oy = offp[(l*4+p)*2+1];
            float a  = awp[l*4+p];
            float x = (gx + ox / fW) * fW - 0.5f;
            float y = (gy + oy / fH) * fH - 0.5f;
            float x0f = floorf(x), y0f = floorf(y);
            float tx = x - x0f, ty = y - y0f;
            int x0 = (int)x0f, y0 = (int)y0f;
            float w00 = (1.f-tx)*(1.f-ty)*a;
            float w10 = tx*(1.f-ty)*a;
            float w01 = (1.f-tx)*ty*a;
            float w11 = tx*ty*a;
            bool xv0 = (x0   >= 0) && (x0   < Wl);
            bool xv1 = (x0+1 >= 0) && (x0+1 < Wl);
            bool yv0 = (y0   >= 0) && (y0   < Hl);
            bool yv1 = (y0+1 >= 0) && (y0+1 < Hl);
            if (xv0 && yv0) acc += w00 * vb[(size_t)(y0*Wl + x0)     * DD];
            if (xv1 && yv0) acc += w10 * vb[(size_t)(y0*Wl + x0 + 1) * DD];
            if (xv0 && yv1) acc += w01 * vb[(size_t)((y0+1)*Wl + x0)     * DD];
            if (xv1 && yv1) acc += w11 * vb[(size_t)((y0+1)*Wl + x0 + 1) * DD];
        }
    }
    out[(size_t)bq*DD + h*32 + lane] = acc;
}

// ---------------- residual + LayerNorm ----------------
__global__ void __launch_bounds__(256)
addln_kernel(float* __restrict__ src, const float* __restrict__ res,
             const float* __restrict__ g, const float* __restrict__ b)
{
    int row = blockIdx.x, t = threadIdx.x;
    size_t idx = (size_t)row*DD + t;
    float x = src[idx] + res[idx];
    float mean = blockSum(x) * (1.f/DD);
    float d = x - mean;
    float var = blockSum(d*d) * (1.f/DD);
    src[idx] = d * rsqrtf(var + 1e-5f) * g[t] + b[t];
}

// ---------------- finalize ----------------
__global__ void finalize_kernel(const float* __restrict__ src, float* __restrict__ out, int out_size)
{
    int i = blockIdx.x*blockDim.x + threadIdx.x;
    if (i >= out_size) return;
    const int n = NB*LQT*DD;
    if (i < n) { out[i] = src[i]; return; }
    int j = i - n;
    float v;
    if (j < 4)       v = (float)c_start[j];
    else if (j < 12) v = (float)c_H[(j-4) >> 1];
    else             v = 1.0f;
    out[i] = v;
}

// ---------------- host orchestration ----------------
extern "C" void kernel_launch(void* const* d_in, const int* in_sizes, int n_in,
                              void* d_out, int out_size)
{
    (void)n_in;
    const float *X[4], *FW[4], *FB[4];
    if (in_sizes[1] == 65536) {
        for (int i = 0; i < 4; i++) {
            X[i]  = (const float*)d_in[3*i+0];
            FW[i] = (const float*)d_in[3*i+1];
            FB[i] = (const float*)d_in[3*i+2];
        }
    } else {
        for (int i = 0; i < 4; i++) {
            X[i]  = (const float*)d_in[i];
            FW[i] = (const float*)d_in[4+2*i];
            FB[i] = (const float*)d_in[5+2*i];
        }
    }
    const float* gn_g  = (const float*)d_in[12];
    const float* gn_b  = (const float*)d_in[13];
    const float* lemb  = (const float*)d_in[14];
    const float* off_w = (const float*)d_in[15];
    const float* off_b = (const float*)d_in[16];
    const float* aw_w  = (const float*)d_in[17];
    const float* aw_b  = (const float*)d_in[18];
    const float* val_w = (const float*)d_in[19];
    const float* val_b = (const float*)d_in[20];
    const float* out_w = (const float*)d_in[21];
    const float* out_b = (const float*)d_in[22];
    const float* ln1_g = (const float*)d_in[23];
    const float* ln1_b = (const float*)d_in[24];
    const float* l1_w  = (const float*)d_in[25];
    const float* l1_b  = (const float*)d_in[26];
    const float* l2_w  = (const float*)d_in[27];
    const float* l2_b  = (const float*)d_in[28];
    const float* ln2_g = (const float*)d_in[29];
    const float* ln2_b = (const float*)d_in[30];

    float *src, *pos, *off, *aw, *val, *msd, *att, *hbuf, *ref;
    __nv_bfloat16 *wh, *wl;
    cudaGetSymbolAddress((void**)&src,  g_src);
    cudaGetSymbolAddress((void**)&pos,  g_pos);
    cudaGetSymbolAddress((void**)&off,  g_off);
    cudaGetSymbolAddress((void**)&aw,   g_aw);
    cudaGetSymbolAddress((void**)&val,  g_val);
    cudaGetSymbolAddress((void**)&msd,  g_msd);
    cudaGetSymbolAddress((void**)&att,  g_att);
    cudaGetSymbolAddress((void**)&hbuf, g_h);
    cudaGetSymbolAddress((void**)&ref,  g_ref);
    cudaGetSymbolAddress((void**)&wh,   g_wh);
    cudaGetSymbolAddress((void**)&wl,   g_wl);

    // ---- pre-split all layer weights into bf16 hi/lo ----
    {
        struct { const float* p; int off; int n; } ws[6] = {
            { off_w, OFF_OFF, 6*256*256 },
            { aw_w,  OFF_AW,  6*128*256 },
            { val_w, OFF_VAL, 6*256*256 },
            { out_w, OFF_OUT, 6*256*256 },
            { l1_w,  OFF_L1,  6*1024*256 },
            { l2_w,  OFF_L2,  6*256*1024 },
        };
        for (int i = 0; i < 6; i++)
            split_kernel<<<(ws[i].n + 255)/256, 256>>>(ws[i].p, wh + ws[i].off, wl + ws[i].off, ws[i].n);
    }

    const int HS[4] = {96,48,24,12};
    const int CIN[4] = {256,512,768,1024};
    const int START[4] = {0,9216,11520,12096};

    for (int l = 0; l < 4; l++) {
        int HW = HS[l]*HS[l];
        dim3 grid(DD/64, (HW + 63)/64);
        for (int b = 0; b < 2; b++) {
            gemm_tn_kernel<<<grid, 256>>>(
                X[l] + (size_t)b*CIN[l]*HW, FW[l], FB[l],
                src + ((size_t)b*LQT + START[l])*DD, HW, DD, CIN[l]);
        }
    }
    gn_kernel<<<4*2*32, 256>>>(src, gn_g, gn_b);
    pos_kernel<<<(LQT*DD + 255)/256, 256>>>(lemb, pos);
    ref_kernel<<<(LQT + 255)/256, 256>>>(ref);

    int gy = (MTOT + 127)/128;
    dim3 g256(DD/128,   gy);
    dim3 g128(1,        gy);
    dim3 g1024(DFF_/128, gy);

    for (int l = 0; l < NLAY; l++) {
        gemm_bf3_kernel<<<g256, 256>>>(src, pos,
            wh + OFF_OFF + (size_t)l*65536, wl + OFF_OFF + (size_t)l*65536,
            off_b + l*DD, off, MTOT, DD, DD, 0);
        gemm_bf3_kernel<<<g128, 256>>>(src, pos,
            wh + OFF_AW + (size_t)l*32768, wl + OFF_AW + (size_t)l*32768,
            aw_b + l*128, aw, MTOT, 128, DD, 0);
        softmax16_kernel<<<(MTOT*NHH + 255)/256, 256>>>(aw, MTOT*NHH);
        gemm_bf3_kernel<<<g256, 256>>>(src, (const float*)0,
            wh + OFF_VAL + (size_t)l*65536, wl + OFF_VAL + (size_t)l*65536,
            val_b + l*DD, val, MTOT, DD, DD, 0);
        msdeform_kernel<<<MTOT, 256>>>(val, off, aw, ref, msd);
        gemm_bf3_kernel<<<g256, 256>>>(msd, (const float*)0,
            wh + OFF_OUT + (size_t)l*65536, wl + OFF_OUT + (size_t)l*65536,
            out_b + l*DD, att, MTOT, DD, DD, 0);
        addln_kernel<<<MTOT, 256>>>(src, att, ln1_g + l*DD, ln1_b + l*DD);
        gemm_bf3_kernel<<<g1024, 256>>>(src, (const float*)0,
            wh + OFF_L1 + (size_t)l*262144, wl + OFF_L1 + (size_t)l*262144,
            l1_b + l*DFF_, hbuf, MTOT, DFF_, DD, 1);
        gemm_bf3_kernel<<<g256, 256>>>(hbuf, (const float*)0,
            wh + OFF_L2 + (size_t)l*262144, wl + OFF_L2 + (size_t)l*262144,
            l2_b + l*DD, att, MTOT, DD, DFF_, 0);
        addln_kernel<<<MTOT, 256>>>(src, att, ln2_g + l*DD, ln2_b + l*DD);
    }

    finalize_kernel<<<(out_size + 255)/256, 256>>>(src, (float*)d_out, out_size);
}

// round 6
// speedup vs baseline: 1.8163x; 1.1405x over previous
#include <cuda_runtime.h>
#include <cuda_bf16.h>
#include <stdint.h>
#include <math.h>

// ---------------- problem constants ----------------
#define NB    2
#define DD    256
#define LQT   12240
#define NHH   8
#define NLAY  6
#define DFF_  1024
#define MTOT  (NB*LQT)   // 24480

__constant__ int c_H[4]     = {96,48,24,12};
__constant__ int c_W[4]     = {96,48,24,12};
__constant__ int c_start[4] = {0,9216,11520,12096};
__constant__ int c_len[4]   = {9216,2304,576,144};

// ---------------- scratch (device globals; no allocation) ----------------
__device__ float g_src[NB*LQT*DD];
__device__ float g_pos[NB*LQT*DD];
__device__ float g_q  [NB*LQT*DD];
__device__ float g_off[NB*LQT*DD];
__device__ float g_aw [NB*LQT*128];
__device__ float g_val[NB*LQT*DD];
__device__ float g_msd[NB*LQT*DD];
__device__ float g_att[NB*LQT*DD];
__device__ float g_h  [NB*LQT*DFF_];
__device__ float g_ref[LQT*2];

// pre-split layer weights (bf16 hi/lo)
#define OFF_OFF 0
#define OFF_AW  393216
#define OFF_VAL 589824
#define OFF_OUT 983040
#define OFF_L1  1376256
#define OFF_L2  2949120
#define W_TOTAL 4521984
__device__ __nv_bfloat16 g_wh[W_TOTAL];
__device__ __nv_bfloat16 g_wl[W_TOTAL];

__device__ __forceinline__ int lvl_of(int q) {
    return (q < 9216) ? 0 : (q < 11520) ? 1 : (q < 12096) ? 2 : 3;
}

__device__ __forceinline__ float blockSum(float v) {
    __shared__ float sh[8];
    int lane = threadIdx.x & 31, w = threadIdx.x >> 5;
    #pragma unroll
    for (int o = 16; o > 0; o >>= 1) v += __shfl_xor_sync(0xffffffffu, v, o);
    if (lane == 0) sh[w] = v;
    __syncthreads();
    if (w == 0) {
        float r = (lane < 8) ? sh[lane] : 0.f;
        #pragma unroll
        for (int o = 4; o > 0; o >>= 1) r += __shfl_xor_sync(0xffffffffu, r, o);
        if (lane == 0) sh[0] = r;
    }
    __syncthreads();
    float res = sh[0];
    __syncthreads();
    return res;
}

// ---------------- weight split ----------------
__global__ void split_kernel(const float* __restrict__ in,
                             __nv_bfloat16* __restrict__ hi,
                             __nv_bfloat16* __restrict__ lo, int n)
{
    int i = blockIdx.x*blockDim.x + threadIdx.x;
    if (i >= n) return;
    float x = in[i];
    __nv_bfloat16 h = __float2bfloat16(x);
    hi[i] = h;
    lo[i] = __float2bfloat16(x - __bfloat162float(h));
}

// ---------------- pipelined bf16x3 tensor-core GEMM ----------------
// C[m,n] = sum_k A[m,k]*W[n,k] + bias[n]; W pre-split bf16 hi/lo.
// BM=BN=128, BK=32, 256 thr (8 warps 4x2), warp tile 32x64.
// Dynamic smem: Ah(10240) Al(10240) + 2 stages x [Bh(10240) Bl(10240)] = 61440 B.
#define SMEM_A_L   10240
#define SMEM_B0    20480
#define SMEM_STG   20480
#define SMEM_TOTAL_G 61440

__device__ __forceinline__ void mma_bf16(float c[4], const unsigned a[4],
                                         unsigned b0, unsigned b1)
{
    asm volatile("mma.sync.aligned.m16n8k16.row.col.f32.bf16.bf16.f32 "
        "{%0,%1,%2,%3}, {%4,%5,%6,%7}, {%8,%9}, {%0,%1,%2,%3};"
        : "+f"(c[0]), "+f"(c[1]), "+f"(c[2]), "+f"(c[3])
        : "r"(a[0]), "r"(a[1]), "r"(a[2]), "r"(a[3]), "r"(b0), "r"(b1));
}

__device__ __forceinline__ void ldsm4(unsigned r[4], unsigned a) {
    asm volatile("ldmatrix.sync.aligned.m8n8.x4.shared.b16 {%0,%1,%2,%3}, [%4];"
        : "=r"(r[0]), "=r"(r[1]), "=r"(r[2]), "=r"(r[3]) : "r"(a));
}

__device__ __forceinline__ void cp_async16(unsigned dst, const void* src) {
    asm volatile("cp.async.cg.shared.global [%0], [%1], 16;" :: "r"(dst), "l"(src));
}
__device__ __forceinline__ void cp_commit() {
    asm volatile("cp.async.commit_group;");
}
__device__ __forceinline__ void cp_wait0() {
    asm volatile("cp.async.wait_group 0;");
}

__global__ void __launch_bounds__(256, 2)
gemm_bf3_kernel(const float* __restrict__ A,
                const __nv_bfloat16* __restrict__ Wh, const __nv_bfloat16* __restrict__ Wl,
                const float* __restrict__ bias, float* __restrict__ C,
                int M, int N, int K, int relu)
{
    extern __shared__ __align__(16) char smem[];
    __nv_bfloat16* sAh = (__nv_bfloat16*)smem;
    __nv_bfloat16* sAl = (__nv_bfloat16*)(smem + SMEM_A_L);
    unsigned sbase = (unsigned)__cvta_generic_to_shared(smem);

    int tid  = threadIdx.x;
    int lane = tid & 31, warp = tid >> 5;
    int wm = warp & 3, wn = warp >> 2;
    int m0 = blockIdx.y * 128, n0 = blockIdx.x * 128;
    int g = lane >> 2, qd = lane & 3;
    int lrow = tid >> 1, lcol = (tid & 1) * 16;

    // lane-invariant ldmatrix base addresses (bytes)
    unsigned aAh = sbase + (unsigned)(((wm*32 + (lane & 15))*40 + ((lane >> 4)*8))*2);
    unsigned aAl = aAh + SMEM_A_L;
    unsigned aB_rel = (unsigned)(((wn*64 + ((lane >> 4) & 1)*8 + (lane & 7))*40 + (((lane >> 3) & 1)*8))*2);

    // cp.async target offset (bytes within a B stage)
    unsigned bso = (unsigned)((lrow*40 + lcol)*2);

    float acc[2][8][4] = {};
    float v[16];
    const int NT = K / 32;
    bool mok = (m0 + lrow) < M;

    // ---- prologue: tile 0 ----
    {
        const float4* ap = (const float4*)(A + (size_t)(m0 + lrow)*K + lcol);
        #pragma unroll
        for (int j = 0; j < 4; j++) {
            float4 f = mok ? ap[j] : make_float4(0.f,0.f,0.f,0.f);
            v[4*j+0]=f.x; v[4*j+1]=f.y; v[4*j+2]=f.z; v[4*j+3]=f.w;
        }
        unsigned dst = sbase + SMEM_B0 + bso;
        size_t go = (size_t)(n0 + lrow)*K + lcol;
        cp_async16(dst,      Wh + go);
        cp_async16(dst + 16, Wh + go + 8);
        cp_async16(dst + SMEM_A_L,      Wl + go);
        cp_async16(dst + SMEM_A_L + 16, Wl + go + 8);
        cp_commit();
        #pragma unroll
        for (int i = 0; i < 8; i++) {
            float x0 = v[2*i], x1 = v[2*i+1];
            __nv_bfloat162 h = __floats2bfloat162_rn(x0, x1);
            __nv_bfloat162 l = __floats2bfloat162_rn(x0 - __bfloat162float(h.x),
                                                     x1 - __bfloat162float(h.y));
            *(__nv_bfloat162*)&sAh[lrow*40 + lcol + 2*i] = h;
            *(__nv_bfloat162*)&sAl[lrow*40 + lcol + 2*i] = l;
        }
        cp_wait0();
        __syncthreads();
    }

    for (int t = 0; t < NT; t++) {
        // ---- issue loads for tile t+1 ----
        if (t + 1 < NT) {
            int k0 = (t + 1) * 32;
            const float4* ap = (const float4*)(A + (size_t)(m0 + lrow)*K + k0 + lcol);
            #pragma unroll
            for (int j = 0; j < 4; j++) {
                float4 f = mok ? ap[j] : make_float4(0.f,0.f,0.f,0.f);
                v[4*j+0]=f.x; v[4*j+1]=f.y; v[4*j+2]=f.z; v[4*j+3]=f.w;
            }
            unsigned dst = sbase + SMEM_B0 + (unsigned)(((t+1) & 1)*SMEM_STG) + bso;
            size_t go = (size_t)(n0 + lrow)*K + k0 + lcol;
            cp_async16(dst,      Wh + go);
            cp_async16(dst + 16, Wh + go + 8);
            cp_async16(dst + SMEM_A_L,      Wl + go);
            cp_async16(dst + SMEM_A_L + 16, Wl + go + 8);
            cp_commit();
        }
        // ---- compute tile t ----
        unsigned bB = sbase + SMEM_B0 + (unsigned)((t & 1)*SMEM_STG) + aB_rel;
        #pragma unroll
        for (int kk = 0; kk < 2; kk++) {
            unsigned ah[2][4], al[2][4];
            #pragma unroll
            for (int im = 0; im < 2; im++) {
                ldsm4(ah[im], aAh + im*1280 + kk*32);
                ldsm4(al[im], aAl + im*1280 + kk*32);
            }
            #pragma unroll
            for (int j = 0; j < 4; j++) {
                unsigned bh[4], bl[4];
                ldsm4(bh, bB + j*1280 + kk*32);
                ldsm4(bl, bB + SMEM_A_L + j*1280 + kk*32);
                #pragma unroll
                for (int im = 0; im < 2; im++) {
                    mma_bf16(acc[im][2*j],   ah[im], bh[0], bh[1]);
                    mma_bf16(acc[im][2*j],   ah[im], bl[0], bl[1]);
                    mma_bf16(acc[im][2*j],   al[im], bh[0], bh[1]);
                    mma_bf16(acc[im][2*j+1], ah[im], bh[2], bh[3]);
                    mma_bf16(acc[im][2*j+1], ah[im], bl[2], bl[3]);
                    mma_bf16(acc[im][2*j+1], al[im], bh[2], bh[3]);
                }
            }
        }
        __syncthreads();   // all warps done reading sAh/sAl
        if (t + 1 < NT) {
            #pragma unroll
            for (int i = 0; i < 8; i++) {
                float x0 = v[2*i], x1 = v[2*i+1];
                __nv_bfloat162 h = __floats2bfloat162_rn(x0, x1);
                __nv_bfloat162 l = __floats2bfloat162_rn(x0 - __bfloat162float(h.x),
                                                         x1 - __bfloat162float(h.y));
                *(__nv_bfloat162*)&sAh[lrow*40 + lcol + 2*i] = h;
                *(__nv_bfloat162*)&sAl[lrow*40 + lcol + 2*i] = l;
            }
            cp_wait0();
        }
        __syncthreads();
    }

    // ---- epilogue ----
    #pragma unroll
    for (int im = 0; im < 2; im++) {
        int r0 = m0 + wm*32 + im*16 + g;
        #pragma unroll
        for (int in_ = 0; in_ < 8; in_++) {
            int cn = n0 + wn*64 + in_*8 + qd*2;
            float bv0 = bias[cn], bv1 = bias[cn+1];
            float v0 = acc[im][in_][0] + bv0;
            float v1 = acc[im][in_][1] + bv1;
            float v2 = acc[im][in_][2] + bv0;
            float v3 = acc[im][in_][3] + bv1;
            if (relu) {
                v0 = fmaxf(v0, 0.f); v1 = fmaxf(v1, 0.f);
                v2 = fmaxf(v2, 0.f); v3 = fmaxf(v3, 0.f);
            }
            if (r0 < M)     *(float2*)(C + (size_t)r0*N + cn)     = make_float2(v0, v1);
            if (r0 + 8 < M) *(float2*)(C + (size_t)(r0+8)*N + cn) = make_float2(v2, v3);
        }
    }
}

// ---------------- GEMM (tokenizer): C[m,n] = sum_k A[k,m]*W[n,k] + bias[n]
__global__ void __launch_bounds__(256)
gemm_tn_kernel(const float* __restrict__ A, const float* __restrict__ W,
               const float* __restrict__ bias, float* __restrict__ C,
               int M, int N, int K)
{
    __shared__ __align__(16) float As[16][68];
    __shared__ __align__(16) float Ws[16][68];
    int tid = threadIdx.x;
    int tx = tid & 15, ty = tid >> 4;
    int m0 = blockIdx.y * 64, n0 = blockIdx.x * 64;
    int ak = tid >> 4, amq = (tid & 15) * 4;
    int wn = tid >> 2, wk  = (tid & 3) * 4;
    bool aok = (m0 + amq) < M;
    float acc[4][4] = {};
    for (int k0 = 0; k0 < K; k0 += 16) {
        float4 a4 = aok ? *(const float4*)(A + (size_t)(k0+ak)*M + m0 + amq)
                        : make_float4(0.f,0.f,0.f,0.f);
        *(float4*)&As[ak][amq] = a4;
        float4 w4 = *(const float4*)(W + (size_t)(n0+wn)*K + k0 + wk);
        Ws[wk+0][wn]=w4.x; Ws[wk+1][wn]=w4.y; Ws[wk+2][wn]=w4.z; Ws[wk+3][wn]=w4.w;
        __syncthreads();
        #pragma unroll
        for (int k = 0; k < 16; k++) {
            float4 a = *(const float4*)&As[k][ty*4];
            float4 w = *(const float4*)&Ws[k][tx*4];
            float ar[4] = {a.x,a.y,a.z,a.w}, wr[4] = {w.x,w.y,w.z,w.w};
            #pragma unroll
            for (int i = 0; i < 4; i++)
                #pragma unroll
                for (int j = 0; j < 4; j++)
                    acc[i][j] = fmaf(ar[i], wr[j], acc[i][j]);
        }
        __syncthreads();
    }
    #pragma unroll
    for (int i = 0; i < 4; i++) {
        int m = m0 + ty*4 + i;
        if (m >= M) break;
        #pragma unroll
        for (int j = 0; j < 4; j++) {
            int n = n0 + tx*4 + j;
            C[(size_t)m*N + n] = acc[i][j] + bias[n];
        }
    }
}

// ---------------- GroupNorm ----------------
__global__ void __launch_bounds__(256)
gn_kernel(float* __restrict__ src, const float* __restrict__ g, const float* __restrict__ b)
{
    int grp = blockIdx.x & 31;
    int bb  = (blockIdx.x >> 5) & 1;
    int lvl = blockIdx.x >> 6;
    int L = c_len[lvl], st = c_start[lvl];
    float* base = src + ((size_t)bb*LQT + st) * DD;
    int n = L * 8;
    float s = 0.f;
    for (int i = threadIdx.x; i < n; i += 256)
        s += base[(size_t)(i>>3)*DD + grp*8 + (i&7)];
    float mean = blockSum(s) / (float)n;
    float s2 = 0.f;
    for (int i = threadIdx.x; i < n; i += 256) {
        float d = base[(size_t)(i>>3)*DD + grp*8 + (i&7)] - mean;
        s2 += d*d;
    }
    float rstd = rsqrtf(blockSum(s2) / (float)n + 1e-5f);
    for (int i = threadIdx.x; i < n; i += 256) {
        int c = grp*8 + (i&7);
        size_t id = (size_t)(i>>3)*DD + c;
        base[id] = (base[id] - mean) * rstd * g[lvl*DD + c] + b[lvl*DD + c];
    }
}

// ---------------- sine positional embedding + level embed ----------------
__global__ void pos_kernel(const float* __restrict__ lemb, float* __restrict__ pos)
{
    int idx = blockIdx.x*blockDim.x + threadIdx.x;
    if (idx >= LQT*DD) return;
    int qq = idx >> 8, d = idx & 255;
    int lvl = lvl_of(qq);
    int st = c_start[lvl], H = c_H[lvl], W = c_W[lvl];
    int p = qq - st; int y = p / W, x = p % W;
    const float TWO_PI = 6.28318530717958647692f;
    const float LN1E4_64 = 0.14391156831212787f;
    float v;
    if (d < 128) {
        float e = (float)(y+1) / ((float)H + 1e-6f) * TWO_PI;
        int i = d >> 1;
        float u = e * expf(-LN1E4_64 * (float)i);
        v = (d & 1) ? cosf(u) : sinf(u);
    } else {
        int dd = d - 128;
        float e = (float)(x+1) / ((float)W + 1e-6f) * TWO_PI;
        int i = dd >> 1;
        float u = e * expf(-LN1E4_64 * (float)i);
        v = (dd & 1) ? cosf(u) : sinf(u);
    }
    v += lemb[lvl*DD + d];
    pos[(size_t)qq*DD + d] = v;
    pos[(size_t)(LQT + qq)*DD + d] = v;
}

__global__ void ref_kernel(float* __restrict__ ref)
{
    int qq = blockIdx.x*blockDim.x + threadIdx.x;
    if (qq >= LQT) return;
    int lvl = lvl_of(qq);
    int st = c_start[lvl], H = c_H[lvl], W = c_W[lvl];
    int p = qq - st; int y = p / W, x = p % W;
    ref[qq*2+0] = ((float)x + 0.5f) / (float)W;
    ref[qq*2+1] = ((float)y + 0.5f) / (float)H;
}

__global__ void add4_kernel(const float4* __restrict__ a, const float4* __restrict__ b,
                            float4* __restrict__ c, int n4)
{
    int i = blockIdx.x*blockDim.x + threadIdx.x;
    if (i < n4) {
        float4 x = a[i], y = b[i];
        c[i] = make_float4(x.x+y.x, x.y+y.y, x.z+y.z, x.w+y.w);
    }
}

// ---------------- softmax over 16 ----------------
__global__ void softmax16_kernel(float* __restrict__ aw, int n)
{
    int t = blockIdx.x*blockDim.x + threadIdx.x;
    if (t >= n) return;
    float* p = aw + (size_t)t*16;
    float buf[16];
    float m = -1e30f;
    #pragma unroll
    for (int i = 0; i < 16; i++) { buf[i] = p[i]; m = fmaxf(m, buf[i]); }
    float s = 0.f;
    #pragma unroll
    for (int i = 0; i < 16; i++) { buf[i] = expf(buf[i] - m); s += buf[i]; }
    float inv = 1.f / s;
    #pragma unroll
    for (int i = 0; i < 16; i++) p[i] = buf[i] * inv;
}

// ---------------- ms-deform attention core ----------------
__global__ void __launch_bounds__(256)
msdeform_kernel(const float* __restrict__ val, const float* __restrict__ off,
                const float* __restrict__ aw, const float* __restrict__ ref,
                float* __restrict__ out)
{
    int warp = blockIdx.x * (blockDim.x >> 5) + (threadIdx.x >> 5);
    int lane = threadIdx.x & 31;
    if (warp >= NB*LQT*NHH) return;
    int h  = warp & 7;
    int bq = warp >> 3;
    int q  = bq % LQT;
    int b  = bq / LQT;
    float gx = ref[q*2], gy = ref[q*2+1];
    const float* offp = off + (size_t)bq*DD  + h*32;
    const float* awp  = aw  + (size_t)bq*128 + h*16;
    float acc = 0.f;
    #pragma unroll
    for (int l = 0; l < 4; l++) {
        int Wl = c_W[l], Hl = c_H[l], st = c_start[l];
        float fW = (float)Wl, fH = (float)Hl;
        const float* vb = val + ((size_t)b*LQT + st)*DD + h*32 + lane;
        #pragma unroll
        for (int p = 0; p < 4; p++) {
            float ox = offp[(l*4+p)*2+0], oy = offp[(l*4+p)*2+1];
            float a  = awp[l*4+p];
            float x = (gx + ox / fW) * fW - 0.5f;
            float y = (gy + oy / fH) * fH - 0.5f;
            float x0f = floorf(x), y0f = floorf(y);
            float tx = x - x0f, ty = y - y0f;
            int x0 = (int)x0f, y0 = (int)y0f;
            float w00 = (1.f-tx)*(1.f-ty)*a;
            float w10 = tx*(1.f-ty)*a;
            float w01 = (1.f-tx)*ty*a;
            float w11 = tx*ty*a;
            bool xv0 = (x0   >= 0) && (x0   < Wl);
            bool xv1 = (x0+1 >= 0) && (x0+1 < Wl);
            bool yv0 = (y0   >= 0) && (y0   < Hl);
            bool yv1 = (y0+1 >= 0) && (y0+1 < Hl);
            if (xv0 && yv0) acc += w00 * vb[(size_t)(y0*Wl + x0)     * DD];
            if (xv1 && yv0) acc += w10 * vb[(size_t)(y0*Wl + x0 + 1) * DD];
            if (xv0 && yv1) acc += w01 * vb[(size_t)((y0+1)*Wl + x0)     * DD];
            if (xv1 && yv1) acc += w11 * vb[(size_t)((y0+1)*Wl + x0 + 1) * DD];
        }
    }
    out[(size_t)bq*DD + h*32 + lane] = acc;
}

// ---------------- residual + LayerNorm ----------------
__global__ void __launch_bounds__(256)
addln_kernel(float* __restrict__ src, const float* __restrict__ res,
             const float* __restrict__ g, const float* __restrict__ b)
{
    int row = blockIdx.x, t = threadIdx.x;
    size_t idx = (size_t)row*DD + t;
    float x = src[idx] + res[idx];
    float mean = blockSum(x) * (1.f/DD);
    float d = x - mean;
    float var = blockSum(d*d) * (1.f/DD);
    src[idx] = d * rsqrtf(var + 1e-5f) * g[t] + b[t];
}

// ---------------- finalize ----------------
__global__ void finalize_kernel(const float* __restrict__ src, float* __restrict__ out, int out_size)
{
    int i = blockIdx.x*blockDim.x + threadIdx.x;
    if (i >= out_size) return;
    const int n = NB*LQT*DD;
    if (i < n) { out[i] = src[i]; return; }
    int j = i - n;
    float v;
    if (j < 4)       v = (float)c_start[j];
    else if (j < 12) v = (float)c_H[(j-4) >> 1];
    else             v = 1.0f;
    out[i] = v;
}

// ---------------- host orchestration ----------------
extern "C" void kernel_launch(void* const* d_in, const int* in_sizes, int n_in,
                              void* d_out, int out_size)
{
    (void)n_in;
    const float *X[4], *FW[4], *FB[4];
    if (in_sizes[1] == 65536) {
        for (int i = 0; i < 4; i++) {
            X[i]  = (const float*)d_in[3*i+0];
            FW[i] = (const float*)d_in[3*i+1];
            FB[i] = (const float*)d_in[3*i+2];
        }
    } else {
        for (int i = 0; i < 4; i++) {
            X[i]  = (const float*)d_in[i];
            FW[i] = (const float*)d_in[4+2*i];
            FB[i] = (const float*)d_in[5+2*i];
        }
    }
    const float* gn_g  = (const float*)d_in[12];
    const float* gn_b  = (const float*)d_in[13];
    const float* lemb  = (const float*)d_in[14];
    const float* off_w = (const float*)d_in[15];
    const float* off_b = (const float*)d_in[16];
    const float* aw_w  = (const float*)d_in[17];
    const float* aw_b  = (const float*)d_in[18];
    const float* val_w = (const float*)d_in[19];
    const float* val_b = (const float*)d_in[20];
    const float* out_w = (const float*)d_in[21];
    const float* out_b = (const float*)d_in[22];
    const float* ln1_g = (const float*)d_in[23];
    const float* ln1_b = (const float*)d_in[24];
    const float* l1_w  = (const float*)d_in[25];
    const float* l1_b  = (const float*)d_in[26];
    const float* l2_w  = (const float*)d_in[27];
    const float* l2_b  = (const float*)d_in[28];
    const float* ln2_g = (const float*)d_in[29];
    const float* ln2_b = (const float*)d_in[30];

    float *src, *pos, *q, *off, *aw, *val, *msd, *att, *hbuf, *ref;
    __nv_bfloat16 *wh, *wl;
    cudaGetSymbolAddress((void**)&src,  g_src);
    cudaGetSymbolAddress((void**)&pos,  g_pos);
    cudaGetSymbolAddress((void**)&q,    g_q);
    cudaGetSymbolAddress((void**)&off,  g_off);
    cudaGetSymbolAddress((void**)&aw,   g_aw);
    cudaGetSymbolAddress((void**)&val,  g_val);
    cudaGetSymbolAddress((void**)&msd,  g_msd);
    cudaGetSymbolAddress((void**)&att,  g_att);
    cudaGetSymbolAddress((void**)&hbuf, g_h);
    cudaGetSymbolAddress((void**)&ref,  g_ref);
    cudaGetSymbolAddress((void**)&wh,   g_wh);
    cudaGetSymbolAddress((void**)&wl,   g_wl);

    cudaFuncSetAttribute(gemm_bf3_kernel,
        cudaFuncAttributeMaxDynamicSharedMemorySize, SMEM_TOTAL_G);

    // ---- pre-split all layer weights ----
    {
        struct { const float* p; int off; int n; } ws[6] = {
            { off_w, OFF_OFF, 6*256*256 },
            { aw_w,  OFF_AW,  6*128*256 },
            { val_w, OFF_VAL, 6*256*256 },
            { out_w, OFF_OUT, 6*256*256 },
            { l1_w,  OFF_L1,  6*1024*256 },
            { l2_w,  OFF_L2,  6*256*1024 },
        };
        for (int i = 0; i < 6; i++)
            split_kernel<<<(ws[i].n + 255)/256, 256>>>(ws[i].p, wh + ws[i].off, wl + ws[i].off, ws[i].n);
    }

    const int HS[4] = {96,48,24,12};
    const int CIN[4] = {256,512,768,1024};
    const int START[4] = {0,9216,11520,12096};

    for (int l = 0; l < 4; l++) {
        int HW = HS[l]*HS[l];
        dim3 grid(DD/64, (HW + 63)/64);
        for (int b = 0; b < 2; b++) {
            gemm_tn_kernel<<<grid, 256>>>(
                X[l] + (size_t)b*CIN[l]*HW, FW[l], FB[l],
                src + ((size_t)b*LQT + START[l])*DD, HW, DD, CIN[l]);
        }
    }
    gn_kernel<<<4*2*32, 256>>>(src, gn_g, gn_b);
    pos_kernel<<<(LQT*DD + 255)/256, 256>>>(lemb, pos);
    ref_kernel<<<(LQT + 255)/256, 256>>>(ref);

    int gy = (MTOT + 127)/128;
    dim3 g256(DD/128,   gy);
    dim3 g128(1,        gy);
    dim3 g1024(DFF_/128, gy);
    int n4 = MTOT*DD/4;

    for (int l = 0; l < NLAY; l++) {
        add4_kernel<<<(n4 + 255)/256, 256>>>((const float4*)src, (const float4*)pos, (float4*)q, n4);
        gemm_bf3_kernel<<<g256, 256, SMEM_TOTAL_G>>>(q,
            wh + OFF_OFF + (size_t)l*65536, wl + OFF_OFF + (size_t)l*65536,
            off_b + l*DD, off, MTOT, DD, DD, 0);
        gemm_bf3_kernel<<<g128, 256, SMEM_TOTAL_G>>>(q,
            wh + OFF_AW + (size_t)l*32768, wl + OFF_AW + (size_t)l*32768,
            aw_b + l*128, aw, MTOT, 128, DD, 0);
        softmax16_kernel<<<(MTOT*NHH + 255)/256, 256>>>(aw, MTOT*NHH);
        gemm_bf3_kernel<<<g256, 256, SMEM_TOTAL_G>>>(src,
            wh + OFF_VAL + (size_t)l*65536, wl + OFF_VAL + (size_t)l*65536,
            val_b + l*DD, val, MTOT, DD, DD, 0);
        msdeform_kernel<<<MTOT, 256>>>(val, off, aw, ref, msd);
        gemm_bf3_kernel<<<g256, 256, SMEM_TOTAL_G>>>(msd,
            wh + OFF_OUT + (size_t)l*65536, wl + OFF_OUT + (size_t)l*65536,
            out_b + l*DD, att, MTOT, DD, DD, 0);
        addln_kernel<<<MTOT, 256>>>(src, att, ln1_g + l*DD, ln1_b + l*DD);
        gemm_bf3_kernel<<<g1024, 256, SMEM_TOTAL_G>>>(src,
            wh + OFF_L1 + (size_t)l*262144, wl + OFF_L1 + (size_t)l*262144,
            l1_b + l*DFF_, hbuf, MTOT, DFF_, DD, 1);
        gemm_bf3_kernel<<<g256, 256, SMEM_TOTAL_G>>>(hbuf,
            wh + OFF_L2 + (size_t)l*262144, wl + OFF_L2 + (size_t)l*262144,
            l2_b + l*DD, att, MTOT, DD, DFF_, 0);
        addln_kernel<<<MTOT, 256>>>(src, att, ln2_g + l*DD, ln2_b + l*DD);
    }

    finalize_kernel<<<(out_size + 255)/256, 256>>>(src, (float*)d_out, out_size);
}

// round 8
// speedup vs baseline: 1.8199x; 1.0020x over previous
#include <cuda_runtime.h>
#include <cuda_bf16.h>
#include <cuda_fp16.h>
#include <stdint.h>
#include <math.h>

// ---------------- problem constants ----------------
#define NB    2
#define DD    256
#define LQT   12240
#define NHH   8
#define NLAY  6
#define DFF_  1024
#define MTOT  (NB*LQT)   // 24480

__constant__ int c_H[4]     = {96,48,24,12};
__constant__ int c_W[4]     = {96,48,24,12};
__constant__ int c_start[4] = {0,9216,11520,12096};
__constant__ int c_len[4]   = {9216,2304,576,144};

// ---------------- scratch (device globals; no allocation) ----------------
__device__ float g_src[NB*LQT*DD];
__device__ float g_pos[NB*LQT*DD];
__device__ float g_off[NB*LQT*DD];
__device__ float g_aw [NB*LQT*128];
__device__ float g_val[NB*LQT*DD];    // holds __half when used as msdeform input
__device__ float g_msd[NB*LQT*DD];
__device__ float g_att[NB*LQT*DD];
__device__ float g_h  [NB*LQT*DFF_];
__device__ float g_ref[LQT*2];
__device__ float g_cbias[NLAY*384];

// pre-split weights (bf16 hi/lo); off+aw fused per layer: off(65536)+aw(32768)
#define OFF_OAW 0
#define OFF_VAL 589824
#define OFF_OUT 983040
#define OFF_L1  1376256
#define OFF_L2  2949120
#define W_TOTAL 4521984
__device__ __nv_bfloat16 g_wh[W_TOTAL];
__device__ __nv_bfloat16 g_wl[W_TOTAL];

__device__ __forceinline__ int lvl_of(int q) {
    return (q < 9216) ? 0 : (q < 11520) ? 1 : (q < 12096) ? 2 : 3;
}

__device__ __forceinline__ float blockSum(float v) {
    __shared__ float sh[8];
    int lane = threadIdx.x & 31, w = threadIdx.x >> 5;
    #pragma unroll
    for (int o = 16; o > 0; o >>= 1) v += __shfl_xor_sync(0xffffffffu, v, o);
    if (lane == 0) sh[w] = v;
    __syncthreads();
    if (w == 0) {
        float r = (lane < 8) ? sh[lane] : 0.f;
        #pragma unroll
        for (int o = 4; o > 0; o >>= 1) r += __shfl_xor_sync(0xffffffffu, r, o);
        if (lane == 0) sh[0] = r;
    }
    __syncthreads();
    float res = sh[0];
    __syncthreads();
    return res;
}

// ---------------- weight split (with layer strides) ----------------
__global__ void split_kernel(const float* __restrict__ in,
                             __nv_bfloat16* __restrict__ hi,
                             __nv_bfloat16* __restrict__ lo,
                             int n_per_layer, int nlayers,
                             long long in_ls, long long out_ls)
{
    long long i = (long long)blockIdx.x*blockDim.x + threadIdx.x;
    if (i >= (long long)n_per_layer*nlayers) return;
    int l = (int)(i / n_per_layer);
    int r = (int)(i - (long long)l*n_per_layer);
    float x = in[(long long)l*in_ls + r];
    __nv_bfloat16 h = __float2bfloat16(x);
    hi[(long long)l*out_ls + r] = h;
    lo[(long long)l*out_ls + r] = __float2bfloat16(x - __bfloat162float(h));
}

__global__ void cbias_kernel(const float* __restrict__ offb, const float* __restrict__ awb,
                             float* __restrict__ cb)
{
    int i = blockIdx.x*blockDim.x + threadIdx.x;
    if (i >= NLAY*384) return;
    int l = i / 384, j = i % 384;
    cb[i] = (j < 256) ? offb[l*256 + j] : awb[l*128 + (j - 256)];
}

// ---------------- pipelined bf16x3 tensor-core GEMM ----------------
// C[m,n] = sum_k (A[m,k](+A2[m,k])) * W[n,k] + bias[n]; BM=BN=128, BK=32.
// Output split at n_split between C0/C1; optional relu; optional fp16 output (C0 only).
#define SMEM_A_L   10240
#define SMEM_B0    20480
#define SMEM_STG   20480
#define SMEM_TOTAL_G 61440

__device__ __forceinline__ void mma_bf16(float c[4], const unsigned a[4],
                                         unsigned b0, unsigned b1)
{
    asm volatile("mma.sync.aligned.m16n8k16.row.col.f32.bf16.bf16.f32 "
        "{%0,%1,%2,%3}, {%4,%5,%6,%7}, {%8,%9}, {%0,%1,%2,%3};"
        : "+f"(c[0]), "+f"(c[1]), "+f"(c[2]), "+f"(c[3])
        : "r"(a[0]), "r"(a[1]), "r"(a[2]), "r"(a[3]), "r"(b0), "r"(b1));
}

__device__ __forceinline__ void ldsm4(unsigned r[4], unsigned a) {
    asm volatile("ldmatrix.sync.aligned.m8n8.x4.shared.b16 {%0,%1,%2,%3}, [%4];"
        : "=r"(r[0]), "=r"(r[1]), "=r"(r[2]), "=r"(r[3]) : "r"(a));
}

__device__ __forceinline__ void cp_async16(unsigned dst, const void* src) {
    asm volatile("cp.async.cg.shared.global [%0], [%1], 16;" :: "r"(dst), "l"(src));
}
__device__ __forceinline__ void cp_commit() { asm volatile("cp.async.commit_group;"); }
__device__ __forceinline__ void cp_wait0()  { asm volatile("cp.async.wait_group 0;"); }

__global__ void __launch_bounds__(256, 2)
gemm_bf3_kernel(const float* __restrict__ A, const float* __restrict__ A2,
                const __nv_bfloat16* __restrict__ Wh, const __nv_bfloat16* __restrict__ Wl,
                const float* __restrict__ bias,
                float* __restrict__ C0, float* __restrict__ C1,
                int n_split, int M, int Ntot, int K, int relu, int outhalf)
{
    extern __shared__ __align__(16) char smem[];
    __nv_bfloat16* sAh = (__nv_bfloat16*)smem;
    __nv_bfloat16* sAl = (__nv_bfloat16*)(smem + SMEM_A_L);
    unsigned sbase = (unsigned)__cvta_generic_to_shared(smem);

    int tid  = threadIdx.x;
    int lane = tid & 31, warp = tid >> 5;
    int wm = warp & 3, wn = warp >> 2;
    int m0 = blockIdx.y * 128, n0 = blockIdx.x * 128;
    int g = lane >> 2, qd = lane & 3;
    int lrow = tid >> 1, lcol = (tid & 1) * 16;

    unsigned aAh = sbase + (unsigned)(((wm*32 + (lane & 15))*40 + ((lane >> 4)*8))*2);
    unsigned aAl = aAh + SMEM_A_L;
    unsigned aB_rel = (unsigned)(((wn*64 + ((lane >> 4) & 1)*8 + (lane & 7))*40 + (((lane >> 3) & 1)*8))*2);
    unsigned bso = (unsigned)((lrow*40 + lcol)*2);

    float acc[2][8][4] = {};
    float v[16];
    const int NT = K / 32;
    bool mok = (m0 + lrow) < M;

    // ---- prologue: tile 0 ----
    {
        const float4* ap = (const float4*)(A + (size_t)(m0 + lrow)*K + lcol);
        #pragma unroll
        for (int j = 0; j < 4; j++) {
            float4 f = mok ? ap[j] : make_float4(0.f,0.f,0.f,0.f);
            v[4*j+0]=f.x; v[4*j+1]=f.y; v[4*j+2]=f.z; v[4*j+3]=f.w;
        }
        if (A2 && mok) {
            const float4* a2 = (const float4*)(A2 + (size_t)(m0 + lrow)*K + lcol);
            #pragma unroll
            for (int j = 0; j < 4; j++) {
                float4 f = a2[j];
                v[4*j+0]+=f.x; v[4*j+1]+=f.y; v[4*j+2]+=f.z; v[4*j+3]+=f.w;
            }
        }
        unsigned dst = sbase + SMEM_B0 + bso;
        size_t go = (size_t)(n0 + lrow)*K + lcol;
        cp_async16(dst,      Wh + go);
        cp_async16(dst + 16, Wh + go + 8);
        cp_async16(dst + SMEM_A_L,      Wl + go);
        cp_async16(dst + SMEM_A_L + 16, Wl + go + 8);
        cp_commit();
        #pragma unroll
        for (int i = 0; i < 8; i++) {
            float x0 = v[2*i], x1 = v[2*i+1];
            __nv_bfloat162 h = __floats2bfloat162_rn(x0, x1);
            __nv_bfloat162 l = __floats2bfloat162_rn(x0 - __bfloat162float(h.x),
                                                     x1 - __bfloat162float(h.y));
            *(__nv_bfloat162*)&sAh[lrow*40 + lcol + 2*i] = h;
            *(__nv_bfloat162*)&sAl[lrow*40 + lcol + 2*i] = l;
        }
        cp_wait0();
        __syncthreads();
    }

    for (int t = 0; t < NT; t++) {
        if (t + 1 < NT) {
            int k0 = (t + 1) * 32;
            const float4* ap = (const float4*)(A + (size_t)(m0 + lrow)*K + k0 + lcol);
            #pragma unroll
            for (int j = 0; j < 4; j++) {
                float4 f = mok ? ap[j] : make_float4(0.f,0.f,0.f,0.f);
                v[4*j+0]=f.x; v[4*j+1]=f.y; v[4*j+2]=f.z; v[4*j+3]=f.w;
            }
            if (A2 && mok) {
                const float4* a2 = (const float4*)(A2 + (size_t)(m0 + lrow)*K + k0 + lcol);
                #pragma unroll
                for (int j = 0; j < 4; j++) {
                    float4 f = a2[j];
                    v[4*j+0]+=f.x; v[4*j+1]+=f.y; v[4*j+2]+=f.z; v[4*j+3]+=f.w;
                }
            }
            unsigned dst = sbase + SMEM_B0 + (unsigned)(((t+1) & 1)*SMEM_STG) + bso;
            size_t go = (size_t)(n0 + lrow)*K + k0 + lcol;
            cp_async16(dst,      Wh + go);
            cp_async16(dst + 16, Wh + go + 8);
            cp_async16(dst + SMEM_A_L,      Wl + go);
            cp_async16(dst + SMEM_A_L + 16, Wl + go + 8);
            cp_commit();
        }
        unsigned bB = sbase + SMEM_B0 + (unsigned)((t & 1)*SMEM_STG) + aB_rel;
        #pragma unroll
        for (int kk = 0; kk < 2; kk++) {
            unsigned ah[2][4], al[2][4];
            #pragma unroll
            for (int im = 0; im < 2; im++) {
                ldsm4(ah[im], aAh + im*1280 + kk*32);
                ldsm4(al[im], aAl + im*1280 + kk*32);
            }
            #pragma unroll
            for (int j = 0; j < 4; j++) {
                unsigned bh[4], bl[4];
                ldsm4(bh, bB + j*1280 + kk*32);
                ldsm4(bl, bB + SMEM_A_L + j*1280 + kk*32);
                #pragma unroll
                for (int im = 0; im < 2; im++) {
                    mma_bf16(acc[im][2*j],   ah[im], bh[0], bh[1]);
                    mma_bf16(acc[im][2*j],   ah[im], bl[0], bl[1]);
                    mma_bf16(acc[im][2*j],   al[im], bh[0], bh[1]);
                    mma_bf16(acc[im][2*j+1], ah[im], bh[2], bh[3]);
                    mma_bf16(acc[im][2*j+1], ah[im], bl[2], bl[3]);
                    mma_bf16(acc[im][2*j+1], al[im], bh[2], bh[3]);
                }
            }
        }
        __syncthreads();
        if (t + 1 < NT) {
            #pragma unroll
            for (int i = 0; i < 8; i++) {
                float x0 = v[2*i], x1 = v[2*i+1];
                __nv_bfloat162 h = __floats2bfloat162_rn(x0, x1);
                __nv_bfloat162 l = __floats2bfloat162_rn(x0 - __bfloat162float(h.x),
                                                         x1 - __bfloat162float(h.y));
                *(__nv_bfloat162*)&sAh[lrow*40 + lcol + 2*i] = h;
                *(__nv_bfloat162*)&sAl[lrow*40 + lcol + 2*i] = l;
            }
            cp_wait0();
        }
        __syncthreads();
    }

    // ---- epilogue with output split ----
    float* Cc; int ldc, base;
    if (n0 < n_split) { Cc = C0; ldc = n_split;        base = 0; }
    else              { Cc = C1; ldc = Ntot - n_split; base = n_split; }
    #pragma unroll
    for (int im = 0; im < 2; im++) {
        int r0 = m0 + wm*32 + im*16 + g;
        #pragma unroll
        for (int in_ = 0; in_ < 8; in_++) {
            int gcol = n0 + wn*64 + in_*8 + qd*2;
            int cn = gcol - base;
            float bv0 = bias[gcol], bv1 = bias[gcol+1];
            float v0 = acc[im][in_][0] + bv0;
            float v1 = acc[im][in_][1] + bv1;
            float v2 = acc[im][in_][2] + bv0;
            float v3 = acc[im][in_][3] + bv1;
            if (relu) {
                v0 = fmaxf(v0, 0.f); v1 = fmaxf(v1, 0.f);
                v2 = fmaxf(v2, 0.f); v3 = fmaxf(v3, 0.f);
            }
            if (outhalf) {
                __half* Ch = (__half*)Cc;
                if (r0 < M)     *(__half2*)(Ch + (size_t)r0*ldc + cn)     = __floats2half2_rn(v0, v1);
                if (r0 + 8 < M) *(__half2*)(Ch + (size_t)(r0+8)*ldc + cn) = __floats2half2_rn(v2, v3);
            } else {
                if (r0 < M)     *(float2*)(Cc + (size_t)r0*ldc + cn)     = make_float2(v0, v1);
                if (r0 + 8 < M) *(float2*)(Cc + (size_t)(r0+8)*ldc + cn) = make_float2(v2, v3);
            }
        }
    }
}

// ---------------- GEMM (tokenizer): C[m,n] = sum_k A[k,m]*W[n,k] + bias[n]
__global__ void __launch_bounds__(256)
gemm_tn_kernel(const float* __restrict__ A, const float* __restrict__ W,
               const float* __restrict__ bias, float* __restrict__ C,
               int M, int N, int K)
{
    __shared__ __align__(16) float As[16][68];
    __shared__ __align__(16) float Ws[16][68];
    int tid = threadIdx.x;
    int tx = tid & 15, ty = tid >> 4;
    int m0 = blockIdx.y * 64, n0 = blockIdx.x * 64;
    int ak = tid >> 4, amq = (tid & 15) * 4;
    int wn = tid >> 2, wk  = (tid & 3) * 4;
    bool aok = (m0 + amq) < M;
    float acc[4][4] = {};
    for (int k0 = 0; k0 < K; k0 += 16) {
        float4 a4 = aok ? *(const float4*)(A + (size_t)(k0+ak)*M + m0 + amq)
                        : make_float4(0.f,0.f,0.f,0.f);
        *(float4*)&As[ak][amq] = a4;
        float4 w4 = *(const float4*)(W + (size_t)(n0+wn)*K + k0 + wk);
        Ws[wk+0][wn]=w4.x; Ws[wk+1][wn]=w4.y; Ws[wk+2][wn]=w4.z; Ws[wk+3][wn]=w4.w;
        __syncthreads();
        #pragma unroll
        for (int k = 0; k < 16; k++) {
            float4 a = *(const float4*)&As[k][ty*4];
            float4 w = *(const float4*)&Ws[k][tx*4];
            float ar[4] = {a.x,a.y,a.z,a.w}, wr[4] = {w.x,w.y,w.z,w.w};
            #pragma unroll
            for (int i = 0; i < 4; i++)
                #pragma unroll
                for (int j = 0; j < 4; j++)
                    acc[i][j] = fmaf(ar[i], wr[j], acc[i][j]);
        }
        __syncthreads();
    }
    #pragma unroll
    for (int i = 0; i < 4; i++) {
        int m = m0 + ty*4 + i;
        if (m >= M) break;
        #pragma unroll
        for (int j = 0; j < 4; j++) {
            int n = n0 + tx*4 + j;
            C[(size_t)m*N + n] = acc[i][j] + bias[n];
        }
    }
}

// ---------------- GroupNorm ----------------
__global__ void __launch_bounds__(256)
gn_kernel(float* __restrict__ src, const float* __restrict__ g, const float* __restrict__ b)
{
    int grp = blockIdx.x & 31;
    int bb  = (blockIdx.x >> 5) & 1;
    int lvl = blockIdx.x >> 6;
    int L = c_len[lvl], st = c_start[lvl];
    float* base = src + ((size_t)bb*LQT + st) * DD;
    int n = L * 8;
    float s = 0.f;
    for (int i = threadIdx.x; i < n; i += 256)
        s += base[(size_t)(i>>3)*DD + grp*8 + (i&7)];
    float mean = blockSum(s) / (float)n;
    float s2 = 0.f;
    for (int i = threadIdx.x; i < n; i += 256) {
        float d = base[(size_t)(i>>3)*DD + grp*8 + (i&7)] - mean;
        s2 += d*d;
    }
    float rstd = rsqrtf(blockSum(s2) / (float)n + 1e-5f);
    for (int i = threadIdx.x; i < n; i += 256) {
        int c = grp*8 + (i&7);
        size_t id = (size_t)(i>>3)*DD + c;
        base[id] = (base[id] - mean) * rstd * g[lvl*DD + c] + b[lvl*DD + c];
    }
}

// ---------------- sine positional embedding + level embed ----------------
__global__ void pos_kernel(const float* __restrict__ lemb, float* __restrict__ pos)
{
    int idx = blockIdx.x*blockDim.x + threadIdx.x;
    if (idx >= LQT*DD) return;
    int qq = idx >> 8, d = idx & 255;
    int lvl = lvl_of(qq);
    int st = c_start[lvl], H = c_H[lvl], W = c_W[lvl];
    int p = qq - st; int y = p / W, x = p % W;
    const float TWO_PI = 6.28318530717958647692f;
    const float LN1E4_64 = 0.14391156831212787f;
    float v;
    if (d < 128) {
        float e = (float)(y+1) / ((float)H + 1e-6f) * TWO_PI;
        int i = d >> 1;
        float u = e * expf(-LN1E4_64 * (float)i);
        v = (d & 1) ? cosf(u) : sinf(u);
    } else {
        int dd = d - 128;
        float e = (float)(x+1) / ((float)W + 1e-6f) * TWO_PI;
        int i = dd >> 1;
        float u = e * expf(-LN1E4_64 * (float)i);
        v = (dd & 1) ? cosf(u) : sinf(u);
    }
    v += lemb[lvl*DD + d];
    pos[(size_t)qq*DD + d] = v;
    pos[(size_t)(LQT + qq)*DD + d] = v;
}

__global__ void ref_kernel(float* __restrict__ ref)
{
    int qq = blockIdx.x*blockDim.x + threadIdx.x;
    if (qq >= LQT) return;
    int lvl = lvl_of(qq);
    int st = c_start[lvl], H = c_H[lvl], W = c_W[lvl];
    int p = qq - st; int y = p / W, x = p % W;
    ref[qq*2+0] = ((float)x + 0.5f) / (float)W;
    ref[qq*2+1] = ((float)y + 0.5f) / (float)H;
}

// ---------------- softmax over 16 ----------------
__global__ void softmax16_kernel(float* __restrict__ aw, int n)
{
    int t = blockIdx.x*blockDim.x + threadIdx.x;
    if (t >= n) return;
    float* p = aw + (size_t)t*16;
    float buf[16];
    float m = -1e30f;
    #pragma unroll
    for (int i = 0; i < 16; i++) { buf[i] = p[i]; m = fmaxf(m, buf[i]); }
    float s = 0.f;
    #pragma unroll
    for (int i = 0; i < 16; i++) { buf[i] = expf(buf[i] - m); s += buf[i]; }
    float inv = 1.f / s;
    #pragma unroll
    for (int i = 0; i < 16; i++) p[i] = buf[i] * inv;
}

// ---------------- ms-deform attention core (fp16 values) ----------------
__global__ void __launch_bounds__(256)
msdeform_kernel(const __half* __restrict__ val, const float* __restrict__ off,
                const float* __restrict__ aw, const float* __restrict__ ref,
                float* __restrict__ out)
{
    int warp = blockIdx.x * (blockDim.x >> 5) + (threadIdx.x >> 5);
    int lane = threadIdx.x & 31;
    if (warp >= NB*LQT*NHH) return;
    int h  = warp & 7;
    int bq = warp >> 3;
    int q  = bq % LQT;
    int b  = bq / LQT;
    float gx = ref[q*2], gy = ref[q*2+1];
    const float* offp = off + (size_t)bq*DD  + h*32;
    const float* awp  = aw  + (size_t)bq*128 + h*16;
    float acc = 0.f;
    #pragma unroll
    for (int l = 0; l < 4; l++) {
        int Wl = c_W[l], Hl = c_H[l], st = c_start[l];
        float fW = (float)Wl, fH = (float)Hl;
        const __half* vb = val + ((size_t)b*LQT + st)*DD + h*32 + lane;
        #pragma unroll
        for (int p = 0; p < 4; p++) {
            float ox = offp[(l*4+p)*2+0], oy = offp[(l*4+p)*2+1];
            float a  = awp[l*4+p];
            float x = (gx + ox / fW) * fW - 0.5f;
            float y = (gy + oy / fH) * fH - 0.5f;
            float x0f = floorf(x), y0f = floorf(y);
            float tx = x - x0f, ty = y - y0f;
            int x0 = (int)x0f, y0 = (int)y0f;
            float w00 = (1.f-tx)*(1.f-ty)*a;
            float w10 = tx*(1.f-ty)*a;
            float w01 = (1.f-tx)*ty*a;
            float w11 = tx*ty*a;
            bool xv0 = (x0   >= 0) && (x0   < Wl);
            bool xv1 = (x0+1 >= 0) && (x0+1 < Wl);
            bool yv0 = (y0   >= 0) && (y0   < Hl);
            bool yv1 = (y0+1 >= 0) && (y0+1 < Hl);
            if (xv0 && yv0) acc += w00 * __half2float(vb[(size_t)(y0*Wl + x0)     * DD]);
            if (xv1 && yv0) acc += w10 * __half2float(vb[(size_t)(y0*Wl + x0 + 1) * DD]);
            if (xv0 && yv1) acc += w01 * __half2float(vb[(size_t)((y0+1)*Wl + x0)     * DD]);
            if (xv1 && yv1) acc += w11 * __half2float(vb[(size_t)((y0+1)*Wl + x0 + 1) * DD]);
        }
    }
    out[(size_t)bq*DD + h*32 + lane] = acc;
}

// ---------------- residual + LayerNorm ----------------
__global__ void __launch_bounds__(256)
addln_kernel(float* __restrict__ src, const float* __restrict__ res,
             const float* __restrict__ g, const float* __restrict__ b)
{
    int row = blockIdx.x, t = threadIdx.x;
    size_t idx = (size_t)row*DD + t;
    float x = src[idx] + res[idx];
    float mean = blockSum(x) * (1.f/DD);
    float d = x - mean;
    float var = blockSum(d*d) * (1.f/DD);
    src[idx] = d * rsqrtf(var + 1e-5f) * g[t] + b[t];
}

// ---------------- finalize ----------------
__global__ void finalize_kernel(const float* __restrict__ src, float* __restrict__ out, int out_size)
{
    int i = blockIdx.x*blockDim.x + threadIdx.x;
    if (i >= out_size) return;
    const int n = NB*LQT*DD;
    if (i < n) { out[i] = src[i]; return; }
    int j = i - n;
    float v;
    if (j < 4)       v = (float)c_start[j];
    else if (j < 12) v = (float)c_H[(j-4) >> 1];
    else             v = 1.0f;
    out[i] = v;
}

// ---------------- host orchestration ----------------
extern "C" void kernel_launch(void* const* d_in, const int* in_sizes, int n_in,
                              void* d_out, int out_size)
{
    (void)n_in;
    const float *X[4], *FW[4], *FB[4];
    if (in_sizes[1] == 65536) {
        for (int i = 0; i < 4; i++) {
            X[i]  = (const float*)d_in[3*i+0];
            FW[i] = (const float*)d_in[3*i+1];
            FB[i] = (const float*)d_in[3*i+2];
        }
    } else {
        for (int i = 0; i < 4; i++) {
            X[i]  = (const float*)d_in[i];
            FW[i] = (const float*)d_in[4+2*i];
            FB[i] = (const float*)d_in[5+2*i];
        }
    }
    const float* gn_g  = (const float*)d_in[12];
    const float* gn_b  = (const float*)d_in[13];
    const float* lemb  = (const float*)d_in[14];
    const float* off_w = (const float*)d_in[15];
    const float* off_b = (const float*)d_in[16];
    const float* aw_w  = (const float*)d_in[17];
    const float* aw_b  = (const float*)d_in[18];
    const float* val_w = (const float*)d_in[19];
    const float* val_b = (const float*)d_in[20];
    const float* out_w = (const float*)d_in[21];
    const float* out_b = (const float*)d_in[22];
    const float* ln1_g = (const float*)d_in[23];
    const float* ln1_b = (const float*)d_in[24];
    const float* l1_w  = (const float*)d_in[25];
    const float* l1_b  = (const float*)d_in[26];
    const float* l2_w  = (const float*)d_in[27];
    const float* l2_b  = (const float*)d_in[28];
    const float* ln2_g = (const float*)d_in[29];
    const float* ln2_b = (const float*)d_in[30];

    float *src, *pos, *off, *aw, *val, *msd, *att, *hbuf, *ref, *cbias;
    __nv_bfloat16 *wh, *wl;
    cudaGetSymbolAddress((void**)&src,   g_src);
    cudaGetSymbolAddress((void**)&pos,   g_pos);
    cudaGetSymbolAddress((void**)&off,   g_off);
    cudaGetSymbolAddress((void**)&aw,    g_aw);
    cudaGetSymbolAddress((void**)&val,   g_val);
    cudaGetSymbolAddress((void**)&msd,   g_msd);
    cudaGetSymbolAddress((void**)&att,   g_att);
    cudaGetSymbolAddress((void**)&hbuf,  g_h);
    cudaGetSymbolAddress((void**)&ref,   g_ref);
    cudaGetSymbolAddress((void**)&cbias, g_cbias);
    cudaGetSymbolAddress((void**)&wh,    g_wh);
    cudaGetSymbolAddress((void**)&wl,    g_wl);

    cudaFuncSetAttribute(gemm_bf3_kernel,
        cudaFuncAttributeMaxDynamicSharedMemorySize, SMEM_TOTAL_G);

    // ---- pre-split weights; off+aw fused per-layer [384,256] ----
    split_kernel<<<(6*65536 + 255)/256, 256>>>(off_w, wh + OFF_OAW, wl + OFF_OAW,
                                               65536, NLAY, 65536, 98304);
    split_kernel<<<(6*32768 + 255)/256, 256>>>(aw_w, wh + OFF_OAW + 65536, wl + OFF_OAW + 65536,
                                               32768, NLAY, 32768, 98304);
    split_kernel<<<(6*65536 + 255)/256, 256>>>(val_w, wh + OFF_VAL, wl + OFF_VAL,
                                               65536, NLAY, 65536, 65536);
    split_kernel<<<(6*65536 + 255)/256, 256>>>(out_w, wh + OFF_OUT, wl + OFF_OUT,
                                               65536, NLAY, 65536, 65536);
    split_kernel<<<(6*262144 + 255)/256, 256>>>(l1_w, wh + OFF_L1, wl + OFF_L1,
                                                262144, NLAY, 262144, 262144);
    split_kernel<<<(6*262144 + 255)/256, 256>>>(l2_w, wh + OFF_L2, wl + OFF_L2,
                                                262144, NLAY, 262144, 262144);
    cbias_kernel<<<(NLAY*384 + 255)/256, 256>>>(off_b, aw_b, cbias);

    const int HS[4] = {96,48,24,12};
    const int CIN[4] = {256,512,768,1024};
    const int START[4] = {0,9216,11520,12096};

    for (int l = 0; l < 4; l++) {
        int HW = HS[l]*HS[l];
        dim3 grid(DD/64, (HW + 63)/64);
        for (int b = 0; b < 2; b++) {
            gemm_tn_kernel<<<grid, 256>>>(
                X[l] + (size_t)b*CIN[l]*HW, FW[l], FB[l],
                src + ((size_t)b*LQT + START[l])*DD, HW, DD, CIN[l]);
        }
    }
    gn_kernel<<<4*2*32, 256>>>(src, gn_g, gn_b);
    pos_kernel<<<(LQT*DD + 255)/256, 256>>>(lemb, pos);
    ref_kernel<<<(LQT + 255)/256, 256>>>(ref);

    const int GY = (MTOT + 127)/128;  // 192
    dim3 g_oaw(3, GY), g_256(2, GY), g_l1(8, GY);

    for (int l = 0; l < NLAY; l++) {
        // fused offset+attention-weight GEMM (q = src + pos folded into A-load)
        gemm_bf3_kernel<<<g_oaw, 256, SMEM_TOTAL_G>>>(src, pos,
            wh + OFF_OAW + (size_t)l*98304, wl + OFF_OAW + (size_t)l*98304,
            cbias + l*384, off, aw, 256, MTOT, 384, 256, 0, 0);
        softmax16_kernel<<<(MTOT*NHH + 255)/256, 256>>>(aw, MTOT*NHH);
        // value projection -> fp16 output
        gemm_bf3_kernel<<<g_256, 256, SMEM_TOTAL_G>>>(src, (const float*)0,
            wh + OFF_VAL + (size_t)l*65536, wl + OFF_VAL + (size_t)l*65536,
            val_b + l*DD, val, (float*)0, 256, MTOT, 256, 256, 0, 1);
        msdeform_kernel<<<MTOT, 256>>>((const __half*)val, off, aw, ref, msd);
        gemm_bf3_kernel<<<g_256, 256, SMEM_TOTAL_G>>>(msd, (const float*)0,
            wh + OFF_OUT + (size_t)l*65536, wl + OFF_OUT + (size_t)l*65536,
            out_b + l*DD, att, (float*)0, 256, MTOT, 256, 256, 0, 0);
        addln_kernel<<<MTOT, 256>>>(src, att, ln1_g + l*DD, ln1_b + l*DD);
        gemm_bf3_kernel<<<g_l1, 256, SMEM_TOTAL_G>>>(src, (const float*)0,
            wh + OFF_L1 + (size_t)l*262144, wl + OFF_L1 + (size_t)l*262144,
            l1_b + l*DFF_, hbuf, (float*)0, 1024, MTOT, 1024, 256, 1, 0);
        gemm_bf3_kernel<<<g_256, 256, SMEM_TOTAL_G>>>(hbuf, (const float*)0,
            wh + OFF_L2 + (size_t)l*262144, wl + OFF_L2 + (size_t)l*262144,
            l2_b + l*DD, att, (float*)0, 256, MTOT, 256, 1024, 0, 0);
        addln_kernel<<<MTOT, 256>>>(src, att, ln2_g + l*DD, ln2_b + l*DD);
    }

    finalize_kernel<<<(out_size + 255)/256, 256>>>(src, (float*)d_out, out_size);
}

// round 10
// speedup vs baseline: 1.8359x; 1.0088x over previous
#include <cuda_runtime.h>
#include <cuda_bf16.h>
#include <cuda_fp16.h>
#include <stdint.h>
#include <math.h>

// ---------------- problem constants ----------------
#define NB    2
#define DD    256
#define LQT   12240
#define NHH   8
#define NLAY  6
#define DFF_  1024
#define MTOT  (NB*LQT)   // 24480

__constant__ int c_H[4]     = {96,48,24,12};
__constant__ int c_W[4]     = {96,48,24,12};
__constant__ int c_start[4] = {0,9216,11520,12096};
__constant__ int c_len[4]   = {9216,2304,576,144};
__constant__ int c_cin[4]   = {256,512,768,1024};

// ---------------- scratch (device globals; no allocation) ----------------
__device__ float g_src[NB*LQT*DD];
__device__ float g_pos[NB*LQT*DD];
__device__ float g_off[NB*LQT*DD];
__device__ float g_aw [NB*LQT*128];
__device__ float g_val[NB*LQT*DD];    // fp16 payload
__device__ float g_att[NB*LQT*DD];
__device__ float g_ref[LQT*2];
__device__ float g_cbias[NLAY*384];
// bf16 hi/lo activation buffers (GEMM A-side inputs)
__device__ __nv_bfloat16 g_qh [MTOT*DD],  g_ql [MTOT*DD];
__device__ __nv_bfloat16 g_sh [MTOT*DD],  g_sl [MTOT*DD];
__device__ __nv_bfloat16 g_th [MTOT*DD],  g_tl [MTOT*DD];
__device__ __nv_bfloat16 g_msh[MTOT*DD],  g_msl[MTOT*DD];
__device__ __nv_bfloat16 g_hbh[MTOT*DFF_], g_hbl[MTOT*DFF_];

// pre-split weights (bf16 hi/lo); oaw fused per layer: off(65536)+aw(32768)
#define OFF_OAW 0
#define OFF_VAL 589824
#define OFF_OUT 983040
#define OFF_L1  1376256
#define OFF_L2  2949120
#define W_TOTAL 4521984
__device__ __nv_bfloat16 g_wh[W_TOTAL];
__device__ __nv_bfloat16 g_wl[W_TOTAL];

__device__ __forceinline__ int lvl_of(int q) {
    return (q < 9216) ? 0 : (q < 11520) ? 1 : (q < 12096) ? 2 : 3;
}

__device__ __forceinline__ float blockSum(float v) {
    __shared__ float sh[8];
    int lane = threadIdx.x & 31, w = threadIdx.x >> 5;
    #pragma unroll
    for (int o = 16; o > 0; o >>= 1) v += __shfl_xor_sync(0xffffffffu, v, o);
    if (lane == 0) sh[w] = v;
    __syncthreads();
    if (w == 0) {
        float r = (lane < 8) ? sh[lane] : 0.f;
        #pragma unroll
        for (int o = 4; o > 0; o >>= 1) r += __shfl_xor_sync(0xffffffffu, r, o);
        if (lane == 0) sh[0] = r;
    }
    __syncthreads();
    float res = sh[0];
    __syncthreads();
    return res;
}

__device__ __forceinline__ void split2(float x, __nv_bfloat16& h, __nv_bfloat16& l) {
    h = __float2bfloat16(x);
    l = __float2bfloat16(x - __bfloat162float(h));
}

// ---------------- setup: split ALL weights + concat bias (one launch) ----------------
__global__ void split_all_kernel(
    const float* __restrict__ off_w, const float* __restrict__ aw_w,
    const float* __restrict__ val_w, const float* __restrict__ out_w,
    const float* __restrict__ l1_w,  const float* __restrict__ l2_w,
    const float* __restrict__ off_b, const float* __restrict__ aw_b,
    __nv_bfloat16* __restrict__ hi, __nv_bfloat16* __restrict__ lo,
    float* __restrict__ cbias)
{
    int i = blockIdx.x*blockDim.x + threadIdx.x;
    if (i >= W_TOTAL + NLAY*384) return;
    if (i >= W_TOTAL) {
        int j = i - W_TOTAL;
        int l = j / 384, c = j % 384;
        cbias[j] = (c < 256) ? off_b[l*256 + c] : aw_b[l*128 + (c - 256)];
        return;
    }
    float x; long long o;
    if (i < 393216) {                 // off -> oaw region
        int l = i >> 16, r = i & 65535;
        x = off_w[i]; o = (long long)l*98304 + r;
    } else if (i < 589824) {          // aw -> oaw region
        int j = i - 393216;
        int l = j >> 15, r = j & 32767;
        x = aw_w[j]; o = (long long)l*98304 + 65536 + r;
    } else if (i < 983040) {
        x = val_w[i - 589824]; o = i;
    } else if (i < 1376256) {
        x = out_w[i - 983040]; o = i;
    } else if (i < 2949120) {
        x = l1_w[i - 1376256]; o = i;
    } else {
        x = l2_w[i - 2949120]; o = i;
    }
    __nv_bfloat16 h, l;
    split2(x, h, l);
    hi[o] = h; lo[o] = l;
}

// ---------------- tokenizer (ALL levels/batches in one launch) ----------------
__global__ void __launch_bounds__(256)
tokenizer_kernel(const float* __restrict__ X0, const float* __restrict__ X1,
                 const float* __restrict__ X2, const float* __restrict__ X3,
                 const float* __restrict__ W0, const float* __restrict__ W1,
                 const float* __restrict__ W2, const float* __restrict__ W3,
                 const float* __restrict__ B0, const float* __restrict__ B1,
                 const float* __restrict__ B2, const float* __restrict__ B3,
                 float* __restrict__ src)
{
    int bid = blockIdx.x;
    int lvl, base;
    if      (bid < 1152) { lvl = 0; base = 0; }
    else if (bid < 1440) { lvl = 1; base = 1152; }
    else if (bid < 1512) { lvl = 2; base = 1440; }
    else                 { lvl = 3; base = 1512; }
    int HW = c_len[lvl], K = c_cin[lvl];
    int rem = bid - base;
    int span = ((HW + 63)/64) * 4;
    int b = rem / span; rem -= b*span;
    int m0 = (rem >> 2) * 64, n0 = (rem & 3) * 64;
    const float* A = (lvl==0?X0:lvl==1?X1:lvl==2?X2:X3) + (size_t)b*K*HW;
    const float* W = (lvl==0?W0:lvl==1?W1:lvl==2?W2:W3);
    const float* bias = (lvl==0?B0:lvl==1?B1:lvl==2?B2:B3);
    float* C = src + ((size_t)b*LQT + c_start[lvl]) * DD;
    int M = HW, N = DD;

    __shared__ __align__(16) float As[16][68];
    __shared__ __align__(16) float Ws[16][68];
    int tid = threadIdx.x;
    int tx = tid & 15, ty = tid >> 4;
    int ak = tid >> 4, amq = (tid & 15) * 4;
    int wn = tid >> 2, wk  = (tid & 3) * 4;
    bool aok = (m0 + amq) < M;
    float acc[4][4] = {};
    for (int k0 = 0; k0 < K; k0 += 16) {
        float4 a4 = aok ? *(const float4*)(A + (size_t)(k0+ak)*M + m0 + amq)
                        : make_float4(0.f,0.f,0.f,0.f);
        *(float4*)&As[ak][amq] = a4;
        float4 w4 = *(const float4*)(W + (size_t)(n0+wn)*K + k0 + wk);
        Ws[wk+0][wn]=w4.x; Ws[wk+1][wn]=w4.y; Ws[wk+2][wn]=w4.z; Ws[wk+3][wn]=w4.w;
        __syncthreads();
        #pragma unroll
        for (int k = 0; k < 16; k++) {
            float4 a = *(const float4*)&As[k][ty*4];
            float4 w = *(const float4*)&Ws[k][tx*4];
            float ar[4] = {a.x,a.y,a.z,a.w}, wr[4] = {w.x,w.y,w.z,w.w};
            #pragma unroll
            for (int i = 0; i < 4; i++)
                #pragma unroll
                for (int j = 0; j < 4; j++)
                    acc[i][j] = fmaf(ar[i], wr[j], acc[i][j]);
        }
        __syncthreads();
    }
    #pragma unroll
    for (int i = 0; i < 4; i++) {
        int m = m0 + ty*4 + i;
        if (m >= M) break;
        #pragma unroll
        for (int j = 0; j < 4; j++) {
            int n = n0 + tx*4 + j;
            C[(size_t)m*N + n] = acc[i][j] + bias[n];
        }
    }
}

// ---------------- GroupNorm ----------------
__global__ void __launch_bounds__(256)
gn_kernel(float* __restrict__ src, const float* __restrict__ g, const float* __restrict__ b)
{
    int grp = blockIdx.x & 31;
    int bb  = (blockIdx.x >> 5) & 1;
    int lvl = blockIdx.x >> 6;
    int L = c_len[lvl], st = c_start[lvl];
    float* base = src + ((size_t)bb*LQT + st) * DD;
    int n = L * 8;
    float s = 0.f;
    for (int i = threadIdx.x; i < n; i += 256)
        s += base[(size_t)(i>>3)*DD + grp*8 + (i&7)];
    float mean = blockSum(s) / (float)n;
    float s2 = 0.f;
    for (int i = threadIdx.x; i < n; i += 256) {
        float d = base[(size_t)(i>>3)*DD + grp*8 + (i&7)] - mean;
        s2 += d*d;
    }
    float rstd = rsqrtf(blockSum(s2) / (float)n + 1e-5f);
    for (int i = threadIdx.x; i < n; i += 256) {
        int c = grp*8 + (i&7);
        size_t id = (size_t)(i>>3)*DD + c;
        base[id] = (base[id] - mean) * rstd * g[lvl*DD + c] + b[lvl*DD + c];
    }
}

// ---------------- pos + level embed + ref points (one launch) ----------------
__global__ void posref_kernel(const float* __restrict__ lemb, float* __restrict__ pos,
                              float* __restrict__ ref)
{
    int idx = blockIdx.x*blockDim.x + threadIdx.x;
    if (idx >= LQT*DD) return;
    int qq = idx >> 8, d = idx & 255;
    int lvl = lvl_of(qq);
    int st = c_start[lvl], H = c_H[lvl], W = c_W[lvl];
    int p = qq - st; int y = p / W, x = p % W;
    const float TWO_PI = 6.28318530717958647692f;
    const float LN1E4_64 = 0.14391156831212787f;
    float v;
    if (d < 128) {
        float e = (float)(y+1) / ((float)H + 1e-6f) * TWO_PI;
        int i = d >> 1;
        float u = e * expf(-LN1E4_64 * (float)i);
        v = (d & 1) ? cosf(u) : sinf(u);
    } else {
        int dd = d - 128;
        float e = (float)(x+1) / ((float)W + 1e-6f) * TWO_PI;
        int i = dd >> 1;
        float u = e * expf(-LN1E4_64 * (float)i);
        v = (dd & 1) ? cosf(u) : sinf(u);
    }
    v += lemb[lvl*DD + d];
    pos[(size_t)qq*DD + d] = v;
    pos[(size_t)(LQT + qq)*DD + d] = v;
    if (d == 0) {
        ref[qq*2+0] = ((float)x + 0.5f) / (float)W;
        ref[qq*2+1] = ((float)y + 0.5f) / (float)H;
    }
}

// ---------------- prep: initial splits for layer 0 ----------------
__global__ void prep_kernel(const float* __restrict__ src, const float* __restrict__ pos,
                            __nv_bfloat16* __restrict__ sh, __nv_bfloat16* __restrict__ sl,
                            __nv_bfloat16* __restrict__ qh, __nv_bfloat16* __restrict__ ql)
{
    int i = blockIdx.x*blockDim.x + threadIdx.x;
    if (i >= MTOT*DD) return;
    float s = src[i];
    __nv_bfloat16 h, l;
    split2(s, h, l);  sh[i] = h; sl[i] = l;
    split2(s + pos[i], h, l);  qh[i] = h; ql[i] = l;
}

// ---------------- pure cp.async bf16x3 tensor-core GEMM ----------------
// C = A(bf16 hi/lo) x W(bf16 hi/lo)^T + bias. BM=BN=128, BK=32, 2-stage cp.async.
// mode 0: fp32 out split at n_split (C0/C1); 1: fp16 out to C0; 2: bf16 hi/lo out to Oh/Ol.
#define STG_SZ 40960
#define SMEM_BB (2*STG_SZ)

__device__ __forceinline__ void mma_bf16(float c[4], const unsigned a[4],
                                         unsigned b0, unsigned b1)
{
    asm volatile("mma.sync.aligned.m16n8k16.row.col.f32.bf16.bf16.f32 "
        "{%0,%1,%2,%3}, {%4,%5,%6,%7}, {%8,%9}, {%0,%1,%2,%3};"
        : "+f"(c[0]), "+f"(c[1]), "+f"(c[2]), "+f"(c[3])
        : "r"(a[0]), "r"(a[1]), "r"(a[2]), "r"(a[3]), "r"(b0), "r"(b1));
}
__device__ __forceinline__ void ldsm4(unsigned r[4], unsigned a) {
    asm volatile("ldmatrix.sync.aligned.m8n8.x4.shared.b16 {%0,%1,%2,%3}, [%4];"
        : "=r"(r[0]), "=r"(r[1]), "=r"(r[2]), "=r"(r[3]) : "r"(a));
}
__device__ __forceinline__ void cp16(unsigned dst, const void* src) {
    asm volatile("cp.async.cg.shared.global [%0], [%1], 16;" :: "r"(dst), "l"(src));
}
__device__ __forceinline__ void cp16z(unsigned dst, const void* src, int sz) {
    asm volatile("cp.async.cg.shared.global [%0], [%1], 16, %2;" :: "r"(dst), "l"(src), "r"(sz));
}
__device__ __forceinline__ void cp_commit() { asm volatile("cp.async.commit_group;"); }
__device__ __forceinline__ void cp_wait1()  { asm volatile("cp.async.wait_group 1;"); }
__device__ __forceinline__ void cp_wait0()  { asm volatile("cp.async.wait_group 0;"); }

__device__ __forceinline__ void fill_bb(
    const __nv_bfloat16* __restrict__ Ah, const __nv_bfloat16* __restrict__ Al,
    const __nv_bfloat16* __restrict__ Wh, const __nv_bfloat16* __restrict__ Wl,
    unsigned sbase, int stage, int m0, int n0, int t, int M, int K, int tid)
{
    int row = tid >> 1, lcol = (tid & 1) * 16;
    unsigned so = sbase + (unsigned)(stage*STG_SZ) + (unsigned)(row*80 + lcol*2);
    size_t ga = (size_t)(m0 + row)*K + t*32 + lcol;
    size_t gb = (size_t)(n0 + row)*K + t*32 + lcol;
    int asz = ((m0 + row) < M) ? 16 : 0;
    cp16z(so,              Ah + ga,     asz);
    cp16z(so + 16,         Ah + ga + 8, asz);
    cp16z(so + 10240,      Al + ga,     asz);
    cp16z(so + 10240 + 16, Al + ga + 8, asz);
    cp16 (so + 20480,      Wh + gb);
    cp16 (so + 20480 + 16, Wh + gb + 8);
    cp16 (so + 30720,      Wl + gb);
    cp16 (so + 30720 + 16, Wl + gb + 8);
    cp_commit();
}

__global__ void __launch_bounds__(256, 2)
gemm_bb_kernel(const __nv_bfloat16* __restrict__ Ah, const __nv_bfloat16* __restrict__ Al,
               const __nv_bfloat16* __restrict__ Wh, const __nv_bfloat16* __restrict__ Wl,
               const float* __restrict__ bias,
               float* __restrict__ C0, float* __restrict__ C1, int n_split,
               __nv_bfloat16* __restrict__ Oh, __nv_bfloat16* __restrict__ Ol,
               int M, int Ntot, int K, int relu, int mode)
{
    extern __shared__ __align__(16) char smem[];
    unsigned sbase = (unsigned)__cvta_generic_to_shared(smem);
    int tid  = threadIdx.x;
    int lane = tid & 31, warp = tid >> 5;
    int wm = warp & 3, wn = warp >> 2;
    int m0 = blockIdx.y * 128, n0 = blockIdx.x * 128;
    int g = lane >> 2, qd = lane & 3;
    const int NT = K / 32;

    unsigned aA_rel = (unsigned)((wm*32 + (lane & 15))*80 + (lane >> 4)*16);
    unsigned aB_rel = (unsigned)((wn*64 + ((lane >> 4) & 1)*8 + (lane & 7))*80 + ((lane >> 3) & 1)*16);

    float acc[2][8][4] = {};

    // prologue: fill stages 0 and 1
    fill_bb(Ah, Al, Wh, Wl, sbase, 0, m0, n0, 0, M, K, tid);
    fill_bb(Ah, Al, Wh, Wl, sbase, 1, m0, n0, 1, M, K, tid);
    cp_wait1();            // stage 0 complete
    __syncthreads();

    for (int t = 0; t < NT; t++) {
        unsigned sA = sbase + (unsigned)((t & 1)*STG_SZ);
        unsigned sB = sA + 20480u;
        #pragma unroll
        for (int kk = 0; kk < 2; kk++) {
            unsigned ah[2][4], al[2][4];
            #pragma unroll
            for (int im = 0; im < 2; im++) {
                ldsm4(ah[im], sA + aA_rel + im*1280 + kk*32);
                ldsm4(al[im], sA + 10240u + aA_rel + im*1280 + kk*32);
            }
            #pragma unroll
            for (int j = 0; j < 4; j++) {
                unsigned bh[4], bl[4];
                ldsm4(bh, sB + aB_rel + j*1280 + kk*32);
                ldsm4(bl, sB + 10240u + aB_rel + j*1280 + kk*32);
                #pragma unroll
                for (int im = 0; im < 2; im++) {
                    mma_bf16(acc[im][2*j],   ah[im], bh[0], bh[1]);
                    mma_bf16(acc[im][2*j],   ah[im], bl[0], bl[1]);
                    mma_bf16(acc[im][2*j],   al[im], bh[0], bh[1]);
                    mma_bf16(acc[im][2*j+1], ah[im], bh[2], bh[3]);
                    mma_bf16(acc[im][2*j+1], ah[im], bl[2], bl[3]);
                    mma_bf16(acc[im][2*j+1], al[im], bh[2], bh[3]);
                }
            }
        }
        __syncthreads();                       // done reading buf[t&1]
        if (t + 2 < NT) {
            fill_bb(Ah, Al, Wh, Wl, sbase, t & 1, m0, n0, t + 2, M, K, tid);
        }
        if (t + 1 < NT) {
            if (t + 2 < NT) cp_wait1(); else cp_wait0();
            __syncthreads();                   // buf[(t+1)&1] ready & visible
        }
    }

    // ---- epilogue ----
    #pragma unroll
    for (int im = 0; im < 2; im++) {
        int r0 = m0 + wm*32 + im*16 + g;
        #pragma unroll
        for (int in_ = 0; in_ < 8; in_++) {
            int gcol = n0 + wn*64 + in_*8 + qd*2;
            float bv0 = bias[gcol], bv1 = bias[gcol+1];
            float v0 = acc[im][in_][0] + bv0;
            float v1 = acc[im][in_][1] + bv1;
            float v2 = acc[im][in_][2] + bv0;
            float v3 = acc[im][in_][3] + bv1;
            if (relu) {
                v0 = fmaxf(v0, 0.f); v1 = fmaxf(v1, 0.f);
                v2 = fmaxf(v2, 0.f); v3 = fmaxf(v3, 0.f);
            }
            if (mode == 2) {
                __nv_bfloat16 h0,l0,h1,l1;
                if (r0 < M) {
                    split2(v0, h0, l0); split2(v1, h1, l1);
                    __nv_bfloat162 hh; hh.x = h0; hh.y = h1;
                    __nv_bfloat162 ll; ll.x = l0; ll.y = l1;
                    *(__nv_bfloat162*)(Oh + (size_t)r0*Ntot + gcol) = hh;
                    *(__nv_bfloat162*)(Ol + (size_t)r0*Ntot + gcol) = ll;
                }
                if (r0 + 8 < M) {
                    split2(v2, h0, l0); split2(v3, h1, l1);
                    __nv_bfloat162 hh; hh.x = h0; hh.y = h1;
                    __nv_bfloat162 ll; ll.x = l0; ll.y = l1;
                    *(__nv_bfloat162*)(Oh + (size_t)(r0+8)*Ntot + gcol) = hh;
                    *(__nv_bfloat162*)(Ol + (size_t)(r0+8)*Ntot + gcol) = ll;
                }
            } else if (mode == 1) {
                __half* Ch = (__half*)C0;
                if (r0 < M)     *(__half2*)(Ch + (size_t)r0*Ntot + gcol)     = __floats2half2_rn(v0, v1);
                if (r0 + 8 < M) *(__half2*)(Ch + (size_t)(r0+8)*Ntot + gcol) = __floats2half2_rn(v2, v3);
            } else {
                float* Cc; int ldc, base;
                if (gcol < n_split) { Cc = C0; ldc = n_split;        base = 0; }
                else                { Cc = C1; ldc = Ntot - n_split; base = n_split; }
                int cn = gcol - base;
                if (r0 < M)     *(float2*)(Cc + (size_t)r0*ldc + cn)     = make_float2(v0, v1);
                if (r0 + 8 < M) *(float2*)(Cc + (size_t)(r0+8)*ldc + cn) = make_float2(v2, v3);
            }
        }
    }
}

// ---------------- softmax over 16 ----------------
__global__ void softmax16_kernel(float* __restrict__ aw, int n)
{
    int t = blockIdx.x*blockDim.x + threadIdx.x;
    if (t >= n) return;
    float* p = aw + (size_t)t*16;
    float buf[16];
    float m = -1e30f;
    #pragma unroll
    for (int i = 0; i < 16; i++) { buf[i] = p[i]; m = fmaxf(m, buf[i]); }
    float s = 0.f;
    #pragma unroll
    for (int i = 0; i < 16; i++) { buf[i] = expf(buf[i] - m); s += buf[i]; }
    float inv = 1.f / s;
    #pragma unroll
    for (int i = 0; i < 16; i++) p[i] = buf[i] * inv;
}

// ---------------- ms-deform attention core (fp16 values, bf16-pair out) ----------------
__global__ void __launch_bounds__(256)
msdeform_kernel(const __half* __restrict__ val, const float* __restrict__ off,
                const float* __restrict__ aw, const float* __restrict__ ref,
                __nv_bfloat16* __restrict__ oh, __nv_bfloat16* __restrict__ ol)
{
    int warp = blockIdx.x * (blockDim.x >> 5) + (threadIdx.x >> 5);
    int lane = threadIdx.x & 31;
    if (warp >= NB*LQT*NHH) return;
    int h  = warp & 7;
    int bq = warp >> 3;
    int q  = bq % LQT;
    int b  = bq / LQT;
    float gx = ref[q*2], gy = ref[q*2+1];
    const float* offp = off + (size_t)bq*DD  + h*32;
    const float* awp  = aw  + (size_t)bq*128 + h*16;
    float acc = 0.f;
    #pragma unroll
    for (int l = 0; l < 4; l++) {
        int Wl = c_W[l], Hl = c_H[l], st = c_start[l];
        float fW = (float)Wl, fH = (float)Hl;
        const __half* vb = val + ((size_t)b*LQT + st)*DD + h*32 + lane;
        #pragma unroll
        for (int p = 0; p < 4; p++) {
            float ox = offp[(l*4+p)*2+0], oy = offp[(l*4+p)*2+1];
            float a  = awp[l*4+p];
            float x = (gx + ox / fW) * fW - 0.5f;
            float y = (gy + oy / fH) * fH - 0.5f;
            float x0f = floorf(x), y0f = floorf(y);
            float tx = x - x0f, ty = y - y0f;
            int x0 = (int)x0f, y0 = (int)y0f;
            float w00 = (1.f-tx)*(1.f-ty)*a;
            float w10 = tx*(1.f-ty)*a;
            float w01 = (1.f-tx)*ty*a;
            float w11 = tx*ty*a;
            bool xv0 = (x0   >= 0) && (x0   < Wl);
            bool xv1 = (x0+1 >= 0) && (x0+1 < Wl);
            bool yv0 = (y0   >= 0) && (y0   < Hl);
            bool yv1 = (y0+1 >= 0) && (y0+1 < Hl);
            if (xv0 && yv0) acc += w00 * __half2float(vb[(size_t)(y0*Wl + x0)     * DD]);
            if (xv1 && yv0) acc += w10 * __half2float(vb[(size_t)(y0*Wl + x0 + 1) * DD]);
            if (xv0 && yv1) acc += w01 * __half2float(vb[(size_t)((y0+1)*Wl + x0)     * DD]);
            if (xv1 && yv1) acc += w11 * __half2float(vb[(size_t)((y0+1)*Wl + x0 + 1) * DD]);
        }
    }
    __nv_bfloat16 hh, ll;
    split2(acc, hh, ll);
    size_t o = (size_t)bq*DD + h*32 + lane;
    oh[o] = hh; ol[o] = ll;
}

// ---------------- residual + LayerNorm (+ bf16-pair outputs, optional q-splits) ----------------
__global__ void __launch_bounds__(256)
addln_kernel(float* __restrict__ src, const float* __restrict__ res,
             const float* __restrict__ g, const float* __restrict__ b,
             __nv_bfloat16* __restrict__ oh, __nv_bfloat16* __restrict__ ol,
             __nv_bfloat16* __restrict__ qh, __nv_bfloat16* __restrict__ ql,
             const float* __restrict__ pos)
{
    int row = blockIdx.x, t = threadIdx.x;
    size_t idx = (size_t)row*DD + t;
    float x = src[idx] + res[idx];
    float mean = blockSum(x) * (1.f/DD);
    float d = x - mean;
    float var = blockSum(d*d) * (1.f/DD);
    float y = d * rsqrtf(var + 1e-5f) * g[t] + b[t];
    src[idx] = y;
    __nv_bfloat16 h, l;
    split2(y, h, l);  oh[idx] = h; ol[idx] = l;
    if (qh) {
        split2(y + pos[idx], h, l);  qh[idx] = h; ql[idx] = l;
    }
}

// ---------------- finalize ----------------
__global__ void finalize_kernel(const float* __restrict__ src, float* __restrict__ out, int out_size)
{
    int i = blockIdx.x*blockDim.x + threadIdx.x;
    if (i >= out_size) return;
    const int n = NB*LQT*DD;
    if (i < n) { out[i] = src[i]; return; }
    int j = i - n;
    float v;
    if (j < 4)       v = (float)c_start[j];
    else if (j < 12) v = (float)c_H[(j-4) >> 1];
    else             v = 1.0f;
    out[i] = v;
}

// ---------------- host orchestration ----------------
extern "C" void kernel_launch(void* const* d_in, const int* in_sizes, int n_in,
                              void* d_out, int out_size)
{
    (void)n_in;
    const float *X[4], *FW[4], *FB[4];
    if (in_sizes[1] == 65536) {
        for (int i = 0; i < 4; i++) {
            X[i]  = (const float*)d_in[3*i+0];
            FW[i] = (const float*)d_in[3*i+1];
            FB[i] = (const float*)d_in[3*i+2];
        }
    } else {
        for (int i = 0; i < 4; i++) {
            X[i]  = (const float*)d_in[i];
            FW[i] = (const float*)d_in[4+2*i];
            FB[i] = (const float*)d_in[5+2*i];
        }
    }
    const float* gn_g  = (const float*)d_in[12];
    const float* gn_b  = (const float*)d_in[13];
    const float* lemb  = (const float*)d_in[14];
    const float* off_w = (const float*)d_in[15];
    const float* off_b = (const float*)d_in[16];
    const float* aw_w  = (const float*)d_in[17];
    const float* aw_b  = (const float*)d_in[18];
    const float* val_w = (const float*)d_in[19];
    const float* val_b = (const float*)d_in[20];
    const float* out_w = (const float*)d_in[21];
    const float* out_b = (const float*)d_in[22];
    const float* ln1_g = (const float*)d_in[23];
    const float* ln1_b = (const float*)d_in[24];
    const float* l1_w  = (const float*)d_in[25];
    const float* l1_b  = (const float*)d_in[26];
    const float* l2_w  = (const float*)d_in[27];
    const float* l2_b  = (const float*)d_in[28];
    const float* ln2_g = (const float*)d_in[29];
    const float* ln2_b = (const float*)d_in[30];

    float *src, *pos, *off, *aw, *val, *att, *ref, *cbias;
    __nv_bfloat16 *wh, *wl, *qh, *ql, *sh, *sl, *th, *tl, *msh, *msl, *hbh, *hbl;
    cudaGetSymbolAddress((void**)&src,   g_src);
    cudaGetSymbolAddress((void**)&pos,   g_pos);
    cudaGetSymbolAddress((void**)&off,   g_off);
    cudaGetSymbolAddress((void**)&aw,    g_aw);
    cudaGetSymbolAddress((void**)&val,   g_val);
    cudaGetSymbolAddress((void**)&att,   g_att);
    cudaGetSymbolAddress((void**)&ref,   g_ref);
    cudaGetSymbolAddress((void**)&cbias, g_cbias);
    cudaGetSymbolAddress((void**)&wh,    g_wh);
    cudaGetSymbolAddress((void**)&wl,    g_wl);
    cudaGetSymbolAddress((void**)&qh,    g_qh);
    cudaGetSymbolAddress((void**)&ql,    g_ql);
    cudaGetSymbolAddress((void**)&sh,    g_sh);
    cudaGetSymbolAddress((void**)&sl,    g_sl);
    cudaGetSymbolAddress((void**)&th,    g_th);
    cudaGetSymbolAddress((void**)&tl,    g_tl);
    cudaGetSymbolAddress((void**)&msh,   g_msh);
    cudaGetSymbolAddress((void**)&msl,   g_msl);
    cudaGetSymbolAddress((void**)&hbh,   g_hbh);
    cudaGetSymbolAddress((void**)&hbl,   g_hbl);

    cudaFuncSetAttribute(gemm_bb_kernel,
        cudaFuncAttributeMaxDynamicSharedMemorySize, SMEM_BB);

    // launch 0: all weight splits + concat bias
    split_all_kernel<<<(W_TOTAL + NLAY*384 + 255)/256, 256>>>(
        off_w, aw_w, val_w, out_w, l1_w, l2_w, off_b, aw_b, wh, wl, cbias);
    // launch 1: tokenizer (all levels/batches)
    tokenizer_kernel<<<1536, 256>>>(X[0], X[1], X[2], X[3],
                                    FW[0], FW[1], FW[2], FW[3],
                                    FB[0], FB[1], FB[2], FB[3], src);
    // launch 2: group norm
    gn_kernel<<<4*2*32, 256>>>(src, gn_g, gn_b);
    // launch 3: pos + ref
    posref_kernel<<<(LQT*DD + 255)/256, 256>>>(lemb, pos, ref);
    // launch 4: initial activation splits
    prep_kernel<<<(MTOT*DD + 255)/256, 256>>>(src, pos, sh, sl, qh, ql);

    const int GY = (MTOT + 127)/128;  // 192
    dim3 g_oaw(3, GY), g_256(2, GY), g_l1(8, GY);

    for (int l = 0; l < NLAY; l++) {
        // launch 5 (first iter): fused offset+attention-weight GEMM
        gemm_bb_kernel<<<g_oaw, 256, SMEM_BB>>>(qh, ql,
            wh + OFF_OAW + (size_t)l*98304, wl + OFF_OAW + (size_t)l*98304,
            cbias + l*384, off, aw, 256, (__nv_bfloat16*)0, (__nv_bfloat16*)0,
            MTOT, 384, 256, 0, 0);
        softmax16_kernel<<<(MTOT*NHH + 255)/256, 256>>>(aw, MTOT*NHH);
        gemm_bb_kernel<<<g_256, 256, SMEM_BB>>>(sh, sl,
            wh + OFF_VAL + (size_t)l*65536, wl + OFF_VAL + (size_t)l*65536,
            val_b + l*DD, val, (float*)0, 256, (__nv_bfloat16*)0, (__nv_bfloat16*)0,
            MTOT, 256, 256, 0, 1);
        msdeform_kernel<<<MTOT, 256>>>((const __half*)val, off, aw, ref, msh, msl);
        gemm_bb_kernel<<<g_256, 256, SMEM_BB>>>(msh, msl,
            wh + OFF_OUT + (size_t)l*65536, wl + OFF_OUT + (size_t)l*65536,
            out_b + l*DD, att, (float*)0, 256, (__nv_bfloat16*)0, (__nv_bfloat16*)0,
            MTOT, 256, 256, 0, 0);
        addln_kernel<<<MTOT, 256>>>(src, att, ln1_g + l*DD, ln1_b + l*DD,
            th, tl, (__nv_bfloat16*)0, (__nv_bfloat16*)0, (const float*)0);
        gemm_bb_kernel<<<g_l1, 256, SMEM_BB>>>(th, tl,
            wh + OFF_L1 + (size_t)l*262144, wl + OFF_L1 + (size_t)l*262144,
            l1_b + l*DFF_, (float*)0, (float*)0, 1024, hbh, hbl,
            MTOT, 1024, 256, 1, 2);
        gemm_bb_kernel<<<g_256, 256, SMEM_BB>>>(hbh, hbl,
            wh + OFF_L2 + (size_t)l*262144, wl + OFF_L2 + (size_t)l*262144,
            l2_b + l*DD, att, (float*)0, 256, (__nv_bfloat16*)0, (__nv_bfloat16*)0,
            MTOT, 256, 1024, 0, 0);
        addln_kernel<<<MTOT, 256>>>(src, att, ln2_g + l*DD, ln2_b + l*DD,
            sh, sl, qh, ql, pos);
    }

    finalize_kernel<<<(out_size + 255)/256, 256>>>(src, (float*)d_out, out_size);
}

// round 11
// speedup vs baseline: 2.1172x; 1.1532x over previous
#include <cuda_runtime.h>
#include <cuda_bf16.h>
#include <cuda_fp16.h>
#include <stdint.h>
#include <math.h>

// ---------------- problem constants ----------------
#define NB    2
#define DD    256
#define LQT   12240
#define NHH   8
#define NLAY  6
#define DFF_  1024
#define MTOT  (NB*LQT)   // 24480

__constant__ int c_H[4]     = {96,48,24,12};
__constant__ int c_W[4]     = {96,48,24,12};
__constant__ int c_start[4] = {0,9216,11520,12096};
__constant__ int c_len[4]   = {9216,2304,576,144};
__constant__ int c_cin[4]   = {256,512,768,1024};

// ---------------- scratch (device globals; no allocation) ----------------
__device__ float g_src[NB*LQT*DD];
__device__ float g_pos[NB*LQT*DD];
__device__ float g_off[NB*LQT*DD];
__device__ float g_aw [NB*LQT*128];
__device__ float g_val[NB*LQT*DD];    // fp16 payload
__device__ float g_att[NB*LQT*DD];
__device__ float g_ref[LQT*2];
__device__ float g_cbias[NLAY*384];
// fp16 hi/lo activation buffers (GEMM A-side inputs)
__device__ __half g_qh [MTOT*DD],  g_ql [MTOT*DD];
__device__ __half g_sh [MTOT*DD],  g_sl [MTOT*DD];
__device__ __half g_th [MTOT*DD],  g_tl [MTOT*DD];
__device__ __half g_msh[MTOT*DD],  g_msl[MTOT*DD];
__device__ __half g_hbh[MTOT*DFF_], g_hbl[MTOT*DFF_];

// fp16 weights; oaw fused per layer: off(65536)+aw(32768)
#define OFF_OAW 0
#define OFF_VAL 589824
#define OFF_OUT 983040
#define OFF_L1  1376256
#define OFF_L2  2949120
#define W_TOTAL 4521984
__device__ __half g_wf[W_TOTAL];

__device__ __forceinline__ int lvl_of(int q) {
    return (q < 9216) ? 0 : (q < 11520) ? 1 : (q < 12096) ? 2 : 3;
}

__device__ __forceinline__ float blockSum(float v) {
    __shared__ float sh[8];
    int lane = threadIdx.x & 31, w = threadIdx.x >> 5;
    #pragma unroll
    for (int o = 16; o > 0; o >>= 1) v += __shfl_xor_sync(0xffffffffu, v, o);
    if (lane == 0) sh[w] = v;
    __syncthreads();
    if (w == 0) {
        float r = (lane < 8) ? sh[lane] : 0.f;
        #pragma unroll
        for (int o = 4; o > 0; o >>= 1) r += __shfl_xor_sync(0xffffffffu, r, o);
        if (lane == 0) sh[0] = r;
    }
    __syncthreads();
    float res = sh[0];
    __syncthreads();
    return res;
}

__device__ __forceinline__ void split2h(float x, __half& h, __half& l) {
    h = __float2half_rn(x);
    l = __float2half_rn(x - __half2float(h));
}

// ---------------- launch 0: weight convert + concat bias + pos/ref ----------------
#define N_WB (W_TOTAL + NLAY*384)
__global__ void setup_kernel(
    const float* __restrict__ off_w, const float* __restrict__ aw_w,
    const float* __restrict__ val_w, const float* __restrict__ out_w,
    const float* __restrict__ l1_w,  const float* __restrict__ l2_w,
    const float* __restrict__ off_b, const float* __restrict__ aw_b,
    __half* __restrict__ wf, float* __restrict__ cbias,
    const float* __restrict__ lemb, float* __restrict__ pos, float* __restrict__ ref)
{
    int i = blockIdx.x*blockDim.x + threadIdx.x;
    if (i < W_TOTAL) {
        float x; long long o;
        if (i < 393216) {
            int l = i >> 16, r = i & 65535;
            x = off_w[i]; o = (long long)l*98304 + r;
        } else if (i < 589824) {
            int j = i - 393216;
            int l = j >> 15, r = j & 32767;
            x = aw_w[j]; o = (long long)l*98304 + 65536 + r;
        } else if (i < 983040) {
            x = val_w[i - 589824]; o = i;
        } else if (i < 1376256) {
            x = out_w[i - 983040]; o = i;
        } else if (i < 2949120) {
            x = l1_w[i - 1376256]; o = i;
        } else {
            x = l2_w[i - 2949120]; o = i;
        }
        wf[o] = __float2half_rn(x);
        return;
    }
    if (i < N_WB) {
        int j = i - W_TOTAL;
        int l = j / 384, c = j % 384;
        cbias[j] = (c < 256) ? off_b[l*256 + c] : aw_b[l*128 + (c - 256)];
        return;
    }
    int idx = i - N_WB;
    if (idx >= LQT*DD) return;
    int qq = idx >> 8, d = idx & 255;
    int lvl = lvl_of(qq);
    int st = c_start[lvl], H = c_H[lvl], W = c_W[lvl];
    int p = qq - st; int y = p / W, x = p % W;
    const float TWO_PI = 6.28318530717958647692f;
    const float LN1E4_64 = 0.14391156831212787f;
    float v;
    if (d < 128) {
        float e = (float)(y+1) / ((float)H + 1e-6f) * TWO_PI;
        int k = d >> 1;
        float u = e * expf(-LN1E4_64 * (float)k);
        v = (d & 1) ? cosf(u) : sinf(u);
    } else {
        int dd = d - 128;
        float e = (float)(x+1) / ((float)W + 1e-6f) * TWO_PI;
        int k = dd >> 1;
        float u = e * expf(-LN1E4_64 * (float)k);
        v = (dd & 1) ? cosf(u) : sinf(u);
    }
    v += lemb[lvl*DD + d];
    pos[(size_t)qq*DD + d] = v;
    pos[(size_t)(LQT + qq)*DD + d] = v;
    if (d == 0) {
        ref[qq*2+0] = ((float)x + 0.5f) / (float)W;
        ref[qq*2+1] = ((float)y + 0.5f) / (float)H;
    }
}

// ---------------- launch 1: tokenizer (all levels/batches) ----------------
__global__ void __launch_bounds__(256)
tokenizer_kernel(const float* __restrict__ X0, const float* __restrict__ X1,
                 const float* __restrict__ X2, const float* __restrict__ X3,
                 const float* __restrict__ W0, const float* __restrict__ W1,
                 const float* __restrict__ W2, const float* __restrict__ W3,
                 const float* __restrict__ B0, const float* __restrict__ B1,
                 const float* __restrict__ B2, const float* __restrict__ B3,
                 float* __restrict__ src)
{
    int bid = blockIdx.x;
    int lvl, base;
    if      (bid < 1152) { lvl = 0; base = 0; }
    else if (bid < 1440) { lvl = 1; base = 1152; }
    else if (bid < 1512) { lvl = 2; base = 1440; }
    else                 { lvl = 3; base = 1512; }
    int HW = c_len[lvl], K = c_cin[lvl];
    int rem = bid - base;
    int span = ((HW + 63)/64) * 4;
    int b = rem / span; rem -= b*span;
    int m0 = (rem >> 2) * 64, n0 = (rem & 3) * 64;
    const float* A = (lvl==0?X0:lvl==1?X1:lvl==2?X2:X3) + (size_t)b*K*HW;
    const float* W = (lvl==0?W0:lvl==1?W1:lvl==2?W2:W3);
    const float* bias = (lvl==0?B0:lvl==1?B1:lvl==2?B2:B3);
    float* C = src + ((size_t)b*LQT + c_start[lvl]) * DD;
    int M = HW, N = DD;

    __shared__ __align__(16) float As[16][68];
    __shared__ __align__(16) float Ws[16][68];
    int tid = threadIdx.x;
    int tx = tid & 15, ty = tid >> 4;
    int ak = tid >> 4, amq = (tid & 15) * 4;
    int wn = tid >> 2, wk  = (tid & 3) * 4;
    bool aok = (m0 + amq) < M;
    float acc[4][4] = {};
    for (int k0 = 0; k0 < K; k0 += 16) {
        float4 a4 = aok ? *(const float4*)(A + (size_t)(k0+ak)*M + m0 + amq)
                        : make_float4(0.f,0.f,0.f,0.f);
        *(float4*)&As[ak][amq] = a4;
        float4 w4 = *(const float4*)(W + (size_t)(n0+wn)*K + k0 + wk);
        Ws[wk+0][wn]=w4.x; Ws[wk+1][wn]=w4.y; Ws[wk+2][wn]=w4.z; Ws[wk+3][wn]=w4.w;
        __syncthreads();
        #pragma unroll
        for (int k = 0; k < 16; k++) {
            float4 a = *(const float4*)&As[k][ty*4];
            float4 w = *(const float4*)&Ws[k][tx*4];
            float ar[4] = {a.x,a.y,a.z,a.w}, wr[4] = {w.x,w.y,w.z,w.w};
            #pragma unroll
            for (int i = 0; i < 4; i++)
                #pragma unroll
                for (int j = 0; j < 4; j++)
                    acc[i][j] = fmaf(ar[i], wr[j], acc[i][j]);
        }
        __syncthreads();
    }
    #pragma unroll
    for (int i = 0; i < 4; i++) {
        int m = m0 + ty*4 + i;
        if (m >= M) break;
        #pragma unroll
        for (int j = 0; j < 4; j++) {
            int n = n0 + tx*4 + j;
            C[(size_t)m*N + n] = acc[i][j] + bias[n];
        }
    }
}

// ---------------- launch 2: GroupNorm + prep splits (fused) ----------------
__global__ void __launch_bounds__(256)
gn_kernel(float* __restrict__ src, const float* __restrict__ g, const float* __restrict__ b,
          const float* __restrict__ pos,
          __half* __restrict__ sh_, __half* __restrict__ sl_,
          __half* __restrict__ qh_, __half* __restrict__ ql_)
{
    int grp = blockIdx.x & 31;
    int bb  = (blockIdx.x >> 5) & 1;
    int lvl = blockIdx.x >> 6;
    int L = c_len[lvl], st = c_start[lvl];
    size_t gbase = ((size_t)bb*LQT + st) * DD;
    float* base = src + gbase;
    int n = L * 8;
    float s = 0.f;
    for (int i = threadIdx.x; i < n; i += 256)
        s += base[(size_t)(i>>3)*DD + grp*8 + (i&7)];
    float mean = blockSum(s) / (float)n;
    float s2 = 0.f;
    for (int i = threadIdx.x; i < n; i += 256) {
        float d = base[(size_t)(i>>3)*DD + grp*8 + (i&7)] - mean;
        s2 += d*d;
    }
    float rstd = rsqrtf(blockSum(s2) / (float)n + 1e-5f);
    for (int i = threadIdx.x; i < n; i += 256) {
        int c = grp*8 + (i&7);
        size_t id = (size_t)(i>>3)*DD + c;
        float y = (base[id] - mean) * rstd * g[lvl*DD + c] + b[lvl*DD + c];
        base[id] = y;
        size_t gid = gbase + id;
        __half h, l;
        split2h(y, h, l);          sh_[gid] = h; sl_[gid] = l;
        split2h(y + pos[gid], h, l); qh_[gid] = h; ql_[gid] = l;
    }
}

// ---------------- fp16x2 cp.async tensor-core GEMM ----------------
// C = (Ah+Al) x W^T + bias; A fp16 hi/lo, W fp16. BM=BN=128, BK=32, 2-stage.
// mode 0: fp32 out split at n_split; 1: fp16 out to C0; 2: fp16 hi/lo out to Oh/Ol.
#define STG_SZ 30720
#define SMEM_BB (2*STG_SZ)

__device__ __forceinline__ void mma_f16(float c[4], const unsigned a[4],
                                        unsigned b0, unsigned b1)
{
    asm volatile("mma.sync.aligned.m16n8k16.row.col.f32.f16.f16.f32 "
        "{%0,%1,%2,%3}, {%4,%5,%6,%7}, {%8,%9}, {%0,%1,%2,%3};"
        : "+f"(c[0]), "+f"(c[1]), "+f"(c[2]), "+f"(c[3])
        : "r"(a[0]), "r"(a[1]), "r"(a[2]), "r"(a[3]), "r"(b0), "r"(b1));
}
__device__ __forceinline__ void ldsm4(unsigned r[4], unsigned a) {
    asm volatile("ldmatrix.sync.aligned.m8n8.x4.shared.b16 {%0,%1,%2,%3}, [%4];"
        : "=r"(r[0]), "=r"(r[1]), "=r"(r[2]), "=r"(r[3]) : "r"(a));
}
__device__ __forceinline__ void cp16(unsigned dst, const void* src) {
    asm volatile("cp.async.cg.shared.global [%0], [%1], 16;" :: "r"(dst), "l"(src));
}
__device__ __forceinline__ void cp16z(unsigned dst, const void* src, int sz) {
    asm volatile("cp.async.cg.shared.global [%0], [%1], 16, %2;" :: "r"(dst), "l"(src), "r"(sz));
}
__device__ __forceinline__ void cp_commit() { asm volatile("cp.async.commit_group;"); }
__device__ __forceinline__ void cp_wait1()  { asm volatile("cp.async.wait_group 1;"); }
__device__ __forceinline__ void cp_wait0()  { asm volatile("cp.async.wait_group 0;"); }

__device__ __forceinline__ void fill_bb(
    const __half* __restrict__ Ah, const __half* __restrict__ Al,
    const __half* __restrict__ Wf,
    unsigned sbase, int stage, int m0, int n0, int t, int M, int K, int tid)
{
    int row = tid >> 1, lcol = (tid & 1) * 16;
    unsigned so = sbase + (unsigned)(stage*STG_SZ) + (unsigned)(row*80 + lcol*2);
    size_t ga = (size_t)(m0 + row)*K + t*32 + lcol;
    size_t gb = (size_t)(n0 + row)*K + t*32 + lcol;
    int asz = ((m0 + row) < M) ? 16 : 0;
    cp16z(so,              Ah + ga,     asz);
    cp16z(so + 16,         Ah + ga + 8, asz);
    cp16z(so + 10240,      Al + ga,     asz);
    cp16z(so + 10240 + 16, Al + ga + 8, asz);
    cp16 (so + 20480,      Wf + gb);
    cp16 (so + 20480 + 16, Wf + gb + 8);
    cp_commit();
}

__global__ void __launch_bounds__(256, 2)
gemm_bb_kernel(const __half* __restrict__ Ah, const __half* __restrict__ Al,
               const __half* __restrict__ Wf,
               const float* __restrict__ bias,
               float* __restrict__ C0, float* __restrict__ C1, int n_split,
               __half* __restrict__ Oh, __half* __restrict__ Ol,
               int M, int Ntot, int K, int relu, int mode)
{
    extern __shared__ __align__(16) char smem[];
    unsigned sbase = (unsigned)__cvta_generic_to_shared(smem);
    int tid  = threadIdx.x;
    int lane = tid & 31, warp = tid >> 5;
    int wm = warp & 3, wn = warp >> 2;
    int m0 = blockIdx.y * 128, n0 = blockIdx.x * 128;
    int g = lane >> 2, qd = lane & 3;
    const int NT = K / 32;

    unsigned aA_rel = (unsigned)((wm*32 + (lane & 15))*80 + (lane >> 4)*16);
    unsigned aB_rel = (unsigned)((wn*64 + ((lane >> 4) & 1)*8 + (lane & 7))*80 + ((lane >> 3) & 1)*16);

    float acc[2][8][4] = {};

    fill_bb(Ah, Al, Wf, sbase, 0, m0, n0, 0, M, K, tid);
    fill_bb(Ah, Al, Wf, sbase, 1, m0, n0, 1, M, K, tid);
    cp_wait1();
    __syncthreads();

    for (int t = 0; t < NT; t++) {
        unsigned sA = sbase + (unsigned)((t & 1)*STG_SZ);
        unsigned sB = sA + 20480u;
        #pragma unroll
        for (int kk = 0; kk < 2; kk++) {
            unsigned ah[2][4], al[2][4];
            #pragma unroll
            for (int im = 0; im < 2; im++) {
                ldsm4(ah[im], sA + aA_rel + im*1280 + kk*32);
                ldsm4(al[im], sA + 10240u + aA_rel + im*1280 + kk*32);
            }
            #pragma unroll
            for (int j = 0; j < 4; j++) {
                unsigned bw[4];
                ldsm4(bw, sB + aB_rel + j*1280 + kk*32);
                #pragma unroll
                for (int im = 0; im < 2; im++) {
                    mma_f16(acc[im][2*j],   ah[im], bw[0], bw[1]);
                    mma_f16(acc[im][2*j],   al[im], bw[0], bw[1]);
                    mma_f16(acc[im][2*j+1], ah[im], bw[2], bw[3]);
                    mma_f16(acc[im][2*j+1], al[im], bw[2], bw[3]);
                }
            }
        }
        __syncthreads();
        if (t + 2 < NT) {
            fill_bb(Ah, Al, Wf, sbase, t & 1, m0, n0, t + 2, M, K, tid);
        }
        if (t + 1 < NT) {
            if (t + 2 < NT) cp_wait1(); else cp_wait0();
            __syncthreads();
        }
    }

    // ---- epilogue ----
    #pragma unroll
    for (int im = 0; im < 2; im++) {
        int r0 = m0 + wm*32 + im*16 + g;
        #pragma unroll
        for (int in_ = 0; in_ < 8; in_++) {
            int gcol = n0 + wn*64 + in_*8 + qd*2;
            float bv0 = bias[gcol], bv1 = bias[gcol+1];
            float v0 = acc[im][in_][0] + bv0;
            float v1 = acc[im][in_][1] + bv1;
            float v2 = acc[im][in_][2] + bv0;
            float v3 = acc[im][in_][3] + bv1;
            if (relu) {
                v0 = fmaxf(v0, 0.f); v1 = fmaxf(v1, 0.f);
                v2 = fmaxf(v2, 0.f); v3 = fmaxf(v3, 0.f);
            }
            if (mode == 2) {
                __half h0,l0,h1,l1;
                if (r0 < M) {
                    split2h(v0, h0, l0); split2h(v1, h1, l1);
                    __half2 hh; hh.x = h0; hh.y = h1;
                    __half2 ll; ll.x = l0; ll.y = l1;
                    *(__half2*)(Oh + (size_t)r0*Ntot + gcol) = hh;
                    *(__half2*)(Ol + (size_t)r0*Ntot + gcol) = ll;
                }
                if (r0 + 8 < M) {
                    split2h(v2, h0, l0); split2h(v3, h1, l1);
                    __half2 hh; hh.x = h0; hh.y = h1;
                    __half2 ll; ll.x = l0; ll.y = l1;
                    *(__half2*)(Oh + (size_t)(r0+8)*Ntot + gcol) = hh;
                    *(__half2*)(Ol + (size_t)(r0+8)*Ntot + gcol) = ll;
                }
            } else if (mode == 1) {
                __half* Ch = (__half*)C0;
                if (r0 < M)     *(__half2*)(Ch + (size_t)r0*Ntot + gcol)     = __floats2half2_rn(v0, v1);
                if (r0 + 8 < M) *(__half2*)(Ch + (size_t)(r0+8)*Ntot + gcol) = __floats2half2_rn(v2, v3);
            } else {
                float* Cc; int ldc, base;
                if (gcol < n_split) { Cc = C0; ldc = n_split;        base = 0; }
                else                { Cc = C1; ldc = Ntot - n_split; base = n_split; }
                int cn = gcol - base;
                if (r0 < M)     *(float2*)(Cc + (size_t)r0*ldc + cn)     = make_float2(v0, v1);
                if (r0 + 8 < M) *(float2*)(Cc + (size_t)(r0+8)*ldc + cn) = make_float2(v2, v3);
            }
        }
    }
}

// ---------------- softmax over 16 ----------------
__global__ void softmax16_kernel(float* __restrict__ aw, int n)
{
    int t = blockIdx.x*blockDim.x + threadIdx.x;
    if (t >= n) return;
    float* p = aw + (size_t)t*16;
    float buf[16];
    float m = -1e30f;
    #pragma unroll
    for (int i = 0; i < 16; i++) { buf[i] = p[i]; m = fmaxf(m, buf[i]); }
    float s = 0.f;
    #pragma unroll
    for (int i = 0; i < 16; i++) { buf[i] = expf(buf[i] - m); s += buf[i]; }
    float inv = 1.f / s;
    #pragma unroll
    for (int i = 0; i < 16; i++) p[i] = buf[i] * inv;
}

// ---------------- ms-deform attention core (fp16 values, fp16-pair out) ----------------
__global__ void __launch_bounds__(256)
msdeform_kernel(const __half* __restrict__ val, const float* __restrict__ off,
                const float* __restrict__ aw, const float* __restrict__ ref,
                __half* __restrict__ oh, __half* __restrict__ ol)
{
    int warp = blockIdx.x * (blockDim.x >> 5) + (threadIdx.x >> 5);
    int lane = threadIdx.x & 31;
    if (warp >= NB*LQT*NHH) return;
    int h  = warp & 7;
    int bq = warp >> 3;
    int q  = bq % LQT;
    int b  = bq / LQT;
    float gx = ref[q*2], gy = ref[q*2+1];
    const float* offp = off + (size_t)bq*DD  + h*32;
    const float* awp  = aw  + (size_t)bq*128 + h*16;
    float acc = 0.f;
    #pragma unroll
    for (int l = 0; l < 4; l++) {
        int Wl = c_W[l], Hl = c_H[l], st = c_start[l];
        float fW = (float)Wl, fH = (float)Hl;
        const __half* vb = val + ((size_t)b*LQT + st)*DD + h*32 + lane;
        #pragma unroll
        for (int p = 0; p < 4; p++) {
            float ox = offp[(l*4+p)*2+0], oy = offp[(l*4+p)*2+1];
            float a  = awp[l*4+p];
            float x = (gx + ox / fW) * fW - 0.5f;
            float y = (gy + oy / fH) * fH - 0.5f;
            float x0f = floorf(x), y0f = floorf(y);
            float tx = x - x0f, ty = y - y0f;
            int x0 = (int)x0f, y0 = (int)y0f;
            float w00 = (1.f-tx)*(1.f-ty)*a;
            float w10 = tx*(1.f-ty)*a;
            float w01 = (1.f-tx)*ty*a;
            float w11 = tx*ty*a;
            bool xv0 = (x0   >= 0) && (x0   < Wl);
            bool xv1 = (x0+1 >= 0) && (x0+1 < Wl);
            bool yv0 = (y0   >= 0) && (y0   < Hl);
            bool yv1 = (y0+1 >= 0) && (y0+1 < Hl);
            if (xv0 && yv0) acc += w00 * __half2float(vb[(size_t)(y0*Wl + x0)     * DD]);
            if (xv1 && yv0) acc += w10 * __half2float(vb[(size_t)(y0*Wl + x0 + 1) * DD]);
            if (xv0 && yv1) acc += w01 * __half2float(vb[(size_t)((y0+1)*Wl + x0)     * DD]);
            if (xv1 && yv1) acc += w11 * __half2float(vb[(size_t)((y0+1)*Wl + x0 + 1) * DD]);
        }
    }
    __half hh, ll;
    split2h(acc, hh, ll);
    size_t o = (size_t)bq*DD + h*32 + lane;
    oh[o] = hh; ol[o] = ll;
}

// ---------------- residual + LayerNorm (+ fp16-pair outputs, optional q-splits) ----------------
__global__ void __launch_bounds__(256)
addln_kernel(float* __restrict__ src, const float* __restrict__ res,
             const float* __restrict__ g, const float* __restrict__ b,
             __half* __restrict__ oh, __half* __restrict__ ol,
             __half* __restrict__ qh, __half* __restrict__ ql,
             const float* __restrict__ pos)
{
    int row = blockIdx.x, t = threadIdx.x;
    size_t idx = (size_t)row*DD + t;
    float x = src[idx] + res[idx];
    float mean = blockSum(x) * (1.f/DD);
    float d = x - mean;
    float var = blockSum(d*d) * (1.f/DD);
    float y = d * rsqrtf(var + 1e-5f) * g[t] + b[t];
    src[idx] = y;
    __half h, l;
    split2h(y, h, l);  oh[idx] = h; ol[idx] = l;
    if (qh) {
        split2h(y + pos[idx], h, l);  qh[idx] = h; ql[idx] = l;
    }
}

// ---------------- finalize ----------------
__global__ void finalize_kernel(const float* __restrict__ src, float* __restrict__ out, int out_size)
{
    int i = blockIdx.x*blockDim.x + threadIdx.x;
    if (i >= out_size) return;
    const int n = NB*LQT*DD;
    if (i < n) { out[i] = src[i]; return; }
    int j = i - n;
    float v;
    if (j < 4)       v = (float)c_start[j];
    else if (j < 12) v = (float)c_H[(j-4) >> 1];
    else             v = 1.0f;
    out[i] = v;
}

// ---------------- host orchestration ----------------
extern "C" void kernel_launch(void* const* d_in, const int* in_sizes, int n_in,
                              void* d_out, int out_size)
{
    (void)n_in;
    const float *X[4], *FW[4], *FB[4];
    if (in_sizes[1] == 65536) {
        for (int i = 0; i < 4; i++) {
            X[i]  = (const float*)d_in[3*i+0];
            FW[i] = (const float*)d_in[3*i+1];
            FB[i] = (const float*)d_in[3*i+2];
        }
    } else {
        for (int i = 0; i < 4; i++) {
            X[i]  = (const float*)d_in[i];
            FW[i] = (const float*)d_in[4+2*i];
            FB[i] = (const float*)d_in[5+2*i];
        }
    }
    const float* gn_g  = (const float*)d_in[12];
    const float* gn_b  = (const float*)d_in[13];
    const float* lemb  = (const float*)d_in[14];
    const float* off_w = (const float*)d_in[15];
    const float* off_b = (const float*)d_in[16];
    const float* aw_w  = (const float*)d_in[17];
    const float* aw_b  = (const float*)d_in[18];
    const float* val_w = (const float*)d_in[19];
    const float* val_b = (const float*)d_in[20];
    const float* out_w = (const float*)d_in[21];
    const float* out_b = (const float*)d_in[22];
    const float* ln1_g = (const float*)d_in[23];
    const float* ln1_b = (const float*)d_in[24];
    const float* l1_w  = (const float*)d_in[25];
    const float* l1_b  = (const float*)d_in[26];
    const float* l2_w  = (const float*)d_in[27];
    const float* l2_b  = (const float*)d_in[28];
    const float* ln2_g = (const float*)d_in[29];
    const float* ln2_b = (const float*)d_in[30];

    float *src, *pos, *off, *aw, *val, *att, *ref, *cbias;
    __half *wf, *qh, *ql, *sh, *sl, *th, *tl, *msh, *msl, *hbh, *hbl;
    cudaGetSymbolAddress((void**)&src,   g_src);
    cudaGetSymbolAddress((void**)&pos,   g_pos);
    cudaGetSymbolAddress((void**)&off,   g_off);
    cudaGetSymbolAddress((void**)&aw,    g_aw);
    cudaGetSymbolAddress((void**)&val,   g_val);
    cudaGetSymbolAddress((void**)&att,   g_att);
    cudaGetSymbolAddress((void**)&ref,   g_ref);
    cudaGetSymbolAddress((void**)&cbias, g_cbias);
    cudaGetSymbolAddress((void**)&wf,    g_wf);
    cudaGetSymbolAddress((void**)&qh,    g_qh);
    cudaGetSymbolAddress((void**)&ql,    g_ql);
    cudaGetSymbolAddress((void**)&sh,    g_sh);
    cudaGetSymbolAddress((void**)&sl,    g_sl);
    cudaGetSymbolAddress((void**)&th,    g_th);
    cudaGetSymbolAddress((void**)&tl,    g_tl);
    cudaGetSymbolAddress((void**)&msh,   g_msh);
    cudaGetSymbolAddress((void**)&msl,   g_msl);
    cudaGetSymbolAddress((void**)&hbh,   g_hbh);
    cudaGetSymbolAddress((void**)&hbl,   g_hbl);

    cudaFuncSetAttribute(gemm_bb_kernel,
        cudaFuncAttributeMaxDynamicSharedMemorySize, SMEM_BB);

    // launch 0: weights + bias + pos/ref
    setup_kernel<<<(N_WB + LQT*DD + 255)/256, 256>>>(
        off_w, aw_w, val_w, out_w, l1_w, l2_w, off_b, aw_b, wf, cbias, lemb, pos, ref);
    // launch 1: tokenizer
    tokenizer_kernel<<<1536, 256>>>(X[0], X[1], X[2], X[3],
                                    FW[0], FW[1], FW[2], FW[3],
                                    FB[0], FB[1], FB[2], FB[3], src);
    // launch 2: group norm + prep splits
    gn_kernel<<<4*2*32, 256>>>(src, gn_g, gn_b, pos, sh, sl, qh, ql);

    const int GY = (MTOT + 127)/128;  // 192
    dim3 g_oaw(3, GY), g_256(2, GY), g_l1(8, GY);

    for (int l = 0; l < NLAY; l++) {
        // launch 3 (first iter): fused offset+attention-weight GEMM
        gemm_bb_kernel<<<g_oaw, 256, SMEM_BB>>>(qh, ql,
            wf + OFF_OAW + (size_t)l*98304,
            cbias + l*384, off, aw, 256, (__half*)0, (__half*)0,
            MTOT, 384, 256, 0, 0);
        softmax16_kernel<<<(MTOT*NHH + 255)/256, 256>>>(aw, MTOT*NHH);
        gemm_bb_kernel<<<g_256, 256, SMEM_BB>>>(sh, sl,
            wf + OFF_VAL + (size_t)l*65536,
            val_b + l*DD, val, (float*)0, 256, (__half*)0, (__half*)0,
            MTOT, 256, 256, 0, 1);
        msdeform_kernel<<<MTOT, 256>>>((const __half*)val, off, aw, ref, msh, msl);
        gemm_bb_kernel<<<g_256, 256, SMEM_BB>>>(msh, msl,
            wf + OFF_OUT + (size_t)l*65536,
            out_b + l*DD, att, (float*)0, 256, (__half*)0, (__half*)0,
            MTOT, 256, 256, 0, 0);
        addln_kernel<<<MTOT, 256>>>(src, att, ln1_g + l*DD, ln1_b + l*DD,
            th, tl, (__half*)0, (__half*)0, (const float*)0);
        gemm_bb_kernel<<<g_l1, 256, SMEM_BB>>>(th, tl,
            wf + OFF_L1 + (size_t)l*262144,
            l1_b + l*DFF_, (float*)0, (float*)0, 1024, hbh, hbl,
            MTOT, 1024, 256, 1, 2);
        gemm_bb_kernel<<<g_256, 256, SMEM_BB>>>(hbh, hbl,
            wf + OFF_L2 + (size_t)l*262144,
            l2_b + l*DD, att, (float*)0, 256, (__half*)0, (__half*)0,
            MTOT, 256, 1024, 0, 0);
        addln_kernel<<<MTOT, 256>>>(src, att, ln2_g + l*DD, ln2_b + l*DD,
            sh, sl, qh, ql, pos);
    }

    finalize_kernel<<<(out_size + 255)/256, 256>>>(src, (float*)d_out, out_size);
}

// round 12
// speedup vs baseline: 2.2430x; 1.0594x over previous
#include <cuda_runtime.h>
#include <cuda_bf16.h>
#include <cuda_fp16.h>
#include <stdint.h>
#include <math.h>

// ---------------- problem constants ----------------
#define NB    2
#define DD    256
#define LQT   12240
#define NHH   8
#define NLAY  6
#define DFF_  1024
#define MTOT  (NB*LQT)   // 24480

__constant__ int c_H[4]     = {96,48,24,12};
__constant__ int c_W[4]     = {96,48,24,12};
__constant__ int c_start[4] = {0,9216,11520,12096};
__constant__ int c_len[4]   = {9216,2304,576,144};
__constant__ int c_cin[4]   = {256,512,768,1024};

// ---------------- scratch (device globals; no allocation) ----------------
__device__ float g_src[NB*LQT*DD];
__device__ float g_pos[NB*LQT*DD];
__device__ float g_off[NB*LQT*DD];
__device__ float g_aw [NB*LQT*128];
__device__ float g_val[NB*LQT*DD];    // fp16 payload
__device__ float g_att[NB*LQT*DD];
__device__ float g_ref[LQT*2];
__device__ float g_cbias[NLAY*384];
// fp16 hi/lo activation buffers (GEMM A-side inputs)
__device__ __half g_qh [MTOT*DD],  g_ql [MTOT*DD];
__device__ __half g_sh [MTOT*DD],  g_sl [MTOT*DD];
__device__ __half g_th [MTOT*DD],  g_tl [MTOT*DD];
__device__ __half g_msh[MTOT*DD],  g_msl[MTOT*DD];
__device__ __half g_hbh[MTOT*DFF_], g_hbl[MTOT*DFF_];

// fp16 weights; oaw fused per layer: off(65536)+aw(32768)
#define OFF_OAW 0
#define OFF_VAL 589824
#define OFF_OUT 983040
#define OFF_L1  1376256
#define OFF_L2  2949120
#define W_TOTAL 4521984
__device__ __half g_wf[W_TOTAL];

__device__ __forceinline__ int lvl_of(int q) {
    return (q < 9216) ? 0 : (q < 11520) ? 1 : (q < 12096) ? 2 : 3;
}

__device__ __forceinline__ float blockSum(float v) {
    __shared__ float sh[8];
    int lane = threadIdx.x & 31, w = threadIdx.x >> 5;
    #pragma unroll
    for (int o = 16; o > 0; o >>= 1) v += __shfl_xor_sync(0xffffffffu, v, o);
    if (lane == 0) sh[w] = v;
    __syncthreads();
    if (w == 0) {
        float r = (lane < 8) ? sh[lane] : 0.f;
        #pragma unroll
        for (int o = 4; o > 0; o >>= 1) r += __shfl_xor_sync(0xffffffffu, r, o);
        if (lane == 0) sh[0] = r;
    }
    __syncthreads();
    float res = sh[0];
    __syncthreads();
    return res;
}

__device__ __forceinline__ void split2h(float x, __half& h, __half& l) {
    h = __float2half_rn(x);
    l = __float2half_rn(x - __half2float(h));
}

// ---------------- launch 0: weight convert + concat bias + pos/ref ----------------
#define N_WB (W_TOTAL + NLAY*384)
__global__ void setup_kernel(
    const float* __restrict__ off_w, const float* __restrict__ aw_w,
    const float* __restrict__ val_w, const float* __restrict__ out_w,
    const float* __restrict__ l1_w,  const float* __restrict__ l2_w,
    const float* __restrict__ off_b, const float* __restrict__ aw_b,
    __half* __restrict__ wf, float* __restrict__ cbias,
    const float* __restrict__ lemb, float* __restrict__ pos, float* __restrict__ ref)
{
    int i = blockIdx.x*blockDim.x + threadIdx.x;
    if (i < W_TOTAL) {
        float x; long long o;
        if (i < 393216) {
            int l = i >> 16, r = i & 65535;
            x = off_w[i]; o = (long long)l*98304 + r;
        } else if (i < 589824) {
            int j = i - 393216;
            int l = j >> 15, r = j & 32767;
            x = aw_w[j]; o = (long long)l*98304 + 65536 + r;
        } else if (i < 983040) {
            x = val_w[i - 589824]; o = i;
        } else if (i < 1376256) {
            x = out_w[i - 983040]; o = i;
        } else if (i < 2949120) {
            x = l1_w[i - 1376256]; o = i;
        } else {
            x = l2_w[i - 2949120]; o = i;
        }
        wf[o] = __float2half_rn(x);
        return;
    }
    if (i < N_WB) {
        int j = i - W_TOTAL;
        int l = j / 384, c = j % 384;
        cbias[j] = (c < 256) ? off_b[l*256 + c] : aw_b[l*128 + (c - 256)];
        return;
    }
    int idx = i - N_WB;
    if (idx >= LQT*DD) return;
    int qq = idx >> 8, d = idx & 255;
    int lvl = lvl_of(qq);
    int st = c_start[lvl], H = c_H[lvl], W = c_W[lvl];
    int p = qq - st; int y = p / W, x = p % W;
    const float TWO_PI = 6.28318530717958647692f;
    const float LN1E4_64 = 0.14391156831212787f;
    float v;
    if (d < 128) {
        float e = (float)(y+1) / ((float)H + 1e-6f) * TWO_PI;
        int k = d >> 1;
        float u = e * expf(-LN1E4_64 * (float)k);
        v = (d & 1) ? cosf(u) : sinf(u);
    } else {
        int dd = d - 128;
        float e = (float)(x+1) / ((float)W + 1e-6f) * TWO_PI;
        int k = dd >> 1;
        float u = e * expf(-LN1E4_64 * (float)k);
        v = (dd & 1) ? cosf(u) : sinf(u);
    }
    v += lemb[lvl*DD + d];
    pos[(size_t)qq*DD + d] = v;
    pos[(size_t)(LQT + qq)*DD + d] = v;
    if (d == 0) {
        ref[qq*2+0] = ((float)x + 0.5f) / (float)W;
        ref[qq*2+1] = ((float)y + 0.5f) / (float)H;
    }
}

// ---------------- launch 1: tokenizer (all levels/batches) ----------------
__global__ void __launch_bounds__(256)
tokenizer_kernel(const float* __restrict__ X0, const float* __restrict__ X1,
                 const float* __restrict__ X2, const float* __restrict__ X3,
                 const float* __restrict__ W0, const float* __restrict__ W1,
                 const float* __restrict__ W2, const float* __restrict__ W3,
                 const float* __restrict__ B0, const float* __restrict__ B1,
                 const float* __restrict__ B2, const float* __restrict__ B3,
                 float* __restrict__ src)
{
    int bid = blockIdx.x;
    int lvl, base;
    if      (bid < 1152) { lvl = 0; base = 0; }
    else if (bid < 1440) { lvl = 1; base = 1152; }
    else if (bid < 1512) { lvl = 2; base = 1440; }
    else                 { lvl = 3; base = 1512; }
    int HW = c_len[lvl], K = c_cin[lvl];
    int rem = bid - base;
    int span = ((HW + 63)/64) * 4;
    int b = rem / span; rem -= b*span;
    int m0 = (rem >> 2) * 64, n0 = (rem & 3) * 64;
    const float* A = (lvl==0?X0:lvl==1?X1:lvl==2?X2:X3) + (size_t)b*K*HW;
    const float* W = (lvl==0?W0:lvl==1?W1:lvl==2?W2:W3);
    const float* bias = (lvl==0?B0:lvl==1?B1:lvl==2?B2:B3);
    float* C = src + ((size_t)b*LQT + c_start[lvl]) * DD;
    int M = HW, N = DD;

    __shared__ __align__(16) float As[16][68];
    __shared__ __align__(16) float Ws[16][68];
    int tid = threadIdx.x;
    int tx = tid & 15, ty = tid >> 4;
    int ak = tid >> 4, amq = (tid & 15) * 4;
    int wn = tid >> 2, wk  = (tid & 3) * 4;
    bool aok = (m0 + amq) < M;
    float acc[4][4] = {};
    for (int k0 = 0; k0 < K; k0 += 16) {
        float4 a4 = aok ? *(const float4*)(A + (size_t)(k0+ak)*M + m0 + amq)
                        : make_float4(0.f,0.f,0.f,0.f);
        *(float4*)&As[ak][amq] = a4;
        float4 w4 = *(const float4*)(W + (size_t)(n0+wn)*K + k0 + wk);
        Ws[wk+0][wn]=w4.x; Ws[wk+1][wn]=w4.y; Ws[wk+2][wn]=w4.z; Ws[wk+3][wn]=w4.w;
        __syncthreads();
        #pragma unroll
        for (int k = 0; k < 16; k++) {
            float4 a = *(const float4*)&As[k][ty*4];
            float4 w = *(const float4*)&Ws[k][tx*4];
            float ar[4] = {a.x,a.y,a.z,a.w}, wr[4] = {w.x,w.y,w.z,w.w};
            #pragma unroll
            for (int i = 0; i < 4; i++)
                #pragma unroll
                for (int j = 0; j < 4; j++)
                    acc[i][j] = fmaf(ar[i], wr[j], acc[i][j]);
        }
        __syncthreads();
    }
    #pragma unroll
    for (int i = 0; i < 4; i++) {
        int m = m0 + ty*4 + i;
        if (m >= M) break;
        #pragma unroll
        for (int j = 0; j < 4; j++) {
            int n = n0 + tx*4 + j;
            C[(size_t)m*N + n] = acc[i][j] + bias[n];
        }
    }
}

// ---------------- launch 2: GroupNorm + prep splits (fused) ----------------
__global__ void __launch_bounds__(256)
gn_kernel(float* __restrict__ src, const float* __restrict__ g, const float* __restrict__ b,
          const float* __restrict__ pos,
          __half* __restrict__ sh_, __half* __restrict__ sl_,
          __half* __restrict__ qh_, __half* __restrict__ ql_)
{
    int grp = blockIdx.x & 31;
    int bb  = (blockIdx.x >> 5) & 1;
    int lvl = blockIdx.x >> 6;
    int L = c_len[lvl], st = c_start[lvl];
    size_t gbase = ((size_t)bb*LQT + st) * DD;
    float* base = src + gbase;
    int n = L * 8;
    float s = 0.f;
    for (int i = threadIdx.x; i < n; i += 256)
        s += base[(size_t)(i>>3)*DD + grp*8 + (i&7)];
    float mean = blockSum(s) / (float)n;
    float s2 = 0.f;
    for (int i = threadIdx.x; i < n; i += 256) {
        float d = base[(size_t)(i>>3)*DD + grp*8 + (i&7)] - mean;
        s2 += d*d;
    }
    float rstd = rsqrtf(blockSum(s2) / (float)n + 1e-5f);
    for (int i = threadIdx.x; i < n; i += 256) {
        int c = grp*8 + (i&7);
        size_t id = (size_t)(i>>3)*DD + c;
        float y = (base[id] - mean) * rstd * g[lvl*DD + c] + b[lvl*DD + c];
        base[id] = y;
        size_t gid = gbase + id;
        __half h, l;
        split2h(y, h, l);          sh_[gid] = h; sl_[gid] = l;
        split2h(y + pos[gid], h, l); qh_[gid] = h; ql_[gid] = l;
    }
}

// ---------------- fp16x2 cp.async tensor-core GEMM ----------------
// C = (Ah+Al) x W^T + bias; A fp16 hi/lo, W fp16. BM=BN=128, BK=32, 2-stage.
// mode 0: fp32 out split at n_split; 1: fp16 out to C0; 2: fp16 hi/lo out to Oh/Ol.
#define STG_SZ 30720
#define SMEM_BB (2*STG_SZ)

__device__ __forceinline__ void mma_f16(float c[4], const unsigned a[4],
                                        unsigned b0, unsigned b1)
{
    asm volatile("mma.sync.aligned.m16n8k16.row.col.f32.f16.f16.f32 "
        "{%0,%1,%2,%3}, {%4,%5,%6,%7}, {%8,%9}, {%0,%1,%2,%3};"
        : "+f"(c[0]), "+f"(c[1]), "+f"(c[2]), "+f"(c[3])
        : "r"(a[0]), "r"(a[1]), "r"(a[2]), "r"(a[3]), "r"(b0), "r"(b1));
}
__device__ __forceinline__ void ldsm4(unsigned r[4], unsigned a) {
    asm volatile("ldmatrix.sync.aligned.m8n8.x4.shared.b16 {%0,%1,%2,%3}, [%4];"
        : "=r"(r[0]), "=r"(r[1]), "=r"(r[2]), "=r"(r[3]) : "r"(a));
}
__device__ __forceinline__ void cp16(unsigned dst, const void* src) {
    asm volatile("cp.async.cg.shared.global [%0], [%1], 16;" :: "r"(dst), "l"(src));
}
__device__ __forceinline__ void cp16z(unsigned dst, const void* src, int sz) {
    asm volatile("cp.async.cg.shared.global [%0], [%1], 16, %2;" :: "r"(dst), "l"(src), "r"(sz));
}
__device__ __forceinline__ void cp_commit() { asm volatile("cp.async.commit_group;"); }
__device__ __forceinline__ void cp_wait1()  { asm volatile("cp.async.wait_group 1;"); }
__device__ __forceinline__ void cp_wait0()  { asm volatile("cp.async.wait_group 0;"); }

__device__ __forceinline__ void fill_bb(
    const __half* __restrict__ Ah, const __half* __restrict__ Al,
    const __half* __restrict__ Wf,
    unsigned sbase, int stage, int m0, int n0, int t, int M, int K, int tid)
{
    int row = tid >> 1, lcol = (tid & 1) * 16;
    unsigned so = sbase + (unsigned)(stage*STG_SZ) + (unsigned)(row*80 + lcol*2);
    size_t ga = (size_t)(m0 + row)*K + t*32 + lcol;
    size_t gb = (size_t)(n0 + row)*K + t*32 + lcol;
    int asz = ((m0 + row) < M) ? 16 : 0;
    cp16z(so,              Ah + ga,     asz);
    cp16z(so + 16,         Ah + ga + 8, asz);
    cp16z(so + 10240,      Al + ga,     asz);
    cp16z(so + 10240 + 16, Al + ga + 8, asz);
    cp16 (so + 20480,      Wf + gb);
    cp16 (so + 20480 + 16, Wf + gb + 8);
    cp_commit();
}

__global__ void __launch_bounds__(256, 2)
gemm_bb_kernel(const __half* __restrict__ Ah, const __half* __restrict__ Al,
               const __half* __restrict__ Wf,
               const float* __restrict__ bias,
               float* __restrict__ C0, float* __restrict__ C1, int n_split,
               __half* __restrict__ Oh, __half* __restrict__ Ol,
               int M, int Ntot, int K, int relu, int mode)
{
    extern __shared__ __align__(16) char smem[];
    unsigned sbase = (unsigned)__cvta_generic_to_shared(smem);
    int tid  = threadIdx.x;
    int lane = tid & 31, warp = tid >> 5;
    int wm = warp & 3, wn = warp >> 2;
    int m0 = blockIdx.y * 128, n0 = blockIdx.x * 128;
    int g = lane >> 2, qd = lane & 3;
    const int NT = K / 32;

    unsigned aA_rel = (unsigned)((wm*32 + (lane & 15))*80 + (lane >> 4)*16);
    unsigned aB_rel = (unsigned)((wn*64 + ((lane >> 4) & 1)*8 + (lane & 7))*80 + ((lane >> 3) & 1)*16);

    float acc[2][8][4] = {};

    fill_bb(Ah, Al, Wf, sbase, 0, m0, n0, 0, M, K, tid);
    fill_bb(Ah, Al, Wf, sbase, 1, m0, n0, 1, M, K, tid);
    cp_wait1();
    __syncthreads();

    for (int t = 0; t < NT; t++) {
        unsigned sA = sbase + (unsigned)((t & 1)*STG_SZ);
        unsigned sB = sA + 20480u;
        #pragma unroll
        for (int kk = 0; kk < 2; kk++) {
            unsigned ah[2][4], al[2][4], bw[4][4];
            #pragma unroll
            for (int im = 0; im < 2; im++) {
                ldsm4(ah[im], sA + aA_rel + im*1280 + kk*32);
                ldsm4(al[im], sA + 10240u + aA_rel + im*1280 + kk*32);
            }
            #pragma unroll
            for (int j = 0; j < 4; j++)
                ldsm4(bw[j], sB + aB_rel + j*1280 + kk*32);
            // pass 1: all hi-part MMAs (dependency distance 16 per acc)
            #pragma unroll
            for (int j = 0; j < 4; j++)
                #pragma unroll
                for (int im = 0; im < 2; im++) {
                    mma_f16(acc[im][2*j],   ah[im], bw[j][0], bw[j][1]);
                    mma_f16(acc[im][2*j+1], ah[im], bw[j][2], bw[j][3]);
                }
            // pass 2: all lo-part MMAs
            #pragma unroll
            for (int j = 0; j < 4; j++)
                #pragma unroll
                for (int im = 0; im < 2; im++) {
                    mma_f16(acc[im][2*j],   al[im], bw[j][0], bw[j][1]);
                    mma_f16(acc[im][2*j+1], al[im], bw[j][2], bw[j][3]);
                }
        }
        __syncthreads();
        if (t + 2 < NT) {
            fill_bb(Ah, Al, Wf, sbase, t & 1, m0, n0, t + 2, M, K, tid);
        }
        if (t + 1 < NT) {
            if (t + 2 < NT) cp_wait1(); else cp_wait0();
            __syncthreads();
        }
    }

    // ---- epilogue ----
    #pragma unroll
    for (int im = 0; im < 2; im++) {
        int r0 = m0 + wm*32 + im*16 + g;
        #pragma unroll
        for (int in_ = 0; in_ < 8; in_++) {
            int gcol = n0 + wn*64 + in_*8 + qd*2;
            float bv0 = bias[gcol], bv1 = bias[gcol+1];
            float v0 = acc[im][in_][0] + bv0;
            float v1 = acc[im][in_][1] + bv1;
            float v2 = acc[im][in_][2] + bv0;
            float v3 = acc[im][in_][3] + bv1;
            if (relu) {
                v0 = fmaxf(v0, 0.f); v1 = fmaxf(v1, 0.f);
                v2 = fmaxf(v2, 0.f); v3 = fmaxf(v3, 0.f);
            }
            if (mode == 2) {
                __half h0,l0,h1,l1;
                if (r0 < M) {
                    split2h(v0, h0, l0); split2h(v1, h1, l1);
                    __half2 hh; hh.x = h0; hh.y = h1;
                    __half2 ll; ll.x = l0; ll.y = l1;
                    *(__half2*)(Oh + (size_t)r0*Ntot + gcol) = hh;
                    *(__half2*)(Ol + (size_t)r0*Ntot + gcol) = ll;
                }
                if (r0 + 8 < M) {
                    split2h(v2, h0, l0); split2h(v3, h1, l1);
                    __half2 hh; hh.x = h0; hh.y = h1;
                    __half2 ll; ll.x = l0; ll.y = l1;
                    *(__half2*)(Oh + (size_t)(r0+8)*Ntot + gcol) = hh;
                    *(__half2*)(Ol + (size_t)(r0+8)*Ntot + gcol) = ll;
                }
            } else if (mode == 1) {
                __half* Ch = (__half*)C0;
                if (r0 < M)     *(__half2*)(Ch + (size_t)r0*Ntot + gcol)     = __floats2half2_rn(v0, v1);
                if (r0 + 8 < M) *(__half2*)(Ch + (size_t)(r0+8)*Ntot + gcol) = __floats2half2_rn(v2, v3);
            } else {
                float* Cc; int ldc, base;
                if (gcol < n_split) { Cc = C0; ldc = n_split;        base = 0; }
                else                { Cc = C1; ldc = Ntot - n_split; base = n_split; }
                int cn = gcol - base;
                if (r0 < M)     *(float2*)(Cc + (size_t)r0*ldc + cn)     = make_float2(v0, v1);
                if (r0 + 8 < M) *(float2*)(Cc + (size_t)(r0+8)*ldc + cn) = make_float2(v2, v3);
            }
        }
    }
}

// ---------------- softmax over 16 ----------------
__global__ void softmax16_kernel(float* __restrict__ aw, int n)
{
    int t = blockIdx.x*blockDim.x + threadIdx.x;
    if (t >= n) return;
    float* p = aw + (size_t)t*16;
    float buf[16];
    float m = -1e30f;
    #pragma unroll
    for (int i = 0; i < 16; i++) { buf[i] = p[i]; m = fmaxf(m, buf[i]); }
    float s = 0.f;
    #pragma unroll
    for (int i = 0; i < 16; i++) { buf[i] = expf(buf[i] - m); s += buf[i]; }
    float inv = 1.f / s;
    #pragma unroll
    for (int i = 0; i < 16; i++) p[i] = buf[i] * inv;
}

// ---------------- ms-deform attention core (fp16 values, fp16-pair out) ----------------
__global__ void __launch_bounds__(256)
msdeform_kernel(const __half* __restrict__ val, const float* __restrict__ off,
                const float* __restrict__ aw, const float* __restrict__ ref,
                __half* __restrict__ oh, __half* __restrict__ ol)
{
    int warp = blockIdx.x * (blockDim.x >> 5) + (threadIdx.x >> 5);
    int lane = threadIdx.x & 31;
    if (warp >= NB*LQT*NHH) return;
    int h  = warp & 7;
    int bq = warp >> 3;
    int q  = bq % LQT;
    int b  = bq / LQT;
    float gx = ref[q*2], gy = ref[q*2+1];
    const float* offp = off + (size_t)bq*DD  + h*32;
    const float* awp  = aw  + (size_t)bq*128 + h*16;
    float acc = 0.f;
    #pragma unroll
    for (int l = 0; l < 4; l++) {
        int Wl = c_W[l], Hl = c_H[l], st = c_start[l];
        float fW = (float)Wl, fH = (float)Hl;
        const __half* vb = val + ((size_t)b*LQT + st)*DD + h*32 + lane;
        #pragma unroll
        for (int p = 0; p < 4; p++) {
            float ox = offp[(l*4+p)*2+0], oy = offp[(l*4+p)*2+1];
            float a  = awp[l*4+p];
            float x = (gx + ox / fW) * fW - 0.5f;
            float y = (gy + oy / fH) * fH - 0.5f;
            float x0f = floorf(x), y0f = floorf(y);
            float tx = x - x0f, ty = y - y0f;
            int x0 = (int)x0f, y0 = (int)y0f;
            float w00 = (1.f-tx)*(1.f-ty)*a;
            float w10 = tx*(1.f-ty)*a;
            float w01 = (1.f-tx)*ty*a;
            float w11 = tx*ty*a;
            bool xv0 = (x0   >= 0) && (x0   < Wl);
            bool xv1 = (x0+1 >= 0) && (x0+1 < Wl);
            bool yv0 = (y0   >= 0) && (y0   < Hl);
            bool yv1 = (y0+1 >= 0) && (y0+1 < Hl);
            if (xv0 && yv0) acc += w00 * __half2float(vb[(size_t)(y0*Wl + x0)     * DD]);
            if (xv1 && yv0) acc += w10 * __half2float(vb[(size_t)(y0*Wl + x0 + 1) * DD]);
            if (xv0 && yv1) acc += w01 * __half2float(vb[(size_t)((y0+1)*Wl + x0)     * DD]);
            if (xv1 && yv1) acc += w11 * __half2float(vb[(size_t)((y0+1)*Wl + x0 + 1) * DD]);
        }
    }
    __half hh, ll;
    split2h(acc, hh, ll);
    size_t o = (size_t)bq*DD + h*32 + lane;
    oh[o] = hh; ol[o] = ll;
}

// ---------------- residual + LayerNorm: warp-per-row, no block barriers ----------------
__global__ void __launch_bounds__(256)
addln_kernel(float* __restrict__ src, const float* __restrict__ res,
             const float* __restrict__ g, const float* __restrict__ b,
             __half* __restrict__ oh, __half* __restrict__ ol,
             __half* __restrict__ qh, __half* __restrict__ ql,
             const float* __restrict__ pos)
{
    int warp = threadIdx.x >> 5, lane = threadIdx.x & 31;
    int row = blockIdx.x*8 + warp;
    size_t base = (size_t)row*DD;
    const float4* s4 = (const float4*)(src + base);
    const float4* r4 = (const float4*)(res + base);
    float4 sa = s4[lane], sb = s4[lane+32];
    float4 ra = r4[lane], rb = r4[lane+32];
    float x[8];
    x[0]=sa.x+ra.x; x[1]=sa.y+ra.y; x[2]=sa.z+ra.z; x[3]=sa.w+ra.w;
    x[4]=sb.x+rb.x; x[5]=sb.y+rb.y; x[6]=sb.z+rb.z; x[7]=sb.w+rb.w;
    float sum = 0.f;
    #pragma unroll
    for (int i = 0; i < 8; i++) sum += x[i];
    #pragma unroll
    for (int o = 16; o > 0; o >>= 1) sum += __shfl_xor_sync(0xffffffffu, sum, o);
    float mean = sum * (1.f/DD);
    float var = 0.f;
    #pragma unroll
    for (int i = 0; i < 8; i++) { float d = x[i]-mean; var += d*d; }
    #pragma unroll
    for (int o = 16; o > 0; o >>= 1) var += __shfl_xor_sync(0xffffffffu, var, o);
    float rstd = rsqrtf(var * (1.f/DD) + 1e-5f);
    int c0 = lane*4, c1 = 128 + lane*4;
    float4 g0 = *(const float4*)(g + c0), g1 = *(const float4*)(g + c1);
    float4 b0 = *(const float4*)(b + c0), b1 = *(const float4*)(b + c1);
    float y[8];
    y[0]=(x[0]-mean)*rstd*g0.x+b0.x; y[1]=(x[1]-mean)*rstd*g0.y+b0.y;
    y[2]=(x[2]-mean)*rstd*g0.z+b0.z; y[3]=(x[3]-mean)*rstd*g0.w+b0.w;
    y[4]=(x[4]-mean)*rstd*g1.x+b1.x; y[5]=(x[5]-mean)*rstd*g1.y+b1.y;
    y[6]=(x[6]-mean)*rstd*g1.z+b1.z; y[7]=(x[7]-mean)*rstd*g1.w+b1.w;
    float4* w4 = (float4*)(src + base);
    w4[lane]    = make_float4(y[0],y[1],y[2],y[3]);
    w4[lane+32] = make_float4(y[4],y[5],y[6],y[7]);
    #pragma unroll
    for (int hblk = 0; hblk < 2; hblk++) {
        size_t o = base + (hblk ? (size_t)c1 : (size_t)c0);
        #pragma unroll
        for (int p = 0; p < 2; p++) {
            __half h0,l0,h1,l1;
            split2h(y[hblk*4+2*p],   h0, l0);
            split2h(y[hblk*4+2*p+1], h1, l1);
            __half2 hh; hh.x=h0; hh.y=h1;
            __half2 ll; ll.x=l0; ll.y=l1;
            *(__half2*)(oh + o + 2*p) = hh;
            *(__half2*)(ol + o + 2*p) = ll;
        }
    }
    if (qh) {
        const float4* p4 = (const float4*)(pos + base);
        float4 pa = p4[lane], pb = p4[lane+32];
        float z[8];
        z[0]=y[0]+pa.x; z[1]=y[1]+pa.y; z[2]=y[2]+pa.z; z[3]=y[3]+pa.w;
        z[4]=y[4]+pb.x; z[5]=y[5]+pb.y; z[6]=y[6]+pb.z; z[7]=y[7]+pb.w;
        #pragma unroll
        for (int hblk = 0; hblk < 2; hblk++) {
            size_t o = base + (hblk ? (size_t)c1 : (size_t)c0);
            #pragma unroll
            for (int p = 0; p < 2; p++) {
                __half h0,l0,h1,l1;
                split2h(z[hblk*4+2*p],   h0, l0);
                split2h(z[hblk*4+2*p+1], h1, l1);
                __half2 hh; hh.x=h0; hh.y=h1;
                __half2 ll; ll.x=l0; ll.y=l1;
                *(__half2*)(qh + o + 2*p) = hh;
                *(__half2*)(ql + o + 2*p) = ll;
            }
        }
    }
}

// ---------------- finalize ----------------
__global__ void finalize_kernel(const float* __restrict__ src, float* __restrict__ out, int out_size)
{
    int i = blockIdx.x*blockDim.x + threadIdx.x;
    if (i >= out_size) return;
    const int n = NB*LQT*DD;
    if (i < n) { out[i] = src[i]; return; }
    int j = i - n;
    float v;
    if (j < 4)       v = (float)c_start[j];
    else if (j < 12) v = (float)c_H[(j-4) >> 1];
    else             v = 1.0f;
    out[i] = v;
}

// ---------------- host orchestration ----------------
extern "C" void kernel_launch(void* const* d_in, const int* in_sizes, int n_in,
                              void* d_out, int out_size)
{
    (void)n_in;
    const float *X[4], *FW[4], *FB[4];
    if (in_sizes[1] == 65536) {
        for (int i = 0; i < 4; i++) {
            X[i]  = (const float*)d_in[3*i+0];
            FW[i] = (const float*)d_in[3*i+1];
            FB[i] = (const float*)d_in[3*i+2];
        }
    } else {
        for (int i = 0; i < 4; i++) {
            X[i]  = (const float*)d_in[i];
            FW[i] = (const float*)d_in[4+2*i];
            FB[i] = (const float*)d_in[5+2*i];
        }
    }
    const float* gn_g  = (const float*)d_in[12];
    const float* gn_b  = (const float*)d_in[13];
    const float* lemb  = (const float*)d_in[14];
    const float* off_w = (const float*)d_in[15];
    const float* off_b = (const float*)d_in[16];
    const float* aw_w  = (const float*)d_in[17];
    const float* aw_b  = (const float*)d_in[18];
    const float* val_w = (const float*)d_in[19];
    const float* val_b = (const float*)d_in[20];
    const float* out_w = (const float*)d_in[21];
    const float* out_b = (const float*)d_in[22];
    const float* ln1_g = (const float*)d_in[23];
    const float* ln1_b = (const float*)d_in[24];
    const float* l1_w  = (const float*)d_in[25];
    const float* l1_b  = (const float*)d_in[26];
    const float* l2_w  = (const float*)d_in[27];
    const float* l2_b  = (const float*)d_in[28];
    const float* ln2_g = (const float*)d_in[29];
    const float* ln2_b = (const float*)d_in[30];

    float *src, *pos, *off, *aw, *val, *att, *ref, *cbias;
    __half *wf, *qh, *ql, *sh, *sl, *th, *tl, *msh, *msl, *hbh, *hbl;
    cudaGetSymbolAddress((void**)&src,   g_src);
    cudaGetSymbolAddress((void**)&pos,   g_pos);
    cudaGetSymbolAddress((void**)&off,   g_off);
    cudaGetSymbolAddress((void**)&aw,    g_aw);
    cudaGetSymbolAddress((void**)&val,   g_val);
    cudaGetSymbolAddress((void**)&att,   g_att);
    cudaGetSymbolAddress((void**)&ref,   g_ref);
    cudaGetSymbolAddress((void**)&cbias, g_cbias);
    cudaGetSymbolAddress((void**)&wf,    g_wf);
    cudaGetSymbolAddress((void**)&qh,    g_qh);
    cudaGetSymbolAddress((void**)&ql,    g_ql);
    cudaGetSymbolAddress((void**)&sh,    g_sh);
    cudaGetSymbolAddress((void**)&sl,    g_sl);
    cudaGetSymbolAddress((void**)&th,    g_th);
    cudaGetSymbolAddress((void**)&tl,    g_tl);
    cudaGetSymbolAddress((void**)&msh,   g_msh);
    cudaGetSymbolAddress((void**)&msl,   g_msl);
    cudaGetSymbolAddress((void**)&hbh,   g_hbh);
    cudaGetSymbolAddress((void**)&hbl,   g_hbl);

    cudaFuncSetAttribute(gemm_bb_kernel,
        cudaFuncAttributeMaxDynamicSharedMemorySize, SMEM_BB);

    setup_kernel<<<(N_WB + LQT*DD + 255)/256, 256>>>(
        off_w, aw_w, val_w, out_w, l1_w, l2_w, off_b, aw_b, wf, cbias, lemb, pos, ref);
    tokenizer_kernel<<<1536, 256>>>(X[0], X[1], X[2], X[3],
                                    FW[0], FW[1], FW[2], FW[3],
                                    FB[0], FB[1], FB[2], FB[3], src);
    gn_kernel<<<4*2*32, 256>>>(src, gn_g, gn_b, pos, sh, sl, qh, ql);

    const int GY = (MTOT + 127)/128;  // 192
    dim3 g_oaw(3, GY), g_256(2, GY), g_l1(8, GY);

    for (int l = 0; l < NLAY; l++) {
        gemm_bb_kernel<<<g_oaw, 256, SMEM_BB>>>(qh, ql,
            wf + OFF_OAW + (size_t)l*98304,
            cbias + l*384, off, aw, 256, (__half*)0, (__half*)0,
            MTOT, 384, 256, 0, 0);
        softmax16_kernel<<<(MTOT*NHH + 255)/256, 256>>>(aw, MTOT*NHH);
        gemm_bb_kernel<<<g_256, 256, SMEM_BB>>>(sh, sl,
            wf + OFF_VAL + (size_t)l*65536,
            val_b + l*DD, val, (float*)0, 256, (__half*)0, (__half*)0,
            MTOT, 256, 256, 0, 1);
        msdeform_kernel<<<MTOT, 256>>>((const __half*)val, off, aw, ref, msh, msl);
        gemm_bb_kernel<<<g_256, 256, SMEM_BB>>>(msh, msl,
            wf + OFF_OUT + (size_t)l*65536,
            out_b + l*DD, att, (float*)0, 256, (__half*)0, (__half*)0,
            MTOT, 256, 256, 0, 0);
        addln_kernel<<<MTOT/8, 256>>>(src, att, ln1_g + l*DD, ln1_b + l*DD,
            th, tl, (__half*)0, (__half*)0, (const float*)0);
        gemm_bb_kernel<<<g_l1, 256, SMEM_BB>>>(th, tl,
            wf + OFF_L1 + (size_t)l*262144,
            l1_b + l*DFF_, (float*)0, (float*)0, 1024, hbh, hbl,
            MTOT, 1024, 256, 1, 2);
        gemm_bb_kernel<<<g_256, 256, SMEM_BB>>>(hbh, hbl,
            wf + OFF_L2 + (size_t)l*262144,
            l2_b + l*DD, att, (float*)0, 256, (__half*)0, (__half*)0,
            MTOT, 256, 1024, 0, 0);
        addln_kernel<<<MTOT/8, 256>>>(src, att, ln2_g + l*DD, ln2_b + l*DD,
            sh, sl, qh, ql, pos);
    }

    finalize_kernel<<<(out_size + 255)/256, 256>>>(src, (float*)d_out, out_size);
}